// round 1
// baseline (speedup 1.0000x reference)
#include <cuda_runtime.h>
#include <math.h>

#define BSZ 256
#define SLEN 512
#define HDIM 1024
#define EDIM 300
#define VOC 32000
#define KX (EDIM + HDIM + HDIM)   // 2348, divisible by 4 -> float4-aligned rows

// Scratch: X = [emb | ctx | h] per batch row
__device__ float g_X[BSZ * KX];

// ---------------------------------------------------------------------------
// Kernel 1: fused attention (one pass over encoder_outputs, online softmax)
// grid = BSZ blocks, 256 threads. Each thread owns 4 contiguous H-elements.
// ---------------------------------------------------------------------------
__global__ void attention_kernel(const int* __restrict__ idx,
                                 const float* __restrict__ hid,
                                 const float* __restrict__ enc,
                                 const float* __restrict__ emb_table,
                                 float* __restrict__ attn_out)
{
    const int b = blockIdx.x;
    const int t = threadIdx.x;

    const float4* enc4 = (const float4*)(enc + (size_t)b * SLEN * HDIM);
    const float4  h4   = ((const float4*)(hid + (size_t)b * HDIM))[t];

    // pack h into X[:, E+H : ]
    ((float4*)(g_X + (size_t)b * KX + EDIM + HDIM))[t] = h4;
    // embedding gather into X[:, 0:E]
    const int ci = idx[b];
    for (int j = t; j < EDIM; j += 256)
        g_X[(size_t)b * KX + j] = emb_table[(size_t)ci * EDIM + j];

    __shared__ float red[8];
    __shared__ float energy[SLEN];
    __shared__ float s_factor, s_p, s_m, s_inv;

    float4 ctx = make_float4(0.f, 0.f, 0.f, 0.f);
    float m = -INFINITY, d = 0.f;

    for (int s = 0; s < SLEN; ++s) {
        const float4 e4 = enc4[s * 256 + t];
        float part = e4.x * h4.x + e4.y * h4.y + e4.z * h4.z + e4.w * h4.w;
        #pragma unroll
        for (int o = 16; o > 0; o >>= 1)
            part += __shfl_down_sync(0xffffffffu, part, o);
        if ((t & 31) == 0) red[t >> 5] = part;
        __syncthreads();
        if (t == 0) {
            float e = 0.f;
            #pragma unroll
            for (int w = 0; w < 8; ++w) e += red[w];
            energy[s] = e;
            const float m2 = fmaxf(m, e);
            const float f  = __expf(m - m2);
            const float p  = __expf(e - m2);
            d = d * f + p;
            m = m2;
            s_factor = f;
            s_p = p;
        }
        __syncthreads();
        const float f = s_factor, p = s_p;
        ctx.x = ctx.x * f + p * e4.x;
        ctx.y = ctx.y * f + p * e4.y;
        ctx.z = ctx.z * f + p * e4.z;
        ctx.w = ctx.w * f + p * e4.w;
    }

    if (t == 0) { s_m = m; s_inv = 1.f / d; }
    __syncthreads();
    const float inv = s_inv, mf = s_m;

    // ctx into X[:, E : E+H]
    float4 c = make_float4(ctx.x * inv, ctx.y * inv, ctx.z * inv, ctx.w * inv);
    ((float4*)(g_X + (size_t)b * KX + EDIM))[t] = c;

    // attention probabilities output
    for (int s = t; s < SLEN; s += 256)
        attn_out[(size_t)b * SLEN + s] = __expf(energy[s] - mf) * inv;
}

// ---------------------------------------------------------------------------
// Kernel 2: RNN step  h_new = tanh(X @ [W_ih|W_hh].T + b_ih + b_hh)
// C[256,1024], K=2348. 64x64 tiles, 16x16 threads, 4x4 per thread.
// ---------------------------------------------------------------------------
__global__ void rnn_gemm(const float* __restrict__ W_ih,
                         const float* __restrict__ b_ih,
                         const float* __restrict__ W_hh,
                         const float* __restrict__ b_hh,
                         float* __restrict__ hn)
{
    const int BM = 64, BN = 64, BK = 16;
    __shared__ float As[BK][BM + 4];
    __shared__ float Bs[BK][BN + 4];

    const int tid = threadIdx.x;
    const int tx = tid % 16, ty = tid / 16;
    const int m0 = blockIdx.y * BM;
    const int n0 = blockIdx.x * BN;

    float acc[4][4] = {};

    for (int k0 = 0; k0 < KX; k0 += BK) {
        for (int i = tid; i < BM * BK; i += 256) {
            const int mm = i / BK, kk = i % BK;
            const int k = k0 + kk;
            As[kk][mm] = (k < KX) ? g_X[(size_t)(m0 + mm) * KX + k] : 0.f;
        }
        for (int i = tid; i < BN * BK; i += 256) {
            const int nn = i / BK, kk = i % BK;
            const int k = k0 + kk;
            const int n = n0 + nn;
            float v = 0.f;
            if (k < KX)
                v = (k < EDIM + HDIM) ? W_ih[(size_t)n * (EDIM + HDIM) + k]
                                      : W_hh[(size_t)n * HDIM + (k - (EDIM + HDIM))];
            Bs[kk][nn] = v;
        }
        __syncthreads();
        #pragma unroll
        for (int kk = 0; kk < BK; ++kk) {
            float a[4], bv[4];
            #pragma unroll
            for (int i = 0; i < 4; ++i) a[i] = As[kk][ty * 4 + i];
            #pragma unroll
            for (int j = 0; j < 4; ++j) bv[j] = Bs[kk][tx * 4 + j];
            #pragma unroll
            for (int i = 0; i < 4; ++i)
                #pragma unroll
                for (int j = 0; j < 4; ++j)
                    acc[i][j] += a[i] * bv[j];
        }
        __syncthreads();
    }

    #pragma unroll
    for (int i = 0; i < 4; ++i)
        #pragma unroll
        for (int j = 0; j < 4; ++j) {
            const int m = m0 + ty * 4 + i;
            const int n = n0 + tx * 4 + j;
            hn[(size_t)m * HDIM + n] = tanhf(acc[i][j] + b_ih[n] + b_hh[n]);
        }
}

// ---------------------------------------------------------------------------
// Kernel 3: logits = h_new @ fc_W.T + fc_b
// C[256,32000], K=1024. 128x128x16 tiles, 256 threads, 8x8 per thread.
// ---------------------------------------------------------------------------
__global__ void logits_gemm(const float* __restrict__ A,   // h_new [256][1024]
                            const float* __restrict__ Wf,  // [32000][1024]
                            const float* __restrict__ bf,
                            float* __restrict__ Cout)
{
    const int BM = 128, BN = 128, BK = 16;
    __shared__ float As[BK][BM + 4];
    __shared__ float Bs[BK][BN + 4];

    const int tid = threadIdx.x;
    const int tx = tid % 16, ty = tid / 16;
    const int m0 = blockIdx.y * BM;
    const int n0 = blockIdx.x * BN;

    float acc[8][8] = {};

    for (int k0 = 0; k0 < HDIM; k0 += BK) {
        // A tile: 128 rows x 16 k = 512 float4, 2 per thread
        #pragma unroll
        for (int r = 0; r < 2; ++r) {
            const int f = tid + r * 256;
            const int mm = f >> 2, k4 = (f & 3) * 4;
            const float4 v = *(const float4*)(A + (size_t)(m0 + mm) * HDIM + k0 + k4);
            As[k4 + 0][mm] = v.x; As[k4 + 1][mm] = v.y;
            As[k4 + 2][mm] = v.z; As[k4 + 3][mm] = v.w;
        }
        // B tile: 128 vocab rows x 16 k
        #pragma unroll
        for (int r = 0; r < 2; ++r) {
            const int f = tid + r * 256;
            const int nn = f >> 2, k4 = (f & 3) * 4;
            const float4 v = *(const float4*)(Wf + (size_t)(n0 + nn) * HDIM + k0 + k4);
            Bs[k4 + 0][nn] = v.x; Bs[k4 + 1][nn] = v.y;
            Bs[k4 + 2][nn] = v.z; Bs[k4 + 3][nn] = v.w;
        }
        __syncthreads();
        #pragma unroll
        for (int kk = 0; kk < BK; ++kk) {
            float a[8], bv[8];
            #pragma unroll
            for (int i = 0; i < 8; ++i) a[i] = As[kk][ty * 8 + i];
            #pragma unroll
            for (int j = 0; j < 8; ++j) bv[j] = Bs[kk][tx * 8 + j];
            #pragma unroll
            for (int i = 0; i < 8; ++i)
                #pragma unroll
                for (int j = 0; j < 8; ++j)
                    acc[i][j] += a[i] * bv[j];
        }
        __syncthreads();
    }

    #pragma unroll
    for (int i = 0; i < 8; ++i)
        #pragma unroll
        for (int j = 0; j < 8; ++j) {
            const int m = m0 + ty * 8 + i;
            const int n = n0 + tx * 8 + j;
            Cout[(size_t)m * VOC + n] = acc[i][j] + bf[n];
        }
}

// ---------------------------------------------------------------------------
// Launch
// inputs (metadata order):
// 0 current_indices (int32, 256)
// 1 hiddens_from_prev_step (f32, 1*256*1024)
// 2 encoder_outputs (f32, 256*512*1024)
// 3 emb_table (f32, 32000*300)
// 4 W_ih (f32, 1024*1324)   5 b_ih (1024)
// 6 W_hh (f32, 1024*1024)   7 b_hh (1024)
// 8 fc_W (f32, 32000*1024)  9 fc_b (32000)
// output: [logits 256*32000 | h_new 256*1024 | attn 256*512]
// ---------------------------------------------------------------------------
extern "C" void kernel_launch(void* const* d_in, const int* in_sizes, int n_in,
                              void* d_out, int out_size)
{
    const int*   idx   = (const int*)d_in[0];
    const float* hid   = (const float*)d_in[1];
    const float* enc   = (const float*)d_in[2];
    const float* emb   = (const float*)d_in[3];
    const float* W_ih  = (const float*)d_in[4];
    const float* b_ih  = (const float*)d_in[5];
    const float* W_hh  = (const float*)d_in[6];
    const float* b_hh  = (const float*)d_in[7];
    const float* fc_W  = (const float*)d_in[8];
    const float* fc_b  = (const float*)d_in[9];

    float* out    = (float*)d_out;
    float* logits = out;
    float* hn     = out + (size_t)BSZ * VOC;
    float* attn   = out + (size_t)BSZ * VOC + (size_t)BSZ * HDIM;

    attention_kernel<<<BSZ, 256>>>(idx, hid, enc, emb, attn);
    rnn_gemm<<<dim3(HDIM / 64, BSZ / 64), 256>>>(W_ih, b_ih, W_hh, b_hh, hn);
    logits_gemm<<<dim3(VOC / 128, BSZ / 128), 256>>>(hn, fc_W, fc_b, logits);
}

// round 2
// speedup vs baseline: 1.8933x; 1.8933x over previous
#include <cuda_runtime.h>
#include <math.h>
#include <stdint.h>

#define BSZ 256
#define SLEN 512
#define HDIM 1024
#define EDIM 300
#define VOC 32000
#define KX  (EDIM + HDIM + HDIM)   // 2348
#define KXP 2352                   // padded to multiple of 16

// Scratch
__device__ float g_X[BSZ * KXP];           // [emb | ctx | h | pad]
__device__ float g_Wpack[HDIM * KXP];      // [W_ih | W_hh | 0-pad] per output row

// ---------------------------------------------------------------------------
// cp.async helpers
// ---------------------------------------------------------------------------
__device__ __forceinline__ void cp_async16(void* smem_dst, const void* gmem_src) {
    uint32_t s = (uint32_t)__cvta_generic_to_shared(smem_dst);
    asm volatile("cp.async.cg.shared.global [%0], [%1], 16;\n" :: "r"(s), "l"(gmem_src));
}
__device__ __forceinline__ void cp_commit() {
    asm volatile("cp.async.commit_group;\n");
}
template<int N>
__device__ __forceinline__ void cp_wait() {
    asm volatile("cp.async.wait_group %0;\n" :: "n"(N) : "memory");
}

// ---------------------------------------------------------------------------
// Kernel 1: fused attention, smem-tiled, cp.async double-buffered.
// grid = BSZ, 256 threads. TS=4 seq positions per stage, 128 stages.
// ---------------------------------------------------------------------------
#define TS 4
__global__ __launch_bounds__(256)
void attention_kernel(const int* __restrict__ idx,
                      const float* __restrict__ hid,
                      const float* __restrict__ enc,
                      const float* __restrict__ emb_table,
                      float* __restrict__ attn_out)
{
    __shared__ float tile[2][TS * HDIM];   // 32 KB
    __shared__ float red[8][TS];
    __shared__ float en_all[SLEN];

    const int b = blockIdx.x;
    const int t = threadIdx.x;
    const int warp = t >> 5;

    const float4* enc4 = (const float4*)(enc + (size_t)b * SLEN * HDIM);
    const float4  h4   = ((const float4*)(hid + (size_t)b * HDIM))[t];

    // pack h into X[:, E+H:], embedding gather, zero pad
    float* Xrow = g_X + (size_t)b * KXP;
    ((float4*)(Xrow + EDIM + HDIM))[t] = h4;
    const int ci = idx[b];
    for (int j = t; j < EDIM; j += 256)
        Xrow[j] = emb_table[(size_t)ci * EDIM + j];
    if (t < 4) Xrow[KX + t] = 0.f;

    // prefetch stage 0: 4 float4 per thread (TS*1024 floats = 1024 float4)
    #pragma unroll
    for (int i = 0; i < TS; ++i) {
        const int e = i * 256 + t;          // float4 index within stage
        const int s = e >> 8;               // 256 float4 per seq position
        const int off = e & 255;
        cp_async16(&tile[0][s * HDIM + off * 4], &enc4[s * 256 + off]);
    }
    cp_commit();

    float4 ctx = make_float4(0.f, 0.f, 0.f, 0.f);
    float m = -1e30f, d = 0.f;

    const int NSTAGE = SLEN / TS;           // 128
    for (int c = 0; c < NSTAGE; ++c) {
        const int buf = c & 1;
        // prefetch next stage
        if (c + 1 < NSTAGE) {
            const int s0n = (c + 1) * TS;
            #pragma unroll
            for (int i = 0; i < TS; ++i) {
                const int e = i * 256 + t;
                const int s = e >> 8;
                const int off = e & 255;
                cp_async16(&tile[buf ^ 1][s * HDIM + off * 4],
                           &enc4[(size_t)(s0n + s) * 256 + off]);
            }
        }
        cp_commit();
        cp_wait<1>();
        __syncthreads();

        // energies: per-thread partial dot for each of TS positions
        float part[TS];
        #pragma unroll
        for (int s = 0; s < TS; ++s) {
            const float4 e4 = ((const float4*)&tile[buf][s * HDIM])[t];
            part[s] = e4.x * h4.x + e4.y * h4.y + e4.z * h4.z + e4.w * h4.w;
        }
        #pragma unroll
        for (int s = 0; s < TS; ++s) {
            #pragma unroll
            for (int o = 16; o > 0; o >>= 1)
                part[s] += __shfl_down_sync(0xffffffffu, part[s], o);
        }
        if ((t & 31) == 0) {
            #pragma unroll
            for (int s = 0; s < TS; ++s) red[warp][s] = part[s];
        }
        __syncthreads();

        // every thread redundantly computes identical en/m/d
        float en[TS];
        #pragma unroll
        for (int s = 0; s < TS; ++s) {
            float e = 0.f;
            #pragma unroll
            for (int w = 0; w < 8; ++w) e += red[w][s];
            en[s] = e;
        }
        float tmax = en[0];
        #pragma unroll
        for (int s = 1; s < TS; ++s) tmax = fmaxf(tmax, en[s]);
        const float nm = fmaxf(m, tmax);
        const float f = __expf(m - nm);
        float p[TS], psum = 0.f;
        #pragma unroll
        for (int s = 0; s < TS; ++s) { p[s] = __expf(en[s] - nm); psum += p[s]; }
        d = d * f + psum;
        m = nm;

        // ctx update from smem tile
        ctx.x *= f; ctx.y *= f; ctx.z *= f; ctx.w *= f;
        #pragma unroll
        for (int s = 0; s < TS; ++s) {
            const float4 e4 = ((const float4*)&tile[buf][s * HDIM])[t];
            ctx.x += p[s] * e4.x;
            ctx.y += p[s] * e4.y;
            ctx.z += p[s] * e4.z;
            ctx.w += p[s] * e4.w;
        }

        // save energies for attn output
        if (t < TS) en_all[c * TS + t] = en[t];
        __syncthreads();   // protect tile[buf] before it is overwritten
    }

    const float inv = 1.f / d;
    float4 cc = make_float4(ctx.x * inv, ctx.y * inv, ctx.z * inv, ctx.w * inv);
    ((float4*)(Xrow + EDIM))[t] = cc;

    for (int s = t; s < SLEN; s += 256)
        attn_out[(size_t)b * SLEN + s] = __expf(en_all[s] - m) * inv;
}

// ---------------------------------------------------------------------------
// Kernel 1b: pack [W_ih | W_hh | 0] into g_Wpack [HDIM][KXP]
// ---------------------------------------------------------------------------
__global__ void pack_weights(const float* __restrict__ W_ih,
                             const float* __restrict__ W_hh)
{
    const int i = blockIdx.x * 256 + threadIdx.x;
    if (i >= HDIM * KXP) return;
    const int n = i / KXP, k = i % KXP;
    float v = 0.f;
    if (k < EDIM + HDIM)      v = W_ih[(size_t)n * (EDIM + HDIM) + k];
    else if (k < KX)          v = W_hh[(size_t)n * HDIM + (k - (EDIM + HDIM))];
    g_Wpack[i] = v;
}

// ---------------------------------------------------------------------------
// Kernel 2: RNN step  h_new = tanh(X @ Wpack.T + b_ih + b_hh)
// 64x64x16 double-buffered, 256 threads, 4x4 micro-tiles.
// ---------------------------------------------------------------------------
__global__ __launch_bounds__(256)
void rnn_gemm(const float* __restrict__ b_ih,
              const float* __restrict__ b_hh,
              float* __restrict__ hn)
{
    __shared__ float As[2][16][64];
    __shared__ float Bs[2][16][64];

    const int tid = threadIdx.x;
    const int tx = tid % 16, ty = tid / 16;
    const int m0 = blockIdx.y * 64;
    const int n0 = blockIdx.x * 64;

    const int lm = tid >> 2, lk4 = (tid & 3) << 2;   // load mapping

    float acc[4][4] = {};

    const int NIT = KXP / 16;   // 147

    // prologue: load tile 0
    {
        float4 av = *(const float4*)(g_X + (size_t)(m0 + lm) * KXP + lk4);
        float4 bv = *(const float4*)(g_Wpack + (size_t)(n0 + lm) * KXP + lk4);
        As[0][lk4 + 0][lm] = av.x; As[0][lk4 + 1][lm] = av.y;
        As[0][lk4 + 2][lm] = av.z; As[0][lk4 + 3][lm] = av.w;
        Bs[0][lk4 + 0][lm] = bv.x; Bs[0][lk4 + 1][lm] = bv.y;
        Bs[0][lk4 + 2][lm] = bv.z; Bs[0][lk4 + 3][lm] = bv.w;
    }
    __syncthreads();

    for (int it = 0; it < NIT; ++it) {
        const int buf = it & 1;
        float4 av, bv;
        const bool more = (it + 1 < NIT);
        if (more) {
            const int k0 = (it + 1) * 16;
            av = *(const float4*)(g_X + (size_t)(m0 + lm) * KXP + k0 + lk4);
            bv = *(const float4*)(g_Wpack + (size_t)(n0 + lm) * KXP + k0 + lk4);
        }
        #pragma unroll
        for (int kk = 0; kk < 16; ++kk) {
            const float4 a = *(const float4*)&As[buf][kk][ty * 4];
            const float4 bq = *(const float4*)&Bs[buf][kk][tx * 4];
            const float aa[4] = {a.x, a.y, a.z, a.w};
            const float bb[4] = {bq.x, bq.y, bq.z, bq.w};
            #pragma unroll
            for (int i = 0; i < 4; ++i)
                #pragma unroll
                for (int j = 0; j < 4; ++j)
                    acc[i][j] += aa[i] * bb[j];
        }
        if (more) {
            As[buf ^ 1][lk4 + 0][lm] = av.x; As[buf ^ 1][lk4 + 1][lm] = av.y;
            As[buf ^ 1][lk4 + 2][lm] = av.z; As[buf ^ 1][lk4 + 3][lm] = av.w;
            Bs[buf ^ 1][lk4 + 0][lm] = bv.x; Bs[buf ^ 1][lk4 + 1][lm] = bv.y;
            Bs[buf ^ 1][lk4 + 2][lm] = bv.z; Bs[buf ^ 1][lk4 + 3][lm] = bv.w;
        }
        __syncthreads();
    }

    #pragma unroll
    for (int i = 0; i < 4; ++i) {
        const int mrow = m0 + ty * 4 + i;
        const int ncol = n0 + tx * 4;
        float4 o;
        o.x = tanhf(acc[i][0] + b_ih[ncol + 0] + b_hh[ncol + 0]);
        o.y = tanhf(acc[i][1] + b_ih[ncol + 1] + b_hh[ncol + 1]);
        o.z = tanhf(acc[i][2] + b_ih[ncol + 2] + b_hh[ncol + 2]);
        o.w = tanhf(acc[i][3] + b_ih[ncol + 3] + b_hh[ncol + 3]);
        *(float4*)(hn + (size_t)mrow * HDIM + ncol) = o;
    }
}

// ---------------------------------------------------------------------------
// Kernel 3: logits = h_new @ fc_W.T + fc_b
// 128x128x8 double-buffered SGEMM, 256 threads, 8x8 micro-tiles.
// ---------------------------------------------------------------------------
__global__ __launch_bounds__(256)
void logits_gemm(const float* __restrict__ A,    // [256][1024]
                 const float* __restrict__ Wf,   // [32000][1024]
                 const float* __restrict__ bf,
                 float* __restrict__ Cout)
{
    __shared__ float As[2][8][128];
    __shared__ float Bs[2][8][128];

    const int tid = threadIdx.x;
    const int tx = tid % 16, ty = tid / 16;
    const int m0 = blockIdx.y * 128;
    const int n0 = blockIdx.x * 128;

    const int lr = tid >> 1, lk4 = (tid & 1) << 2;   // load mapping

    float acc[8][8] = {};

    const int NIT = HDIM / 8;   // 128

    // prologue
    {
        float4 av = *(const float4*)(A  + (size_t)(m0 + lr) * HDIM + lk4);
        float4 bv = *(const float4*)(Wf + (size_t)(n0 + lr) * HDIM + lk4);
        As[0][lk4 + 0][lr] = av.x; As[0][lk4 + 1][lr] = av.y;
        As[0][lk4 + 2][lr] = av.z; As[0][lk4 + 3][lr] = av.w;
        Bs[0][lk4 + 0][lr] = bv.x; Bs[0][lk4 + 1][lr] = bv.y;
        Bs[0][lk4 + 2][lr] = bv.z; Bs[0][lk4 + 3][lr] = bv.w;
    }
    __syncthreads();

    for (int it = 0; it < NIT; ++it) {
        const int buf = it & 1;
        float4 av, bv;
        const bool more = (it + 1 < NIT);
        if (more) {
            const int k0 = (it + 1) * 8;
            av = *(const float4*)(A  + (size_t)(m0 + lr) * HDIM + k0 + lk4);
            bv = *(const float4*)(Wf + (size_t)(n0 + lr) * HDIM + k0 + lk4);
        }
        #pragma unroll
        for (int kk = 0; kk < 8; ++kk) {
            const float4 a0 = *(const float4*)&As[buf][kk][ty * 8];
            const float4 a1 = *(const float4*)&As[buf][kk][ty * 8 + 4];
            const float4 b0 = *(const float4*)&Bs[buf][kk][tx * 8];
            const float4 b1 = *(const float4*)&Bs[buf][kk][tx * 8 + 4];
            const float aa[8] = {a0.x, a0.y, a0.z, a0.w, a1.x, a1.y, a1.z, a1.w};
            const float bb[8] = {b0.x, b0.y, b0.z, b0.w, b1.x, b1.y, b1.z, b1.w};
            #pragma unroll
            for (int i = 0; i < 8; ++i)
                #pragma unroll
                for (int j = 0; j < 8; ++j)
                    acc[i][j] += aa[i] * bb[j];
        }
        if (more) {
            As[buf ^ 1][lk4 + 0][lr] = av.x; As[buf ^ 1][lk4 + 1][lr] = av.y;
            As[buf ^ 1][lk4 + 2][lr] = av.z; As[buf ^ 1][lk4 + 3][lr] = av.w;
            Bs[buf ^ 1][lk4 + 0][lr] = bv.x; Bs[buf ^ 1][lk4 + 1][lr] = bv.y;
            Bs[buf ^ 1][lk4 + 2][lr] = bv.z; Bs[buf ^ 1][lk4 + 3][lr] = bv.w;
        }
        __syncthreads();
    }

    #pragma unroll
    for (int i = 0; i < 8; ++i) {
        const int mrow = m0 + ty * 8 + i;
        #pragma unroll
        for (int j4 = 0; j4 < 2; ++j4) {
            const int ncol = n0 + tx * 8 + j4 * 4;
            float4 o;
            o.x = acc[i][j4 * 4 + 0] + bf[ncol + 0];
            o.y = acc[i][j4 * 4 + 1] + bf[ncol + 1];
            o.z = acc[i][j4 * 4 + 2] + bf[ncol + 2];
            o.w = acc[i][j4 * 4 + 3] + bf[ncol + 3];
            *(float4*)(Cout + (size_t)mrow * VOC + ncol) = o;
        }
    }
}

// ---------------------------------------------------------------------------
// Launch
// output: [logits 256*32000 | h_new 256*1024 | attn 256*512]
// ---------------------------------------------------------------------------
extern "C" void kernel_launch(void* const* d_in, const int* in_sizes, int n_in,
                              void* d_out, int out_size)
{
    const int*   idx   = (const int*)d_in[0];
    const float* hid   = (const float*)d_in[1];
    const float* enc   = (const float*)d_in[2];
    const float* emb   = (const float*)d_in[3];
    const float* W_ih  = (const float*)d_in[4];
    const float* b_ih  = (const float*)d_in[5];
    const float* W_hh  = (const float*)d_in[6];
    const float* b_hh  = (const float*)d_in[7];
    const float* fc_W  = (const float*)d_in[8];
    const float* fc_b  = (const float*)d_in[9];

    float* out    = (float*)d_out;
    float* logits = out;
    float* hn     = out + (size_t)BSZ * VOC;
    float* attn   = out + (size_t)BSZ * VOC + (size_t)BSZ * HDIM;

    pack_weights<<<(HDIM * KXP + 255) / 256, 256>>>(W_ih, W_hh);
    attention_kernel<<<BSZ, 256>>>(idx, hid, enc, emb, attn);
    rnn_gemm<<<dim3(HDIM / 64, BSZ / 64), 256>>>(b_ih, b_hh, hn);
    logits_gemm<<<dim3(VOC / 128, BSZ / 128), 256>>>(hn, fc_W, fc_b, logits);
}

// round 4
// speedup vs baseline: 2.8341x; 1.4969x over previous
#include <cuda_runtime.h>
#include <cuda_bf16.h>
#include <math.h>
#include <stdint.h>

#define BSZ 256
#define SLEN 512
#define HDIM 1024
#define EDIM 300
#define VOC 32000
#define KX  (EDIM + HDIM + HDIM)   // 2348
#define KXP 2352

__device__ float g_X[BSZ * KXP];
__device__ float g_Wpack[HDIM * KXP];

extern __shared__ char dynsm[];

// ---------------------------------------------------------------------------
// helpers
// ---------------------------------------------------------------------------
__device__ __forceinline__ uint32_t s2u(const void* p) {
    return (uint32_t)__cvta_generic_to_shared(p);
}
__device__ __forceinline__ void cp_async16(void* smem_dst, const void* gmem_src) {
    uint32_t s = s2u(smem_dst);
    asm volatile("cp.async.cg.shared.global [%0], [%1], 16;\n" :: "r"(s), "l"(gmem_src));
}
__device__ __forceinline__ void cp_commit() { asm volatile("cp.async.commit_group;\n"); }
template<int N> __device__ __forceinline__ void cp_wait() {
    asm volatile("cp.async.wait_group %0;\n" :: "n"(N) : "memory");
}
__device__ __forceinline__ void ldsm4(uint32_t* r, uint32_t a) {
    asm volatile("ldmatrix.sync.aligned.m8n8.x4.shared.b16 {%0,%1,%2,%3}, [%4];"
                 : "=r"(r[0]), "=r"(r[1]), "=r"(r[2]), "=r"(r[3]) : "r"(a));
}
__device__ __forceinline__ void ldsm2(uint32_t* r, uint32_t a) {
    asm volatile("ldmatrix.sync.aligned.m8n8.x2.shared.b16 {%0,%1}, [%2];"
                 : "=r"(r[0]), "=r"(r[1]) : "r"(a));
}
__device__ __forceinline__ void mma16816(float* c, const uint32_t* a, const uint32_t* b) {
    asm volatile(
        "mma.sync.aligned.m16n8k16.row.col.f32.bf16.bf16.f32 "
        "{%0,%1,%2,%3}, {%4,%5,%6,%7}, {%8,%9}, {%0,%1,%2,%3};"
        : "+f"(c[0]), "+f"(c[1]), "+f"(c[2]), "+f"(c[3])
        : "r"(a[0]), "r"(a[1]), "r"(a[2]), "r"(a[3]), "r"(b[0]), "r"(b[1]));
}
union BF4 { __nv_bfloat16 h[4]; uint2 u; };
__device__ __forceinline__ void split4(const float4 v, uint2& hi, uint2& lo) {
    BF4 H, L;
    H.h[0] = __float2bfloat16(v.x); L.h[0] = __float2bfloat16(v.x - __bfloat162float(H.h[0]));
    H.h[1] = __float2bfloat16(v.y); L.h[1] = __float2bfloat16(v.y - __bfloat162float(H.h[1]));
    H.h[2] = __float2bfloat16(v.z); L.h[2] = __float2bfloat16(v.z - __bfloat162float(H.h[2]));
    H.h[3] = __float2bfloat16(v.w); L.h[3] = __float2bfloat16(v.w - __bfloat162float(H.h[3]));
    hi = H.u; lo = L.u;
}

// ---------------------------------------------------------------------------
// Kernel 1: fused attention, TS=8, cp.async double buffered, dynamic smem.
// ---------------------------------------------------------------------------
#define TS 8
__global__ __launch_bounds__(256)
void attention_kernel(const int* __restrict__ idx,
                      const float* __restrict__ hid,
                      const float* __restrict__ enc,
                      const float* __restrict__ emb_table,
                      float* __restrict__ attn_out)
{
    float* tile   = (float*)dynsm;
    float* en_all = tile + 2 * TS * HDIM;
    float* red    = en_all + SLEN;

    const int b = blockIdx.x;
    const int t = threadIdx.x;
    const int warp = t >> 5;

    const float4* enc4 = (const float4*)(enc + (size_t)b * SLEN * HDIM);
    const float4  h4   = ((const float4*)(hid + (size_t)b * HDIM))[t];

    float* Xrow = g_X + (size_t)b * KXP;
    ((float4*)(Xrow + EDIM + HDIM))[t] = h4;
    const int ci = idx[b];
    for (int j = t; j < EDIM; j += 256)
        Xrow[j] = emb_table[(size_t)ci * EDIM + j];
    if (t < 4) Xrow[KX + t] = 0.f;

    #pragma unroll
    for (int i = 0; i < TS; ++i)
        cp_async16(&tile[i * HDIM + t * 4], &enc4[i * 256 + t]);
    cp_commit();

    float4 ctx = make_float4(0.f, 0.f, 0.f, 0.f);
    float m = -1e30f, d = 0.f;

    const int NSTAGE = SLEN / TS;
    for (int c = 0; c < NSTAGE; ++c) {
        const int buf = c & 1;
        float* cur = tile + buf * TS * HDIM;
        if (c + 1 < NSTAGE) {
            float* nxt = tile + (buf ^ 1) * TS * HDIM;
            const int s0n = (c + 1) * TS;
            #pragma unroll
            for (int i = 0; i < TS; ++i)
                cp_async16(&nxt[i * HDIM + t * 4], &enc4[(size_t)(s0n + i) * 256 + t]);
        }
        cp_commit();
        cp_wait<1>();
        __syncthreads();

        float part[TS];
        #pragma unroll
        for (int s = 0; s < TS; ++s) {
            const float4 e4 = ((const float4*)&cur[s * HDIM])[t];
            part[s] = e4.x * h4.x + e4.y * h4.y + e4.z * h4.z + e4.w * h4.w;
        }
        #pragma unroll
        for (int s = 0; s < TS; ++s)
            #pragma unroll
            for (int o = 16; o > 0; o >>= 1)
                part[s] += __shfl_down_sync(0xffffffffu, part[s], o);
        if ((t & 31) == 0) {
            #pragma unroll
            for (int s = 0; s < TS; ++s) red[warp * TS + s] = part[s];
        }
        __syncthreads();

        float en[TS];
        #pragma unroll
        for (int s = 0; s < TS; ++s) {
            float e = 0.f;
            #pragma unroll
            for (int w = 0; w < 8; ++w) e += red[w * TS + s];
            en[s] = e;
        }
        float tmax = en[0];
        #pragma unroll
        for (int s = 1; s < TS; ++s) tmax = fmaxf(tmax, en[s]);
        const float nm = fmaxf(m, tmax);
        const float f = __expf(m - nm);
        float p[TS], psum = 0.f;
        #pragma unroll
        for (int s = 0; s < TS; ++s) { p[s] = __expf(en[s] - nm); psum += p[s]; }
        d = d * f + psum;
        m = nm;

        ctx.x *= f; ctx.y *= f; ctx.z *= f; ctx.w *= f;
        #pragma unroll
        for (int s = 0; s < TS; ++s) {
            const float4 e4 = ((const float4*)&cur[s * HDIM])[t];
            ctx.x += p[s] * e4.x;
            ctx.y += p[s] * e4.y;
            ctx.z += p[s] * e4.z;
            ctx.w += p[s] * e4.w;
        }
        if (t < TS) en_all[c * TS + t] = en[t];
        __syncthreads();
    }

    const float inv = 1.f / d;
    float4 cc = make_float4(ctx.x * inv, ctx.y * inv, ctx.z * inv, ctx.w * inv);
    ((float4*)(Xrow + EDIM))[t] = cc;

    for (int s = t; s < SLEN; s += 256)
        attn_out[(size_t)b * SLEN + s] = __expf(en_all[s] - m) * inv;
}

// ---------------------------------------------------------------------------
// Kernel 1b: pack weights
// ---------------------------------------------------------------------------
__global__ void pack_weights(const float* __restrict__ W_ih,
                             const float* __restrict__ W_hh)
{
    const int i = blockIdx.x * 256 + threadIdx.x;
    if (i >= HDIM * KXP) return;
    const int n = i / KXP, k = i % KXP;
    float v = 0.f;
    if (k < EDIM + HDIM)      v = W_ih[(size_t)n * (EDIM + HDIM) + k];
    else if (k < KX)          v = W_hh[(size_t)n * HDIM + (k - (EDIM + HDIM))];
    g_Wpack[i] = v;
}

// ---------------------------------------------------------------------------
// Kernel 2: RNN step GEMM (SIMT, small)
// ---------------------------------------------------------------------------
__global__ __launch_bounds__(256)
void rnn_gemm(const float* __restrict__ b_ih,
              const float* __restrict__ b_hh,
              float* __restrict__ hn)
{
    __shared__ float As[2][16][64];
    __shared__ float Bs[2][16][64];

    const int tid = threadIdx.x;
    const int tx = tid % 16, ty = tid / 16;
    const int m0 = blockIdx.y * 64;
    const int n0 = blockIdx.x * 64;
    const int lm = tid >> 2, lk4 = (tid & 3) << 2;

    float acc[4][4] = {};
    const int NIT = KXP / 16;

    {
        float4 av = *(const float4*)(g_X + (size_t)(m0 + lm) * KXP + lk4);
        float4 bv = *(const float4*)(g_Wpack + (size_t)(n0 + lm) * KXP + lk4);
        As[0][lk4 + 0][lm] = av.x; As[0][lk4 + 1][lm] = av.y;
        As[0][lk4 + 2][lm] = av.z; As[0][lk4 + 3][lm] = av.w;
        Bs[0][lk4 + 0][lm] = bv.x; Bs[0][lk4 + 1][lm] = bv.y;
        Bs[0][lk4 + 2][lm] = bv.z; Bs[0][lk4 + 3][lm] = bv.w;
    }
    __syncthreads();

    for (int it = 0; it < NIT; ++it) {
        const int buf = it & 1;
        float4 av, bv;
        const bool more = (it + 1 < NIT);
        if (more) {
            const int k0 = (it + 1) * 16;
            av = *(const float4*)(g_X + (size_t)(m0 + lm) * KXP + k0 + lk4);
            bv = *(const float4*)(g_Wpack + (size_t)(n0 + lm) * KXP + k0 + lk4);
        }
        #pragma unroll
        for (int kk = 0; kk < 16; ++kk) {
            const float4 a = *(const float4*)&As[buf][kk][ty * 4];
            const float4 bq = *(const float4*)&Bs[buf][kk][tx * 4];
            const float aa[4] = {a.x, a.y, a.z, a.w};
            const float bb[4] = {bq.x, bq.y, bq.z, bq.w};
            #pragma unroll
            for (int i = 0; i < 4; ++i)
                #pragma unroll
                for (int j = 0; j < 4; ++j)
                    acc[i][j] += aa[i] * bb[j];
        }
        if (more) {
            As[buf ^ 1][lk4 + 0][lm] = av.x; As[buf ^ 1][lk4 + 1][lm] = av.y;
            As[buf ^ 1][lk4 + 2][lm] = av.z; As[buf ^ 1][lk4 + 3][lm] = av.w;
            Bs[buf ^ 1][lk4 + 0][lm] = bv.x; Bs[buf ^ 1][lk4 + 1][lm] = bv.y;
            Bs[buf ^ 1][lk4 + 2][lm] = bv.z; Bs[buf ^ 1][lk4 + 3][lm] = bv.w;
        }
        __syncthreads();
    }

    #pragma unroll
    for (int i = 0; i < 4; ++i) {
        const int mrow = m0 + ty * 4 + i;
        const int ncol = n0 + tx * 4;
        float4 o;
        o.x = tanhf(acc[i][0] + b_ih[ncol + 0] + b_hh[ncol + 0]);
        o.y = tanhf(acc[i][1] + b_ih[ncol + 1] + b_hh[ncol + 1]);
        o.z = tanhf(acc[i][2] + b_ih[ncol + 2] + b_hh[ncol + 2]);
        o.w = tanhf(acc[i][3] + b_ih[ncol + 3] + b_hh[ncol + 3]);
        *(float4*)(hn + (size_t)mrow * HDIM + ncol) = o;
    }
}

// ---------------------------------------------------------------------------
// Kernel 3: logits via mma.sync bf16x3 split.
// CTA: M=256 (all), N=64. 8 warps (4m x 2n), warp tile 64x32. K stages of 16.
// smem/stage (20KB): Ah[256x16 bf16] Al Bh[64x16] Bl, XOR-16B swizzle. x2 stages.
// ---------------------------------------------------------------------------
#define STG 20480
#define AL_OFF 8192
#define BH_OFF 16384
#define BL_OFF 18432

__global__ __launch_bounds__(256, 1)
void logits_mma(const float* __restrict__ A,    // h_new [256][1024]
                const float* __restrict__ Wf,   // [32000][1024]
                const float* __restrict__ bf,
                float* __restrict__ Cout)
{
    const uint32_t smb = s2u(dynsm);
    const int tid = threadIdx.x, lane = tid & 31, warp = tid >> 5;
    const int n0 = blockIdx.x * 64;
    const int wm = (warp >> 1) * 64;
    const int wn = (warp & 1) * 32;

    // loader mapping (A: 4 float4/thread, B: 1 float4/thread)
    int arow[4], asrc[4]; uint32_t asts[4];
    #pragma unroll
    for (int i = 0; i < 4; ++i) {
        const int f = i * 256 + tid;
        arow[i] = f >> 2;
        const int c4 = f & 3;
        asrc[i] = c4 * 4;
        asts[i] = (uint32_t)(arow[i] * 32 + ((c4 * 8) ^ (((arow[i] >> 2) & 1) << 4)));
    }
    const int brow = tid >> 2, bc4 = tid & 3;
    const uint32_t bsts = (uint32_t)(brow * 32 + ((bc4 * 8) ^ (((brow >> 2) & 1) << 4)));

    // ldmatrix per-lane relative offsets
    const int lr = lane & 7, lq = (lane >> 3) & 1, lh = lane >> 4;
    uint32_t aoff[4], boff[4];
    #pragma unroll
    for (int mf = 0; mf < 4; ++mf) {
        const int row = wm + mf * 16 + lr + lq * 8;
        aoff[mf] = (uint32_t)(row * 32 + ((lh * 16) ^ (((row >> 2) & 1) << 4)));
    }
    #pragma unroll
    for (int nf = 0; nf < 4; ++nf) {
        const int row = wn + nf * 8 + lr;
        boff[nf] = (uint32_t)(row * 32 + ((lq * 16) ^ (((row >> 2) & 1) << 4)));
    }

    float c[4][4][4] = {};

    float4 ra[4], rb;

    // prologue: stage 0
    #pragma unroll
    for (int i = 0; i < 4; ++i)
        ra[i] = *(const float4*)(A + (size_t)arow[i] * HDIM + asrc[i]);
    rb = *(const float4*)(Wf + (size_t)(n0 + brow) * HDIM + bc4 * 4);
    {
        char* base = dynsm;
        uint2 hi, lo;
        #pragma unroll
        for (int i = 0; i < 4; ++i) {
            split4(ra[i], hi, lo);
            *(uint2*)(base + asts[i]) = hi;
            *(uint2*)(base + AL_OFF + asts[i]) = lo;
        }
        split4(rb, hi, lo);
        *(uint2*)(base + BH_OFF + bsts) = hi;
        *(uint2*)(base + BL_OFF + bsts) = lo;
    }
    __syncthreads();

    const int NS = HDIM / 16;   // 64
    for (int s = 0; s < NS; ++s) {
        const int buf = s & 1;
        const uint32_t Ah = smb + buf * STG;
        const uint32_t Al = Ah + AL_OFF;
        const uint32_t Bh = Ah + BH_OFF;
        const uint32_t Bl = Ah + BL_OFF;

        const bool more = (s + 1 < NS);
        if (more) {
            const int kc = (s + 1) * 16;
            #pragma unroll
            for (int i = 0; i < 4; ++i)
                ra[i] = *(const float4*)(A + (size_t)arow[i] * HDIM + kc + asrc[i]);
            rb = *(const float4*)(Wf + (size_t)(n0 + brow) * HDIM + kc + bc4 * 4);
        }

        uint32_t bh[4][2], bl[4][2];
        #pragma unroll
        for (int nf = 0; nf < 4; ++nf) {
            ldsm2(bh[nf], Bh + boff[nf]);
            ldsm2(bl[nf], Bl + boff[nf]);
        }
        #pragma unroll
        for (int mf = 0; mf < 4; ++mf) {
            uint32_t ah[4], al[4];
            ldsm4(ah, Ah + aoff[mf]);
            ldsm4(al, Al + aoff[mf]);
            #pragma unroll
            for (int nf = 0; nf < 4; ++nf) {
                mma16816(c[mf][nf], ah, bh[nf]);
                mma16816(c[mf][nf], ah, bl[nf]);
                mma16816(c[mf][nf], al, bh[nf]);
            }
        }

        if (more) {
            char* base = dynsm + (buf ^ 1) * STG;
            uint2 hi, lo;
            #pragma unroll
            for (int i = 0; i < 4; ++i) {
                split4(ra[i], hi, lo);
                *(uint2*)(base + asts[i]) = hi;
                *(uint2*)(base + AL_OFF + asts[i]) = lo;
            }
            split4(rb, hi, lo);
            *(uint2*)(base + BH_OFF + bsts) = hi;
            *(uint2*)(base + BL_OFF + bsts) = lo;
        }
        __syncthreads();
    }

    // epilogue: bias + store
    #pragma unroll
    for (int mf = 0; mf < 4; ++mf) {
        const int m = wm + mf * 16 + (lane >> 2);
        #pragma unroll
        for (int nf = 0; nf < 4; ++nf) {
            const int n = n0 + wn + nf * 8 + (lane & 3) * 2;
            const float b0 = bf[n], b1 = bf[n + 1];
            float2 o0 = make_float2(c[mf][nf][0] + b0, c[mf][nf][1] + b1);
            float2 o1 = make_float2(c[mf][nf][2] + b0, c[mf][nf][3] + b1);
            *(float2*)(Cout + (size_t)m * VOC + n) = o0;
            *(float2*)(Cout + (size_t)(m + 8) * VOC + n) = o1;
        }
    }
}

// ---------------------------------------------------------------------------
// Launch
// ---------------------------------------------------------------------------
extern "C" void kernel_launch(void* const* d_in, const int* in_sizes, int n_in,
                              void* d_out, int out_size)
{
    const int*   idx   = (const int*)d_in[0];
    const float* hid   = (const float*)d_in[1];
    const float* enc   = (const float*)d_in[2];
    const float* emb   = (const float*)d_in[3];
    const float* W_ih  = (const float*)d_in[4];
    const float* b_ih  = (const float*)d_in[5];
    const float* W_hh  = (const float*)d_in[6];
    const float* b_hh  = (const float*)d_in[7];
    const float* fc_W  = (const float*)d_in[8];
    const float* fc_b  = (const float*)d_in[9];

    float* out    = (float*)d_out;
    float* logits = out;
    float* hn     = out + (size_t)BSZ * VOC;
    float* attn   = out + (size_t)BSZ * VOC + (size_t)BSZ * HDIM;

    const int attn_smem = (2 * TS * HDIM + SLEN + 64) * 4;
    const int mma_smem  = 2 * STG;

    cudaFuncSetAttribute(attention_kernel, cudaFuncAttributeMaxDynamicSharedMemorySize, attn_smem);
    cudaFuncSetAttribute(logits_mma,       cudaFuncAttributeMaxDynamicSharedMemorySize, mma_smem);

    pack_weights<<<(HDIM * KXP + 255) / 256, 256>>>(W_ih, W_hh);
    attention_kernel<<<BSZ, 256, attn_smem>>>(idx, hid, enc, emb, attn);
    rnn_gemm<<<dim3(HDIM / 64, BSZ / 64), 256>>>(b_ih, b_hh, hn);
    logits_mma<<<VOC / 64, 256, mma_smem>>>(hn, fc_W, fc_b, logits);
}

// round 5
// speedup vs baseline: 3.0679x; 1.0825x over previous
#include <cuda_runtime.h>
#include <cuda_bf16.h>
#include <math.h>
#include <stdint.h>

#define BSZ 256
#define SLEN 512
#define HDIM 1024
#define EDIM 300
#define VOC 32000
#define KX  (EDIM + HDIM + HDIM)   // 2348
#define KXP 2352

__device__ float g_X[BSZ * KXP];
__device__ float g_Wpack[HDIM * KXP];
__device__ __nv_bfloat16 g_Ahi[BSZ * HDIM];
__device__ __nv_bfloat16 g_Alo[BSZ * HDIM];
__device__ float g_ctx[2][BSZ][HDIM];
__device__ float g_en[BSZ][SLEN];
__device__ float2 g_md[2][BSZ];

extern __shared__ char dynsm[];

// ---------------------------------------------------------------------------
// helpers
// ---------------------------------------------------------------------------
__device__ __forceinline__ uint32_t s2u(const void* p) {
    return (uint32_t)__cvta_generic_to_shared(p);
}
__device__ __forceinline__ void cp_async16(void* smem_dst, const void* gmem_src) {
    uint32_t s = s2u(smem_dst);
    asm volatile("cp.async.cg.shared.global [%0], [%1], 16;\n" :: "r"(s), "l"(gmem_src));
}
__device__ __forceinline__ void cp_commit() { asm volatile("cp.async.commit_group;\n"); }
template<int N> __device__ __forceinline__ void cp_wait() {
    asm volatile("cp.async.wait_group %0;\n" :: "n"(N) : "memory");
}
__device__ __forceinline__ void ldsm4(uint32_t* r, uint32_t a) {
    asm volatile("ldmatrix.sync.aligned.m8n8.x4.shared.b16 {%0,%1,%2,%3}, [%4];"
                 : "=r"(r[0]), "=r"(r[1]), "=r"(r[2]), "=r"(r[3]) : "r"(a));
}
__device__ __forceinline__ void ldsm2(uint32_t* r, uint32_t a) {
    asm volatile("ldmatrix.sync.aligned.m8n8.x2.shared.b16 {%0,%1}, [%2];"
                 : "=r"(r[0]), "=r"(r[1]) : "r"(a));
}
__device__ __forceinline__ void mma16816(float* c, const uint32_t* a, const uint32_t* b) {
    asm volatile(
        "mma.sync.aligned.m16n8k16.row.col.f32.bf16.bf16.f32 "
        "{%0,%1,%2,%3}, {%4,%5,%6,%7}, {%8,%9}, {%0,%1,%2,%3};"
        : "+f"(c[0]), "+f"(c[1]), "+f"(c[2]), "+f"(c[3])
        : "r"(a[0]), "r"(a[1]), "r"(a[2]), "r"(a[3]), "r"(b[0]), "r"(b[1]));
}
union BF4 { __nv_bfloat16 h[4]; uint2 u; };
__device__ __forceinline__ void split8(const float4 a, const float4 b, uint4& hi, uint4& lo) {
    BF4 H0, L0, H1, L1;
    H0.h[0] = __float2bfloat16(a.x); L0.h[0] = __float2bfloat16(a.x - __bfloat162float(H0.h[0]));
    H0.h[1] = __float2bfloat16(a.y); L0.h[1] = __float2bfloat16(a.y - __bfloat162float(H0.h[1]));
    H0.h[2] = __float2bfloat16(a.z); L0.h[2] = __float2bfloat16(a.z - __bfloat162float(H0.h[2]));
    H0.h[3] = __float2bfloat16(a.w); L0.h[3] = __float2bfloat16(a.w - __bfloat162float(H0.h[3]));
    H1.h[0] = __float2bfloat16(b.x); L1.h[0] = __float2bfloat16(b.x - __bfloat162float(H1.h[0]));
    H1.h[1] = __float2bfloat16(b.y); L1.h[1] = __float2bfloat16(b.y - __bfloat162float(H1.h[1]));
    H1.h[2] = __float2bfloat16(b.z); L1.h[2] = __float2bfloat16(b.z - __bfloat162float(H1.h[2]));
    H1.h[3] = __float2bfloat16(b.w); L1.h[3] = __float2bfloat16(b.w - __bfloat162float(H1.h[3]));
    hi = make_uint4(H0.u.x, H0.u.y, H1.u.x, H1.u.y);
    lo = make_uint4(L0.u.x, L0.u.y, L1.u.x, L1.u.y);
}

// ---------------------------------------------------------------------------
// Kernel 1: attention halves. grid = BSZ*2 (bx>>1 = b, bx&1 = half).
// Each CTA handles 256 seq positions with online softmax; partials to scratch.
// smem: tile ring3 [3][TS*HDIM] + red[8*TS]
// ---------------------------------------------------------------------------
#define TS 8
#define HSTAGES 32   // 256/TS
__global__ __launch_bounds__(256)
void attention_half(const float* __restrict__ hid,
                    const float* __restrict__ enc)
{
    float* tile = (float*)dynsm;
    float* red  = tile + 3 * TS * HDIM;

    const int b = blockIdx.x >> 1;
    const int half = blockIdx.x & 1;
    const int t = threadIdx.x;
    const int warp = t >> 5;

    const float4* enc4 = (const float4*)(enc + (size_t)b * SLEN * HDIM + (size_t)half * 256 * HDIM);
    const float4  h4   = ((const float4*)(hid + (size_t)b * HDIM))[t];

    // prefetch stages 0,1
    #pragma unroll
    for (int st = 0; st < 2; ++st) {
        #pragma unroll
        for (int i = 0; i < TS; ++i)
            cp_async16(&tile[st * TS * HDIM + i * HDIM + t * 4], &enc4[(st * TS + i) * 256 + t]);
        cp_commit();
    }

    float4 ctx = make_float4(0.f, 0.f, 0.f, 0.f);
    float m = -1e30f, d = 0.f;

    for (int c = 0; c < HSTAGES; ++c) {
        if (c + 2 < HSTAGES) {
            float* nxt = tile + ((c + 2) % 3) * TS * HDIM;
            const int s0n = (c + 2) * TS;
            #pragma unroll
            for (int i = 0; i < TS; ++i)
                cp_async16(&nxt[i * HDIM + t * 4], &enc4[(size_t)(s0n + i) * 256 + t]);
        }
        cp_commit();
        cp_wait<2>();
        __syncthreads();

        float* cur = tile + (c % 3) * TS * HDIM;
        float part[TS];
        #pragma unroll
        for (int s = 0; s < TS; ++s) {
            const float4 e4 = ((const float4*)&cur[s * HDIM])[t];
            part[s] = e4.x * h4.x + e4.y * h4.y + e4.z * h4.z + e4.w * h4.w;
        }
        #pragma unroll
        for (int s = 0; s < TS; ++s)
            #pragma unroll
            for (int o = 16; o > 0; o >>= 1)
                part[s] += __shfl_down_sync(0xffffffffu, part[s], o);
        if ((t & 31) == 0) {
            #pragma unroll
            for (int s = 0; s < TS; ++s) red[warp * TS + s] = part[s];
        }
        __syncthreads();

        float en[TS];
        #pragma unroll
        for (int s = 0; s < TS; ++s) {
            float e = 0.f;
            #pragma unroll
            for (int w = 0; w < 8; ++w) e += red[w * TS + s];
            en[s] = e;
        }
        float tmax = en[0];
        #pragma unroll
        for (int s = 1; s < TS; ++s) tmax = fmaxf(tmax, en[s]);
        const float nm = fmaxf(m, tmax);
        const float f = __expf(m - nm);
        float p[TS], psum = 0.f;
        #pragma unroll
        for (int s = 0; s < TS; ++s) { p[s] = __expf(en[s] - nm); psum += p[s]; }
        d = d * f + psum;
        m = nm;

        ctx.x *= f; ctx.y *= f; ctx.z *= f; ctx.w *= f;
        #pragma unroll
        for (int s = 0; s < TS; ++s) {
            const float4 e4 = ((const float4*)&cur[s * HDIM])[t];
            ctx.x += p[s] * e4.x;
            ctx.y += p[s] * e4.y;
            ctx.z += p[s] * e4.z;
            ctx.w += p[s] * e4.w;
        }
        if (t < TS) g_en[b][half * 256 + c * TS + t] = en[t];
    }

    ((float4*)&g_ctx[half][b][0])[t] = ctx;
    if (t == 0) g_md[half][b] = make_float2(m, d);
}

// ---------------------------------------------------------------------------
// Kernel 1c: merge halves; build X = [emb | ctx | h]; write attn probs.
// ---------------------------------------------------------------------------
__global__ __launch_bounds__(256)
void attention_merge(const int* __restrict__ idx,
                     const float* __restrict__ hid,
                     const float* __restrict__ emb_table,
                     float* __restrict__ attn_out)
{
    const int b = blockIdx.x;
    const int t = threadIdx.x;

    const float2 md0 = g_md[0][b];
    const float2 md1 = g_md[1][b];
    const float m = fmaxf(md0.x, md1.x);
    const float f0 = __expf(md0.x - m), f1 = __expf(md1.x - m);
    const float dd = md0.y * f0 + md1.y * f1;
    const float inv = 1.f / dd;

    float* Xrow = g_X + (size_t)b * KXP;

    const float4 c0 = ((const float4*)&g_ctx[0][b][0])[t];
    const float4 c1 = ((const float4*)&g_ctx[1][b][0])[t];
    float4 cc;
    cc.x = (c0.x * f0 + c1.x * f1) * inv;
    cc.y = (c0.y * f0 + c1.y * f1) * inv;
    cc.z = (c0.z * f0 + c1.z * f1) * inv;
    cc.w = (c0.w * f0 + c1.w * f1) * inv;
    ((float4*)(Xrow + EDIM))[t] = cc;

    ((float4*)(Xrow + EDIM + HDIM))[t] = ((const float4*)(hid + (size_t)b * HDIM))[t];

    const int ci = idx[b];
    for (int j = t; j < EDIM; j += 256)
        Xrow[j] = emb_table[(size_t)ci * EDIM + j];
    if (t < 4) Xrow[KX + t] = 0.f;

    for (int s = t; s < SLEN; s += 256)
        attn_out[(size_t)b * SLEN + s] = __expf(g_en[b][s] - m) * inv;
}

// ---------------------------------------------------------------------------
// Kernel 1b: pack weights
// ---------------------------------------------------------------------------
__global__ void pack_weights(const float* __restrict__ W_ih,
                             const float* __restrict__ W_hh)
{
    const int i = blockIdx.x * 256 + threadIdx.x;
    if (i >= HDIM * KXP) return;
    const int n = i / KXP, k = i % KXP;
    float v = 0.f;
    if (k < EDIM + HDIM)      v = W_ih[(size_t)n * (EDIM + HDIM) + k];
    else if (k < KX)          v = W_hh[(size_t)n * HDIM + (k - (EDIM + HDIM))];
    g_Wpack[i] = v;
}

// ---------------------------------------------------------------------------
// Kernel 2: RNN step GEMM; epilogue also writes bf16 hi/lo split of h_new.
// ---------------------------------------------------------------------------
__global__ __launch_bounds__(256)
void rnn_gemm(const float* __restrict__ b_ih,
              const float* __restrict__ b_hh,
              float* __restrict__ hn)
{
    __shared__ float As[2][16][64];
    __shared__ float Bs[2][16][64];

    const int tid = threadIdx.x;
    const int tx = tid % 16, ty = tid / 16;
    const int m0 = blockIdx.y * 64;
    const int n0 = blockIdx.x * 64;
    const int lm = tid >> 2, lk4 = (tid & 3) << 2;

    float acc[4][4] = {};
    const int NIT = KXP / 16;

    {
        float4 av = *(const float4*)(g_X + (size_t)(m0 + lm) * KXP + lk4);
        float4 bv = *(const float4*)(g_Wpack + (size_t)(n0 + lm) * KXP + lk4);
        As[0][lk4 + 0][lm] = av.x; As[0][lk4 + 1][lm] = av.y;
        As[0][lk4 + 2][lm] = av.z; As[0][lk4 + 3][lm] = av.w;
        Bs[0][lk4 + 0][lm] = bv.x; Bs[0][lk4 + 1][lm] = bv.y;
        Bs[0][lk4 + 2][lm] = bv.z; Bs[0][lk4 + 3][lm] = bv.w;
    }
    __syncthreads();

    for (int it = 0; it < NIT; ++it) {
        const int buf = it & 1;
        float4 av, bv;
        const bool more = (it + 1 < NIT);
        if (more) {
            const int k0 = (it + 1) * 16;
            av = *(const float4*)(g_X + (size_t)(m0 + lm) * KXP + k0 + lk4);
            bv = *(const float4*)(g_Wpack + (size_t)(n0 + lm) * KXP + k0 + lk4);
        }
        #pragma unroll
        for (int kk = 0; kk < 16; ++kk) {
            const float4 a = *(const float4*)&As[buf][kk][ty * 4];
            const float4 bq = *(const float4*)&Bs[buf][kk][tx * 4];
            const float aa[4] = {a.x, a.y, a.z, a.w};
            const float bb[4] = {bq.x, bq.y, bq.z, bq.w};
            #pragma unroll
            for (int i = 0; i < 4; ++i)
                #pragma unroll
                for (int j = 0; j < 4; ++j)
                    acc[i][j] += aa[i] * bb[j];
        }
        if (more) {
            As[buf ^ 1][lk4 + 0][lm] = av.x; As[buf ^ 1][lk4 + 1][lm] = av.y;
            As[buf ^ 1][lk4 + 2][lm] = av.z; As[buf ^ 1][lk4 + 3][lm] = av.w;
            Bs[buf ^ 1][lk4 + 0][lm] = bv.x; Bs[buf ^ 1][lk4 + 1][lm] = bv.y;
            Bs[buf ^ 1][lk4 + 2][lm] = bv.z; Bs[buf ^ 1][lk4 + 3][lm] = bv.w;
        }
        __syncthreads();
    }

    #pragma unroll
    for (int i = 0; i < 4; ++i) {
        const int mrow = m0 + ty * 4 + i;
        const int ncol = n0 + tx * 4;
        float4 o;
        o.x = tanhf(acc[i][0] + b_ih[ncol + 0] + b_hh[ncol + 0]);
        o.y = tanhf(acc[i][1] + b_ih[ncol + 1] + b_hh[ncol + 1]);
        o.z = tanhf(acc[i][2] + b_ih[ncol + 2] + b_hh[ncol + 2]);
        o.w = tanhf(acc[i][3] + b_ih[ncol + 3] + b_hh[ncol + 3]);
        *(float4*)(hn + (size_t)mrow * HDIM + ncol) = o;

        BF4 H, L;
        H.h[0] = __float2bfloat16(o.x); L.h[0] = __float2bfloat16(o.x - __bfloat162float(H.h[0]));
        H.h[1] = __float2bfloat16(o.y); L.h[1] = __float2bfloat16(o.y - __bfloat162float(H.h[1]));
        H.h[2] = __float2bfloat16(o.z); L.h[2] = __float2bfloat16(o.z - __bfloat162float(H.h[2]));
        H.h[3] = __float2bfloat16(o.w); L.h[3] = __float2bfloat16(o.w - __bfloat162float(H.h[3]));
        *(uint2*)(g_Ahi + (size_t)mrow * HDIM + ncol) = H.u;
        *(uint2*)(g_Alo + (size_t)mrow * HDIM + ncol) = L.u;
    }
}

// ---------------------------------------------------------------------------
// Kernel 3: logits, mma.sync bf16x3, CTA 128x64, 128 threads, 4 CTAs/SM.
// A (pre-split bf16 hi/lo) via cp.async ring-3; B inline split, reg dbuf.
// smem layout: A slots 3 x 8192 (hi 4096 | lo 4096); B at 24576: 2 x 4096
// ---------------------------------------------------------------------------
#define LA_STG 8192
#define LB_OFF 24576
#define LB_STG 4096
#define L_SMEM 32768

__global__ __launch_bounds__(128, 4)
void logits_mma(const __nv_bfloat16* __restrict__ Ahi,
                const __nv_bfloat16* __restrict__ Alo,
                const float* __restrict__ Wf,
                const float* __restrict__ bf,
                float* __restrict__ Cout)
{
    const uint32_t smb = s2u(dynsm);
    const int tid = threadIdx.x, lane = tid & 31, warp = tid >> 5;
    const int n0 = blockIdx.x * 64;
    const int m0 = blockIdx.y * 128;
    const int wm = (warp >> 1) * 64;
    const int wn = (warp & 1) * 32;

    // A cp.async mapping: 2 chunks (16B) per thread per (hi|lo) buffer
    int arow[2], acol[2]; uint32_t adst[2];
    #pragma unroll
    for (int i = 0; i < 2; ++i) {
        const int f = i * 128 + tid;
        arow[i] = f >> 1;
        const int ch = f & 1;
        acol[i] = ch * 8;
        adst[i] = (uint32_t)(arow[i] * 32 + ((ch * 16) ^ (((arow[i] >> 2) & 1) << 4)));
    }
    // B mapping: 8 fp32 per thread (one 16B bf16 chunk)
    const int brow = tid >> 1, bhalf = tid & 1;
    const uint32_t bdst = (uint32_t)(brow * 32 + ((bhalf * 16) ^ (((brow >> 2) & 1) << 4)));
    const float* bsrc = Wf + (size_t)(n0 + brow) * HDIM + bhalf * 8;

    // ldmatrix offsets
    const int lr = lane & 7, lq = (lane >> 3) & 1, lh = lane >> 4;
    uint32_t aoff[4], boff[4];
    #pragma unroll
    for (int mf = 0; mf < 4; ++mf) {
        const int row = wm + mf * 16 + lr + lq * 8;
        aoff[mf] = (uint32_t)(row * 32 + ((lh * 16) ^ (((row >> 2) & 1) << 4)));
    }
    #pragma unroll
    for (int nf = 0; nf < 4; ++nf) {
        const int row = wn + nf * 8 + lr;
        boff[nf] = (uint32_t)(row * 32 + ((lq * 16) ^ (((row >> 2) & 1) << 4)));
    }

    float c[4][4][4] = {};

    // prologue: B stage0 LDG + STS, A stages 0,1 cp.async
    float4 rb0 = *(const float4*)bsrc;
    float4 rb1 = *(const float4*)(bsrc + 4);
    #pragma unroll
    for (int st = 0; st < 2; ++st) {
        char* base = dynsm + st * LA_STG;
        #pragma unroll
        for (int i = 0; i < 2; ++i) {
            cp_async16(base + adst[i],        Ahi + (size_t)(m0 + arow[i]) * HDIM + st * 16 + acol[i]);
            cp_async16(base + 4096 + adst[i], Alo + (size_t)(m0 + arow[i]) * HDIM + st * 16 + acol[i]);
        }
        cp_commit();
    }
    {
        uint4 hi, lo;
        split8(rb0, rb1, hi, lo);
        *(uint4*)(dynsm + LB_OFF + bdst) = hi;
        *(uint4*)(dynsm + LB_OFF + 2048 + bdst) = lo;
    }

    const int NS = HDIM / 16;   // 64
    for (int s = 0; s < NS; ++s) {
        const bool more = (s + 1 < NS);
        if (more) {
            rb0 = *(const float4*)(bsrc + (s + 1) * 16);
            rb1 = *(const float4*)(bsrc + (s + 1) * 16 + 4);
        }
        cp_wait<1>();
        __syncthreads();

        // issue A stage s+2
        if (s + 2 < NS) {
            char* base = dynsm + ((s + 2) % 3) * LA_STG;
            #pragma unroll
            for (int i = 0; i < 2; ++i) {
                cp_async16(base + adst[i],        Ahi + (size_t)(m0 + arow[i]) * HDIM + (s + 2) * 16 + acol[i]);
                cp_async16(base + 4096 + adst[i], Alo + (size_t)(m0 + arow[i]) * HDIM + (s + 2) * 16 + acol[i]);
            }
        }
        cp_commit();

        // STS B stage s+1
        if (more) {
            uint4 hi, lo;
            split8(rb0, rb1, hi, lo);
            char* bb = dynsm + LB_OFF + ((s + 1) & 1) * LB_STG;
            *(uint4*)(bb + bdst) = hi;
            *(uint4*)(bb + 2048 + bdst) = lo;
        }

        // compute on stage s
        const uint32_t Ah = smb + (s % 3) * LA_STG;
        const uint32_t Al = Ah + 4096;
        const uint32_t Bh = smb + LB_OFF + (s & 1) * LB_STG;
        const uint32_t Bl = Bh + 2048;

        uint32_t bh[4][2], bl[4][2];
        #pragma unroll
        for (int nf = 0; nf < 4; ++nf) {
            ldsm2(bh[nf], Bh + boff[nf]);
            ldsm2(bl[nf], Bl + boff[nf]);
        }
        #pragma unroll
        for (int mf = 0; mf < 4; ++mf) {
            uint32_t ah[4], al[4];
            ldsm4(ah, Ah + aoff[mf]);
            ldsm4(al, Al + aoff[mf]);
            #pragma unroll
            for (int nf = 0; nf < 4; ++nf) {
                mma16816(c[mf][nf], ah, bh[nf]);
                mma16816(c[mf][nf], ah, bl[nf]);
                mma16816(c[mf][nf], al, bh[nf]);
            }
        }
    }

    // epilogue
    #pragma unroll
    for (int mf = 0; mf < 4; ++mf) {
        const int m = m0 + wm + mf * 16 + (lane >> 2);
        #pragma unroll
        for (int nf = 0; nf < 4; ++nf) {
            const int n = n0 + wn + nf * 8 + (lane & 3) * 2;
            const float b0 = bf[n], b1 = bf[n + 1];
            float2 o0 = make_float2(c[mf][nf][0] + b0, c[mf][nf][1] + b1);
            float2 o1 = make_float2(c[mf][nf][2] + b0, c[mf][nf][3] + b1);
            *(float2*)(Cout + (size_t)m * VOC + n) = o0;
            *(float2*)(Cout + (size_t)(m + 8) * VOC + n) = o1;
        }
    }
}

// ---------------------------------------------------------------------------
// Launch
// ---------------------------------------------------------------------------
extern "C" void kernel_launch(void* const* d_in, const int* in_sizes, int n_in,
                              void* d_out, int out_size)
{
    const int*   idx   = (const int*)d_in[0];
    const float* hid   = (const float*)d_in[1];
    const float* enc   = (const float*)d_in[2];
    const float* emb   = (const float*)d_in[3];
    const float* W_ih  = (const float*)d_in[4];
    const float* b_ih  = (const float*)d_in[5];
    const float* W_hh  = (const float*)d_in[6];
    const float* b_hh  = (const float*)d_in[7];
    const float* fc_W  = (const float*)d_in[8];
    const float* fc_b  = (const float*)d_in[9];

    float* out    = (float*)d_out;
    float* logits = out;
    float* hn     = out + (size_t)BSZ * VOC;
    float* attn   = out + (size_t)BSZ * VOC + (size_t)BSZ * HDIM;

    __nv_bfloat16 *Ahi, *Alo;
    cudaGetSymbolAddress((void**)&Ahi, g_Ahi);
    cudaGetSymbolAddress((void**)&Alo, g_Alo);

    const int attn_smem = (3 * TS * HDIM + 8 * TS) * 4;

    cudaFuncSetAttribute(attention_half, cudaFuncAttributeMaxDynamicSharedMemorySize, attn_smem);
    cudaFuncSetAttribute(logits_mma,     cudaFuncAttributeMaxDynamicSharedMemorySize, L_SMEM);

    pack_weights<<<(HDIM * KXP + 255) / 256, 256>>>(W_ih, W_hh);
    attention_half<<<BSZ * 2, 256, attn_smem>>>(hid, enc);
    attention_merge<<<BSZ, 256>>>(idx, hid, emb, attn);
    rnn_gemm<<<dim3(HDIM / 64, BSZ / 64), 256>>>(b_ih, b_hh, hn);
    logits_mma<<<dim3(VOC / 64, BSZ / 128), 128, L_SMEM>>>(Ahi, Alo, fc_W, fc_b, logits);
}

// round 6
// speedup vs baseline: 3.6349x; 1.1848x over previous
#include <cuda_runtime.h>
#include <cuda_bf16.h>
#include <math.h>
#include <stdint.h>

#define BSZ 256
#define SLEN 512
#define HDIM 1024
#define EDIM 300
#define VOC 32000
#define KX  (EDIM + HDIM + HDIM)   // 2348
#define KXP 2352                   // 147 * 16

__device__ __nv_bfloat16 g_Xhi[BSZ * KXP];
__device__ __nv_bfloat16 g_Xlo[BSZ * KXP];
__device__ __nv_bfloat16 g_Whi[HDIM * KXP];
__device__ __nv_bfloat16 g_Wlo[HDIM * KXP];
__device__ __nv_bfloat16 g_Ahi[BSZ * HDIM];
__device__ __nv_bfloat16 g_Alo[BSZ * HDIM];
__device__ float g_ctx[2][BSZ][HDIM];
__device__ float g_en[BSZ][SLEN];
__device__ float2 g_md[2][BSZ];

extern __shared__ char dynsm[];

// ---------------------------------------------------------------------------
// helpers
// ---------------------------------------------------------------------------
__device__ __forceinline__ uint32_t s2u(const void* p) {
    return (uint32_t)__cvta_generic_to_shared(p);
}
__device__ __forceinline__ void cp_async16(void* smem_dst, const void* gmem_src) {
    uint32_t s = s2u(smem_dst);
    asm volatile("cp.async.cg.shared.global [%0], [%1], 16;\n" :: "r"(s), "l"(gmem_src));
}
__device__ __forceinline__ void cp_commit() { asm volatile("cp.async.commit_group;\n"); }
template<int N> __device__ __forceinline__ void cp_wait() {
    asm volatile("cp.async.wait_group %0;\n" :: "n"(N) : "memory");
}
__device__ __forceinline__ void ldsm4(uint32_t* r, uint32_t a) {
    asm volatile("ldmatrix.sync.aligned.m8n8.x4.shared.b16 {%0,%1,%2,%3}, [%4];"
                 : "=r"(r[0]), "=r"(r[1]), "=r"(r[2]), "=r"(r[3]) : "r"(a));
}
__device__ __forceinline__ void ldsm2(uint32_t* r, uint32_t a) {
    asm volatile("ldmatrix.sync.aligned.m8n8.x2.shared.b16 {%0,%1}, [%2];"
                 : "=r"(r[0]), "=r"(r[1]) : "r"(a));
}
__device__ __forceinline__ void mma16816(float* c, const uint32_t* a, const uint32_t* b) {
    asm volatile(
        "mma.sync.aligned.m16n8k16.row.col.f32.bf16.bf16.f32 "
        "{%0,%1,%2,%3}, {%4,%5,%6,%7}, {%8,%9}, {%0,%1,%2,%3};"
        : "+f"(c[0]), "+f"(c[1]), "+f"(c[2]), "+f"(c[3])
        : "r"(a[0]), "r"(a[1]), "r"(a[2]), "r"(a[3]), "r"(b[0]), "r"(b[1]));
}
union BF4 { __nv_bfloat16 h[4]; uint2 u; };
__device__ __forceinline__ void split8(const float4 a, const float4 b, uint4& hi, uint4& lo) {
    BF4 H0, L0, H1, L1;
    H0.h[0] = __float2bfloat16(a.x); L0.h[0] = __float2bfloat16(a.x - __bfloat162float(H0.h[0]));
    H0.h[1] = __float2bfloat16(a.y); L0.h[1] = __float2bfloat16(a.y - __bfloat162float(H0.h[1]));
    H0.h[2] = __float2bfloat16(a.z); L0.h[2] = __float2bfloat16(a.z - __bfloat162float(H0.h[2]));
    H0.h[3] = __float2bfloat16(a.w); L0.h[3] = __float2bfloat16(a.w - __bfloat162float(H0.h[3]));
    H1.h[0] = __float2bfloat16(b.x); L1.h[0] = __float2bfloat16(b.x - __bfloat162float(H1.h[0]));
    H1.h[1] = __float2bfloat16(b.y); L1.h[1] = __float2bfloat16(b.y - __bfloat162float(H1.h[1]));
    H1.h[2] = __float2bfloat16(b.z); L1.h[2] = __float2bfloat16(b.z - __bfloat162float(H1.h[2]));
    H1.h[3] = __float2bfloat16(b.w); L1.h[3] = __float2bfloat16(b.w - __bfloat162float(H1.h[3]));
    hi = make_uint4(H0.u.x, H0.u.y, H1.u.x, H1.u.y);
    lo = make_uint4(L0.u.x, L0.u.y, L1.u.x, L1.u.y);
}
__device__ __forceinline__ void split4v(const float4 v, uint2& hi, uint2& lo) {
    BF4 H, L;
    H.h[0] = __float2bfloat16(v.x); L.h[0] = __float2bfloat16(v.x - __bfloat162float(H.h[0]));
    H.h[1] = __float2bfloat16(v.y); L.h[1] = __float2bfloat16(v.y - __bfloat162float(H.h[1]));
    H.h[2] = __float2bfloat16(v.z); L.h[2] = __float2bfloat16(v.z - __bfloat162float(H.h[2]));
    H.h[3] = __float2bfloat16(v.w); L.h[3] = __float2bfloat16(v.w - __bfloat162float(H.h[3]));
    hi = H.u; lo = L.u;
}

// ---------------------------------------------------------------------------
// Kernel 1: attention halves (unchanged from R5)
// ---------------------------------------------------------------------------
#define TS 8
#define HSTAGES 32
__global__ __launch_bounds__(256)
void attention_half(const float* __restrict__ hid,
                    const float* __restrict__ enc)
{
    float* tile = (float*)dynsm;
    float* red  = tile + 3 * TS * HDIM;

    const int b = blockIdx.x >> 1;
    const int half = blockIdx.x & 1;
    const int t = threadIdx.x;
    const int warp = t >> 5;

    const float4* enc4 = (const float4*)(enc + (size_t)b * SLEN * HDIM + (size_t)half * 256 * HDIM);
    const float4  h4   = ((const float4*)(hid + (size_t)b * HDIM))[t];

    #pragma unroll
    for (int st = 0; st < 2; ++st) {
        #pragma unroll
        for (int i = 0; i < TS; ++i)
            cp_async16(&tile[st * TS * HDIM + i * HDIM + t * 4], &enc4[(st * TS + i) * 256 + t]);
        cp_commit();
    }

    float4 ctx = make_float4(0.f, 0.f, 0.f, 0.f);
    float m = -1e30f, d = 0.f;

    for (int c = 0; c < HSTAGES; ++c) {
        if (c + 2 < HSTAGES) {
            float* nxt = tile + ((c + 2) % 3) * TS * HDIM;
            const int s0n = (c + 2) * TS;
            #pragma unroll
            for (int i = 0; i < TS; ++i)
                cp_async16(&nxt[i * HDIM + t * 4], &enc4[(size_t)(s0n + i) * 256 + t]);
        }
        cp_commit();
        cp_wait<2>();
        __syncthreads();

        float* cur = tile + (c % 3) * TS * HDIM;
        float part[TS];
        #pragma unroll
        for (int s = 0; s < TS; ++s) {
            const float4 e4 = ((const float4*)&cur[s * HDIM])[t];
            part[s] = e4.x * h4.x + e4.y * h4.y + e4.z * h4.z + e4.w * h4.w;
        }
        #pragma unroll
        for (int s = 0; s < TS; ++s)
            #pragma unroll
            for (int o = 16; o > 0; o >>= 1)
                part[s] += __shfl_down_sync(0xffffffffu, part[s], o);
        if ((t & 31) == 0) {
            #pragma unroll
            for (int s = 0; s < TS; ++s) red[warp * TS + s] = part[s];
        }
        __syncthreads();

        float en[TS];
        #pragma unroll
        for (int s = 0; s < TS; ++s) {
            float e = 0.f;
            #pragma unroll
            for (int w = 0; w < 8; ++w) e += red[w * TS + s];
            en[s] = e;
        }
        float tmax = en[0];
        #pragma unroll
        for (int s = 1; s < TS; ++s) tmax = fmaxf(tmax, en[s]);
        const float nm = fmaxf(m, tmax);
        const float f = __expf(m - nm);
        float p[TS], psum = 0.f;
        #pragma unroll
        for (int s = 0; s < TS; ++s) { p[s] = __expf(en[s] - nm); psum += p[s]; }
        d = d * f + psum;
        m = nm;

        ctx.x *= f; ctx.y *= f; ctx.z *= f; ctx.w *= f;
        #pragma unroll
        for (int s = 0; s < TS; ++s) {
            const float4 e4 = ((const float4*)&cur[s * HDIM])[t];
            ctx.x += p[s] * e4.x;
            ctx.y += p[s] * e4.y;
            ctx.z += p[s] * e4.z;
            ctx.w += p[s] * e4.w;
        }
        if (t < TS) g_en[b][half * 256 + c * TS + t] = en[t];
    }

    ((float4*)&g_ctx[half][b][0])[t] = ctx;
    if (t == 0) g_md[half][b] = make_float2(m, d);
}

// ---------------------------------------------------------------------------
// Kernel 1c: merge halves; write X as bf16 hi/lo; write attn probs.
// ---------------------------------------------------------------------------
__global__ __launch_bounds__(256)
void attention_merge(const int* __restrict__ idx,
                     const float* __restrict__ hid,
                     const float* __restrict__ emb_table,
                     float* __restrict__ attn_out)
{
    const int b = blockIdx.x;
    const int t = threadIdx.x;

    const float2 md0 = g_md[0][b];
    const float2 md1 = g_md[1][b];
    const float m = fmaxf(md0.x, md1.x);
    const float f0 = __expf(md0.x - m), f1 = __expf(md1.x - m);
    const float dd = md0.y * f0 + md1.y * f1;
    const float inv = 1.f / dd;

    __nv_bfloat16* Xh = g_Xhi + (size_t)b * KXP;
    __nv_bfloat16* Xl = g_Xlo + (size_t)b * KXP;

    const float4 c0 = ((const float4*)&g_ctx[0][b][0])[t];
    const float4 c1 = ((const float4*)&g_ctx[1][b][0])[t];
    float4 cc;
    cc.x = (c0.x * f0 + c1.x * f1) * inv;
    cc.y = (c0.y * f0 + c1.y * f1) * inv;
    cc.z = (c0.z * f0 + c1.z * f1) * inv;
    cc.w = (c0.w * f0 + c1.w * f1) * inv;
    uint2 hi, lo;
    split4v(cc, hi, lo);
    *(uint2*)(Xh + EDIM + t * 4) = hi;
    *(uint2*)(Xl + EDIM + t * 4) = lo;

    const float4 h4 = ((const float4*)(hid + (size_t)b * HDIM))[t];
    split4v(h4, hi, lo);
    *(uint2*)(Xh + EDIM + HDIM + t * 4) = hi;
    *(uint2*)(Xl + EDIM + HDIM + t * 4) = lo;

    const int ci = idx[b];
    for (int j = t; j < EDIM; j += 256) {
        const float v = emb_table[(size_t)ci * EDIM + j];
        const __nv_bfloat16 H = __float2bfloat16(v);
        Xh[j] = H;
        Xl[j] = __float2bfloat16(v - __bfloat162float(H));
    }
    if (t < 4) { Xh[KX + t] = __float2bfloat16(0.f); Xl[KX + t] = __float2bfloat16(0.f); }

    for (int s = t; s < SLEN; s += 256)
        attn_out[(size_t)b * SLEN + s] = __expf(g_en[b][s] - m) * inv;
}

// ---------------------------------------------------------------------------
// Kernel 1b: pack weights -> bf16 hi/lo [HDIM][KXP]
// ---------------------------------------------------------------------------
__global__ void pack_weights(const float* __restrict__ W_ih,
                             const float* __restrict__ W_hh)
{
    const int i = blockIdx.x * 256 + threadIdx.x;
    if (i >= HDIM * KXP) return;
    const int n = i / KXP, k = i % KXP;
    float v = 0.f;
    if (k < EDIM + HDIM)      v = W_ih[(size_t)n * (EDIM + HDIM) + k];
    else if (k < KX)          v = W_hh[(size_t)n * HDIM + (k - (EDIM + HDIM))];
    const __nv_bfloat16 H = __float2bfloat16(v);
    g_Whi[i] = H;
    g_Wlo[i] = __float2bfloat16(v - __bfloat162float(H));
}

// ---------------------------------------------------------------------------
// Kernel 2: RNN step via mma.sync bf16x3.
// CTA 64x64, 128 threads (4 warps 2x2), cp.async ring-3 on A(X) and B(W).
// smem: A slots 3 x 4096 (hi 2048 | lo 2048), B slots 3 x 4096 at 12288.
// Epilogue: tanh(+biases) -> hn (fp32) and g_Ahi/g_Alo bf16 split.
// ---------------------------------------------------------------------------
#define R_STG 4096
#define R_BOFF 12288
#define R_SMEM 24576

__global__ __launch_bounds__(128, 4)
void rnn_mma(const float* __restrict__ b_ih,
             const float* __restrict__ b_hh,
             float* __restrict__ hn)
{
    const uint32_t smb = s2u(dynsm);
    const int tid = threadIdx.x, lane = tid & 31, warp = tid >> 5;
    const int m0 = blockIdx.y * 64;
    const int n0 = blockIdx.x * 64;
    const int wm = (warp >> 1) * 32;
    const int wn = (warp & 1) * 32;

    // copy mapping: 1 x 16B chunk per thread per sub-buffer
    const int crow = tid >> 1, chalf = tid & 1;
    const uint32_t cdst = (uint32_t)(crow * 32 + ((chalf * 16) ^ (((crow >> 2) & 1) << 4)));
    const __nv_bfloat16* Asrc_h = g_Xhi + (size_t)(m0 + crow) * KXP + chalf * 8;
    const __nv_bfloat16* Asrc_l = g_Xlo + (size_t)(m0 + crow) * KXP + chalf * 8;
    const __nv_bfloat16* Bsrc_h = g_Whi + (size_t)(n0 + crow) * KXP + chalf * 8;
    const __nv_bfloat16* Bsrc_l = g_Wlo + (size_t)(n0 + crow) * KXP + chalf * 8;

    // ldmatrix offsets
    const int lr = lane & 7, lq = (lane >> 3) & 1, lh = lane >> 4;
    uint32_t aoff[2], boff[4];
    #pragma unroll
    for (int mf = 0; mf < 2; ++mf) {
        const int row = wm + mf * 16 + lr + lq * 8;
        aoff[mf] = (uint32_t)(row * 32 + ((lh * 16) ^ (((row >> 2) & 1) << 4)));
    }
    #pragma unroll
    for (int nf = 0; nf < 4; ++nf) {
        const int row = wn + nf * 8 + lr;
        boff[nf] = (uint32_t)(row * 32 + ((lq * 16) ^ (((row >> 2) & 1) << 4)));
    }

    float c[2][4][4] = {};

    const int NS = KXP / 16;   // 147

    // prologue: stages 0,1
    #pragma unroll
    for (int st = 0; st < 2; ++st) {
        char* ab = dynsm + st * R_STG;
        char* bb = dynsm + R_BOFF + st * R_STG;
        cp_async16(ab + cdst,        Asrc_h + st * 16);
        cp_async16(ab + 2048 + cdst, Asrc_l + st * 16);
        cp_async16(bb + cdst,        Bsrc_h + st * 16);
        cp_async16(bb + 2048 + cdst, Bsrc_l + st * 16);
        cp_commit();
    }

    for (int s = 0; s < NS; ++s) {
        if (s + 2 < NS) {
            char* ab = dynsm + ((s + 2) % 3) * R_STG;
            char* bb = dynsm + R_BOFF + ((s + 2) % 3) * R_STG;
            cp_async16(ab + cdst,        Asrc_h + (s + 2) * 16);
            cp_async16(ab + 2048 + cdst, Asrc_l + (s + 2) * 16);
            cp_async16(bb + cdst,        Bsrc_h + (s + 2) * 16);
            cp_async16(bb + 2048 + cdst, Bsrc_l + (s + 2) * 16);
        }
        cp_commit();
        cp_wait<2>();
        __syncthreads();

        const uint32_t Ah = smb + (s % 3) * R_STG;
        const uint32_t Al = Ah + 2048;
        const uint32_t Bh = smb + R_BOFF + (s % 3) * R_STG;
        const uint32_t Bl = Bh + 2048;

        uint32_t bh[4][2], bl[4][2];
        #pragma unroll
        for (int nf = 0; nf < 4; ++nf) {
            ldsm2(bh[nf], Bh + boff[nf]);
            ldsm2(bl[nf], Bl + boff[nf]);
        }
        #pragma unroll
        for (int mf = 0; mf < 2; ++mf) {
            uint32_t ah[4], al[4];
            ldsm4(ah, Ah + aoff[mf]);
            ldsm4(al, Al + aoff[mf]);
            #pragma unroll
            for (int nf = 0; nf < 4; ++nf) {
                mma16816(c[mf][nf], ah, bh[nf]);
                mma16816(c[mf][nf], ah, bl[nf]);
                mma16816(c[mf][nf], al, bh[nf]);
            }
        }
        __syncthreads();
    }

    // epilogue: tanh + bias; write hn and bf16 split for logits
    #pragma unroll
    for (int mf = 0; mf < 2; ++mf) {
        #pragma unroll
        for (int nf = 0; nf < 4; ++nf) {
            const int n = n0 + wn + nf * 8 + (lane & 3) * 2;
            const float bsum0 = b_ih[n] + b_hh[n];
            const float bsum1 = b_ih[n + 1] + b_hh[n + 1];
            #pragma unroll
            for (int rr = 0; rr < 2; ++rr) {
                const int m = m0 + wm + mf * 16 + (lane >> 2) + rr * 8;
                const float o0 = tanhf(c[mf][nf][rr * 2 + 0] + bsum0);
                const float o1 = tanhf(c[mf][nf][rr * 2 + 1] + bsum1);
                *(float2*)(hn + (size_t)m * HDIM + n) = make_float2(o0, o1);
                BF4 H, L;
                H.h[0] = __float2bfloat16(o0); L.h[0] = __float2bfloat16(o0 - __bfloat162float(H.h[0]));
                H.h[1] = __float2bfloat16(o1); L.h[1] = __float2bfloat16(o1 - __bfloat162float(H.h[1]));
                *(uint32_t*)(g_Ahi + (size_t)m * HDIM + n) = H.u.x;
                *(uint32_t*)(g_Alo + (size_t)m * HDIM + n) = L.u.x;
            }
        }
    }
}

// ---------------------------------------------------------------------------
// Kernel 3: logits mma (unchanged from R5)
// ---------------------------------------------------------------------------
#define LA_STG 8192
#define LB_OFF 24576
#define LB_STG 4096
#define L_SMEM 32768

__global__ __launch_bounds__(128, 4)
void logits_mma(const __nv_bfloat16* __restrict__ Ahi,
                const __nv_bfloat16* __restrict__ Alo,
                const float* __restrict__ Wf,
                const float* __restrict__ bf,
                float* __restrict__ Cout)
{
    const uint32_t smb = s2u(dynsm);
    const int tid = threadIdx.x, lane = tid & 31, warp = tid >> 5;
    const int n0 = blockIdx.x * 64;
    const int m0 = blockIdx.y * 128;
    const int wm = (warp >> 1) * 64;
    const int wn = (warp & 1) * 32;

    int arow[2], acol[2]; uint32_t adst[2];
    #pragma unroll
    for (int i = 0; i < 2; ++i) {
        const int f = i * 128 + tid;
        arow[i] = f >> 1;
        const int ch = f & 1;
        acol[i] = ch * 8;
        adst[i] = (uint32_t)(arow[i] * 32 + ((ch * 16) ^ (((arow[i] >> 2) & 1) << 4)));
    }
    const int brow = tid >> 1, bhalf = tid & 1;
    const uint32_t bdst = (uint32_t)(brow * 32 + ((bhalf * 16) ^ (((brow >> 2) & 1) << 4)));
    const float* bsrc = Wf + (size_t)(n0 + brow) * HDIM + bhalf * 8;

    const int lr = lane & 7, lq = (lane >> 3) & 1, lh = lane >> 4;
    uint32_t aoff[4], boff[4];
    #pragma unroll
    for (int mf = 0; mf < 4; ++mf) {
        const int row = wm + mf * 16 + lr + lq * 8;
        aoff[mf] = (uint32_t)(row * 32 + ((lh * 16) ^ (((row >> 2) & 1) << 4)));
    }
    #pragma unroll
    for (int nf = 0; nf < 4; ++nf) {
        const int row = wn + nf * 8 + lr;
        boff[nf] = (uint32_t)(row * 32 + ((lq * 16) ^ (((row >> 2) & 1) << 4)));
    }

    float c[4][4][4] = {};

    float4 rb0 = *(const float4*)bsrc;
    float4 rb1 = *(const float4*)(bsrc + 4);
    #pragma unroll
    for (int st = 0; st < 2; ++st) {
        char* base = dynsm + st * LA_STG;
        #pragma unroll
        for (int i = 0; i < 2; ++i) {
            cp_async16(base + adst[i],        Ahi + (size_t)(m0 + arow[i]) * HDIM + st * 16 + acol[i]);
            cp_async16(base + 4096 + adst[i], Alo + (size_t)(m0 + arow[i]) * HDIM + st * 16 + acol[i]);
        }
        cp_commit();
    }
    {
        uint4 hi, lo;
        split8(rb0, rb1, hi, lo);
        *(uint4*)(dynsm + LB_OFF + bdst) = hi;
        *(uint4*)(dynsm + LB_OFF + 2048 + bdst) = lo;
    }

    const int NS = HDIM / 16;
    for (int s = 0; s < NS; ++s) {
        const bool more = (s + 1 < NS);
        if (more) {
            rb0 = *(const float4*)(bsrc + (s + 1) * 16);
            rb1 = *(const float4*)(bsrc + (s + 1) * 16 + 4);
        }
        cp_wait<1>();
        __syncthreads();

        if (s + 2 < NS) {
            char* base = dynsm + ((s + 2) % 3) * LA_STG;
            #pragma unroll
            for (int i = 0; i < 2; ++i) {
                cp_async16(base + adst[i],        Ahi + (size_t)(m0 + arow[i]) * HDIM + (s + 2) * 16 + acol[i]);
                cp_async16(base + 4096 + adst[i], Alo + (size_t)(m0 + arow[i]) * HDIM + (s + 2) * 16 + acol[i]);
            }
        }
        cp_commit();

        if (more) {
            uint4 hi, lo;
            split8(rb0, rb1, hi, lo);
            char* bb = dynsm + LB_OFF + ((s + 1) & 1) * LB_STG;
            *(uint4*)(bb + bdst) = hi;
            *(uint4*)(bb + 2048 + bdst) = lo;
        }

        const uint32_t Ah = smb + (s % 3) * LA_STG;
        const uint32_t Al = Ah + 4096;
        const uint32_t Bh = smb + LB_OFF + (s & 1) * LB_STG;
        const uint32_t Bl = Bh + 2048;

        uint32_t bh[4][2], bl[4][2];
        #pragma unroll
        for (int nf = 0; nf < 4; ++nf) {
            ldsm2(bh[nf], Bh + boff[nf]);
            ldsm2(bl[nf], Bl + boff[nf]);
        }
        #pragma unroll
        for (int mf = 0; mf < 4; ++mf) {
            uint32_t ah[4], al[4];
            ldsm4(ah, Ah + aoff[mf]);
            ldsm4(al, Al + aoff[mf]);
            #pragma unroll
            for (int nf = 0; nf < 4; ++nf) {
                mma16816(c[mf][nf], ah, bh[nf]);
                mma16816(c[mf][nf], ah, bl[nf]);
                mma16816(c[mf][nf], al, bh[nf]);
            }
        }
    }

    #pragma unroll
    for (int mf = 0; mf < 4; ++mf) {
        const int m = m0 + wm + mf * 16 + (lane >> 2);
        #pragma unroll
        for (int nf = 0; nf < 4; ++nf) {
            const int n = n0 + wn + nf * 8 + (lane & 3) * 2;
            const float b0 = bf[n], b1 = bf[n + 1];
            float2 o0 = make_float2(c[mf][nf][0] + b0, c[mf][nf][1] + b1);
            float2 o1 = make_float2(c[mf][nf][2] + b0, c[mf][nf][3] + b1);
            *(float2*)(Cout + (size_t)m * VOC + n) = o0;
            *(float2*)(Cout + (size_t)(m + 8) * VOC + n) = o1;
        }
    }
}

// ---------------------------------------------------------------------------
// Launch
// ---------------------------------------------------------------------------
extern "C" void kernel_launch(void* const* d_in, const int* in_sizes, int n_in,
                              void* d_out, int out_size)
{
    const int*   idx   = (const int*)d_in[0];
    const float* hid   = (const float*)d_in[1];
    const float* enc   = (const float*)d_in[2];
    const float* emb   = (const float*)d_in[3];
    const float* W_ih  = (const float*)d_in[4];
    const float* b_ih  = (const float*)d_in[5];
    const float* W_hh  = (const float*)d_in[6];
    const float* b_hh  = (const float*)d_in[7];
    const float* fc_W  = (const float*)d_in[8];
    const float* fc_b  = (const float*)d_in[9];

    float* out    = (float*)d_out;
    float* logits = out;
    float* hn     = out + (size_t)BSZ * VOC;
    float* attn   = out + (size_t)BSZ * VOC + (size_t)BSZ * HDIM;

    __nv_bfloat16 *Ahi, *Alo;
    cudaGetSymbolAddress((void**)&Ahi, g_Ahi);
    cudaGetSymbolAddress((void**)&Alo, g_Alo);

    const int attn_smem = (3 * TS * HDIM + 8 * TS) * 4;

    cudaFuncSetAttribute(attention_half, cudaFuncAttributeMaxDynamicSharedMemorySize, attn_smem);
    cudaFuncSetAttribute(rnn_mma,        cudaFuncAttributeMaxDynamicSharedMemorySize, R_SMEM);
    cudaFuncSetAttribute(logits_mma,     cudaFuncAttributeMaxDynamicSharedMemorySize, L_SMEM);

    pack_weights<<<(HDIM * KXP + 255) / 256, 256>>>(W_ih, W_hh);
    attention_half<<<BSZ * 2, 256, attn_smem>>>(hid, enc);
    attention_merge<<<BSZ, 256>>>(idx, hid, emb, attn);
    rnn_mma<<<dim3(HDIM / 64, BSZ / 64), 128, R_SMEM>>>(b_ih, b_hh, hn);
    logits_mma<<<dim3(VOC / 64, BSZ / 128), 128, L_SMEM>>>(Ahi, Alo, fc_W, fc_b, logits);
}

// round 7
// speedup vs baseline: 3.8439x; 1.0575x over previous
#include <cuda_runtime.h>
#include <cuda_bf16.h>
#include <math.h>
#include <stdint.h>

#define BSZ 256
#define SLEN 512
#define HDIM 1024
#define EDIM 300
#define VOC 32000
#define KX  (EDIM + HDIM + HDIM)   // 2348
#define KXP 2352                   // 147*16 = 3*784

__device__ __nv_bfloat16 g_Xhi[BSZ * KXP];
__device__ __nv_bfloat16 g_Xlo[BSZ * KXP];
__device__ __nv_bfloat16 g_Whi[HDIM * KXP];
__device__ __nv_bfloat16 g_Wlo[HDIM * KXP];
__device__ __nv_bfloat16 g_Ahi[BSZ * HDIM];
__device__ __nv_bfloat16 g_Alo[BSZ * HDIM];
__device__ float g_part[3][BSZ][HDIM];
__device__ float g_ctx[2][BSZ][HDIM];
__device__ float g_en[BSZ][SLEN];
__device__ float2 g_md[2][BSZ];

extern __shared__ char dynsm[];

// ---------------------------------------------------------------------------
// helpers
// ---------------------------------------------------------------------------
__device__ __forceinline__ uint32_t s2u(const void* p) {
    return (uint32_t)__cvta_generic_to_shared(p);
}
__device__ __forceinline__ void cp_async16(void* smem_dst, const void* gmem_src) {
    uint32_t s = s2u(smem_dst);
    asm volatile("cp.async.cg.shared.global [%0], [%1], 16;\n" :: "r"(s), "l"(gmem_src));
}
__device__ __forceinline__ void cp_commit() { asm volatile("cp.async.commit_group;\n"); }
template<int N> __device__ __forceinline__ void cp_wait() {
    asm volatile("cp.async.wait_group %0;\n" :: "n"(N) : "memory");
}
__device__ __forceinline__ void ldsm4(uint32_t* r, uint32_t a) {
    asm volatile("ldmatrix.sync.aligned.m8n8.x4.shared.b16 {%0,%1,%2,%3}, [%4];"
                 : "=r"(r[0]), "=r"(r[1]), "=r"(r[2]), "=r"(r[3]) : "r"(a));
}
__device__ __forceinline__ void ldsm2(uint32_t* r, uint32_t a) {
    asm volatile("ldmatrix.sync.aligned.m8n8.x2.shared.b16 {%0,%1}, [%2];"
                 : "=r"(r[0]), "=r"(r[1]) : "r"(a));
}
__device__ __forceinline__ void mma16816(float* c, const uint32_t* a, const uint32_t* b) {
    asm volatile(
        "mma.sync.aligned.m16n8k16.row.col.f32.bf16.bf16.f32 "
        "{%0,%1,%2,%3}, {%4,%5,%6,%7}, {%8,%9}, {%0,%1,%2,%3};"
        : "+f"(c[0]), "+f"(c[1]), "+f"(c[2]), "+f"(c[3])
        : "r"(a[0]), "r"(a[1]), "r"(a[2]), "r"(a[3]), "r"(b[0]), "r"(b[1]));
}
union BF4 { __nv_bfloat16 h[4]; uint2 u; };
__device__ __forceinline__ void split8(const float4 a, const float4 b, uint4& hi, uint4& lo) {
    BF4 H0, L0, H1, L1;
    H0.h[0] = __float2bfloat16(a.x); L0.h[0] = __float2bfloat16(a.x - __bfloat162float(H0.h[0]));
    H0.h[1] = __float2bfloat16(a.y); L0.h[1] = __float2bfloat16(a.y - __bfloat162float(H0.h[1]));
    H0.h[2] = __float2bfloat16(a.z); L0.h[2] = __float2bfloat16(a.z - __bfloat162float(H0.h[2]));
    H0.h[3] = __float2bfloat16(a.w); L0.h[3] = __float2bfloat16(a.w - __bfloat162float(H0.h[3]));
    H1.h[0] = __float2bfloat16(b.x); L1.h[0] = __float2bfloat16(b.x - __bfloat162float(H1.h[0]));
    H1.h[1] = __float2bfloat16(b.y); L1.h[1] = __float2bfloat16(b.y - __bfloat162float(H1.h[1]));
    H1.h[2] = __float2bfloat16(b.z); L1.h[2] = __float2bfloat16(b.z - __bfloat162float(H1.h[2]));
    H1.h[3] = __float2bfloat16(b.w); L1.h[3] = __float2bfloat16(b.w - __bfloat162float(H1.h[3]));
    hi = make_uint4(H0.u.x, H0.u.y, H1.u.x, H1.u.y);
    lo = make_uint4(L0.u.x, L0.u.y, L1.u.x, L1.u.y);
}
__device__ __forceinline__ void split4v(const float4 v, uint2& hi, uint2& lo) {
    BF4 H, L;
    H.h[0] = __float2bfloat16(v.x); L.h[0] = __float2bfloat16(v.x - __bfloat162float(H.h[0]));
    H.h[1] = __float2bfloat16(v.y); L.h[1] = __float2bfloat16(v.y - __bfloat162float(H.h[1]));
    H.h[2] = __float2bfloat16(v.z); L.h[2] = __float2bfloat16(v.z - __bfloat162float(H.h[2]));
    H.h[3] = __float2bfloat16(v.w); L.h[3] = __float2bfloat16(v.w - __bfloat162float(H.h[3]));
    hi = H.u; lo = L.u;
}

// ---------------------------------------------------------------------------
// Kernel 1: attention halves (unchanged)
// ---------------------------------------------------------------------------
#define TS 8
#define HSTAGES 32
__global__ __launch_bounds__(256)
void attention_half(const float* __restrict__ hid,
                    const float* __restrict__ enc)
{
    float* tile = (float*)dynsm;
    float* red  = tile + 3 * TS * HDIM;

    const int b = blockIdx.x >> 1;
    const int half = blockIdx.x & 1;
    const int t = threadIdx.x;
    const int warp = t >> 5;

    const float4* enc4 = (const float4*)(enc + (size_t)b * SLEN * HDIM + (size_t)half * 256 * HDIM);
    const float4  h4   = ((const float4*)(hid + (size_t)b * HDIM))[t];

    #pragma unroll
    for (int st = 0; st < 2; ++st) {
        #pragma unroll
        for (int i = 0; i < TS; ++i)
            cp_async16(&tile[st * TS * HDIM + i * HDIM + t * 4], &enc4[(st * TS + i) * 256 + t]);
        cp_commit();
    }

    float4 ctx = make_float4(0.f, 0.f, 0.f, 0.f);
    float m = -1e30f, d = 0.f;

    for (int c = 0; c < HSTAGES; ++c) {
        if (c + 2 < HSTAGES) {
            float* nxt = tile + ((c + 2) % 3) * TS * HDIM;
            const int s0n = (c + 2) * TS;
            #pragma unroll
            for (int i = 0; i < TS; ++i)
                cp_async16(&nxt[i * HDIM + t * 4], &enc4[(size_t)(s0n + i) * 256 + t]);
        }
        cp_commit();
        cp_wait<2>();
        __syncthreads();

        float* cur = tile + (c % 3) * TS * HDIM;
        float part[TS];
        #pragma unroll
        for (int s = 0; s < TS; ++s) {
            const float4 e4 = ((const float4*)&cur[s * HDIM])[t];
            part[s] = e4.x * h4.x + e4.y * h4.y + e4.z * h4.z + e4.w * h4.w;
        }
        #pragma unroll
        for (int s = 0; s < TS; ++s)
            #pragma unroll
            for (int o = 16; o > 0; o >>= 1)
                part[s] += __shfl_down_sync(0xffffffffu, part[s], o);
        if ((t & 31) == 0) {
            #pragma unroll
            for (int s = 0; s < TS; ++s) red[warp * TS + s] = part[s];
        }
        __syncthreads();

        float en[TS];
        #pragma unroll
        for (int s = 0; s < TS; ++s) {
            float e = 0.f;
            #pragma unroll
            for (int w = 0; w < 8; ++w) e += red[w * TS + s];
            en[s] = e;
        }
        float tmax = en[0];
        #pragma unroll
        for (int s = 1; s < TS; ++s) tmax = fmaxf(tmax, en[s]);
        const float nm = fmaxf(m, tmax);
        const float f = __expf(m - nm);
        float p[TS], psum = 0.f;
        #pragma unroll
        for (int s = 0; s < TS; ++s) { p[s] = __expf(en[s] - nm); psum += p[s]; }
        d = d * f + psum;
        m = nm;

        ctx.x *= f; ctx.y *= f; ctx.z *= f; ctx.w *= f;
        #pragma unroll
        for (int s = 0; s < TS; ++s) {
            const float4 e4 = ((const float4*)&cur[s * HDIM])[t];
            ctx.x += p[s] * e4.x;
            ctx.y += p[s] * e4.y;
            ctx.z += p[s] * e4.z;
            ctx.w += p[s] * e4.w;
        }
        if (t < TS) g_en[b][half * 256 + c * TS + t] = en[t];
    }

    ((float4*)&g_ctx[half][b][0])[t] = ctx;
    if (t == 0) g_md[half][b] = make_float2(m, d);
}

// ---------------------------------------------------------------------------
// Kernel 1c: merge halves (unchanged)
// ---------------------------------------------------------------------------
__global__ __launch_bounds__(256)
void attention_merge(const int* __restrict__ idx,
                     const float* __restrict__ hid,
                     const float* __restrict__ emb_table,
                     float* __restrict__ attn_out)
{
    const int b = blockIdx.x;
    const int t = threadIdx.x;

    const float2 md0 = g_md[0][b];
    const float2 md1 = g_md[1][b];
    const float m = fmaxf(md0.x, md1.x);
    const float f0 = __expf(md0.x - m), f1 = __expf(md1.x - m);
    const float dd = md0.y * f0 + md1.y * f1;
    const float inv = 1.f / dd;

    __nv_bfloat16* Xh = g_Xhi + (size_t)b * KXP;
    __nv_bfloat16* Xl = g_Xlo + (size_t)b * KXP;

    const float4 c0 = ((const float4*)&g_ctx[0][b][0])[t];
    const float4 c1 = ((const float4*)&g_ctx[1][b][0])[t];
    float4 cc;
    cc.x = (c0.x * f0 + c1.x * f1) * inv;
    cc.y = (c0.y * f0 + c1.y * f1) * inv;
    cc.z = (c0.z * f0 + c1.z * f1) * inv;
    cc.w = (c0.w * f0 + c1.w * f1) * inv;
    uint2 hi, lo;
    split4v(cc, hi, lo);
    *(uint2*)(Xh + EDIM + t * 4) = hi;
    *(uint2*)(Xl + EDIM + t * 4) = lo;

    const float4 h4 = ((const float4*)(hid + (size_t)b * HDIM))[t];
    split4v(h4, hi, lo);
    *(uint2*)(Xh + EDIM + HDIM + t * 4) = hi;
    *(uint2*)(Xl + EDIM + HDIM + t * 4) = lo;

    const int ci = idx[b];
    for (int j = t; j < EDIM; j += 256) {
        const float v = emb_table[(size_t)ci * EDIM + j];
        const __nv_bfloat16 H = __float2bfloat16(v);
        Xh[j] = H;
        Xl[j] = __float2bfloat16(v - __bfloat162float(H));
    }
    if (t < 4) { Xh[KX + t] = __float2bfloat16(0.f); Xl[KX + t] = __float2bfloat16(0.f); }

    for (int s = t; s < SLEN; s += 256)
        attn_out[(size_t)b * SLEN + s] = __expf(g_en[b][s] - m) * inv;
}

// ---------------------------------------------------------------------------
// Kernel 1b: pack weights -> bf16 hi/lo, one block per output row
// ---------------------------------------------------------------------------
__global__ __launch_bounds__(256)
void pack_weights(const float* __restrict__ W_ih,
                  const float* __restrict__ W_hh)
{
    const int n = blockIdx.x;
    const float* src_ih = W_ih + (size_t)n * (EDIM + HDIM);
    const float* src_hh = W_hh + (size_t)n * HDIM;
    __nv_bfloat16* dh = g_Whi + (size_t)n * KXP;
    __nv_bfloat16* dl = g_Wlo + (size_t)n * KXP;
    for (int k = threadIdx.x; k < KXP; k += 256) {
        float v = 0.f;
        if (k < EDIM + HDIM)      v = src_ih[k];
        else if (k < KX)          v = src_hh[k - (EDIM + HDIM)];
        const __nv_bfloat16 H = __float2bfloat16(v);
        dh[k] = H;
        dl[k] = __float2bfloat16(v - __bfloat162float(H));
    }
}

// ---------------------------------------------------------------------------
// Kernel 2: RNN split-K mma. grid (16, 4, 3). 49 iters per CTA.
// ---------------------------------------------------------------------------
#define R_STG 4096
#define R_BOFF 12288
#define R_SMEM 24576
#define KCH 784   // KXP/3

__global__ __launch_bounds__(128, 4)
void rnn_mma(float* __restrict__ dummy)
{
    const uint32_t smb = s2u(dynsm);
    const int tid = threadIdx.x, lane = tid & 31, warp = tid >> 5;
    const int m0 = blockIdx.y * 64;
    const int n0 = blockIdx.x * 64;
    const int kc = blockIdx.z;
    const int kbase = kc * KCH;
    const int wm = (warp >> 1) * 32;
    const int wn = (warp & 1) * 32;

    const int crow = tid >> 1, chalf = tid & 1;
    const uint32_t cdst = (uint32_t)(crow * 32 + ((chalf * 16) ^ (((crow >> 2) & 1) << 4)));
    const __nv_bfloat16* Asrc_h = g_Xhi + (size_t)(m0 + crow) * KXP + kbase + chalf * 8;
    const __nv_bfloat16* Asrc_l = g_Xlo + (size_t)(m0 + crow) * KXP + kbase + chalf * 8;
    const __nv_bfloat16* Bsrc_h = g_Whi + (size_t)(n0 + crow) * KXP + kbase + chalf * 8;
    const __nv_bfloat16* Bsrc_l = g_Wlo + (size_t)(n0 + crow) * KXP + kbase + chalf * 8;

    const int lr = lane & 7, lq = (lane >> 3) & 1, lh = lane >> 4;
    uint32_t aoff[2], boff[4];
    #pragma unroll
    for (int mf = 0; mf < 2; ++mf) {
        const int row = wm + mf * 16 + lr + lq * 8;
        aoff[mf] = (uint32_t)(row * 32 + ((lh * 16) ^ (((row >> 2) & 1) << 4)));
    }
    #pragma unroll
    for (int nf = 0; nf < 4; ++nf) {
        const int row = wn + nf * 8 + lr;
        boff[nf] = (uint32_t)(row * 32 + ((lq * 16) ^ (((row >> 2) & 1) << 4)));
    }

    float c[2][4][4] = {};
    const int NS = KCH / 16;   // 49

    #pragma unroll
    for (int st = 0; st < 2; ++st) {
        char* ab = dynsm + st * R_STG;
        char* bb = dynsm + R_BOFF + st * R_STG;
        cp_async16(ab + cdst,        Asrc_h + st * 16);
        cp_async16(ab + 2048 + cdst, Asrc_l + st * 16);
        cp_async16(bb + cdst,        Bsrc_h + st * 16);
        cp_async16(bb + 2048 + cdst, Bsrc_l + st * 16);
        cp_commit();
    }

    for (int s = 0; s < NS; ++s) {
        if (s + 2 < NS) {
            char* ab = dynsm + ((s + 2) % 3) * R_STG;
            char* bb = dynsm + R_BOFF + ((s + 2) % 3) * R_STG;
            cp_async16(ab + cdst,        Asrc_h + (s + 2) * 16);
            cp_async16(ab + 2048 + cdst, Asrc_l + (s + 2) * 16);
            cp_async16(bb + cdst,        Bsrc_h + (s + 2) * 16);
            cp_async16(bb + 2048 + cdst, Bsrc_l + (s + 2) * 16);
        }
        cp_commit();
        cp_wait<2>();
        __syncthreads();

        const uint32_t Ah = smb + (s % 3) * R_STG;
        const uint32_t Al = Ah + 2048;
        const uint32_t Bh = smb + R_BOFF + (s % 3) * R_STG;
        const uint32_t Bl = Bh + 2048;

        uint32_t bh[4][2], bl[4][2];
        #pragma unroll
        for (int nf = 0; nf < 4; ++nf) {
            ldsm2(bh[nf], Bh + boff[nf]);
            ldsm2(bl[nf], Bl + boff[nf]);
        }
        #pragma unroll
        for (int mf = 0; mf < 2; ++mf) {
            uint32_t ah[4], al[4];
            ldsm4(ah, Ah + aoff[mf]);
            ldsm4(al, Al + aoff[mf]);
            #pragma unroll
            for (int nf = 0; nf < 4; ++nf) {
                mma16816(c[mf][nf], ah, bh[nf]);
                mma16816(c[mf][nf], ah, bl[nf]);
                mma16816(c[mf][nf], al, bh[nf]);
            }
        }
        __syncthreads();
    }

    #pragma unroll
    for (int mf = 0; mf < 2; ++mf) {
        #pragma unroll
        for (int nf = 0; nf < 4; ++nf) {
            const int n = n0 + wn + nf * 8 + (lane & 3) * 2;
            #pragma unroll
            for (int rr = 0; rr < 2; ++rr) {
                const int m = m0 + wm + mf * 16 + (lane >> 2) + rr * 8;
                *(float2*)&g_part[kc][m][n] =
                    make_float2(c[mf][nf][rr * 2 + 0], c[mf][nf][rr * 2 + 1]);
            }
        }
    }
}

// ---------------------------------------------------------------------------
// Kernel 2b: reduce partials, bias+tanh, write hn and bf16 split
// ---------------------------------------------------------------------------
__global__ __launch_bounds__(256)
void rnn_finish(const float* __restrict__ b_ih,
                const float* __restrict__ b_hh,
                float* __restrict__ hn)
{
    const int m = blockIdx.x;
    const int n = threadIdx.x * 4;
    const float4 p0 = *(const float4*)&g_part[0][m][n];
    const float4 p1 = *(const float4*)&g_part[1][m][n];
    const float4 p2 = *(const float4*)&g_part[2][m][n];
    const float4 bi = *(const float4*)(b_ih + n);
    const float4 bh = *(const float4*)(b_hh + n);
    float4 o;
    o.x = tanhf(p0.x + p1.x + p2.x + bi.x + bh.x);
    o.y = tanhf(p0.y + p1.y + p2.y + bi.y + bh.y);
    o.z = tanhf(p0.z + p1.z + p2.z + bi.z + bh.z);
    o.w = tanhf(p0.w + p1.w + p2.w + bi.w + bh.w);
    *(float4*)(hn + (size_t)m * HDIM + n) = o;
    uint2 hi, lo;
    split4v(o, hi, lo);
    *(uint2*)(g_Ahi + (size_t)m * HDIM + n) = hi;
    *(uint2*)(g_Alo + (size_t)m * HDIM + n) = lo;
}

// ---------------------------------------------------------------------------
// Kernel 3: logits mma, CTA 256x64 (M = whole batch), 256 threads, 2 CTA/SM.
// smem: A ring-3 x 16384 (hi 8192 | lo 8192), B dbuf at 49152: 2 x 4096.
// ---------------------------------------------------------------------------
#define LA_STG 16384
#define LB_OFF 49152
#define LB_STG 4096
#define L_SMEM 57344

__global__ __launch_bounds__(256, 2)
void logits_mma(const __nv_bfloat16* __restrict__ Ahi,
                const __nv_bfloat16* __restrict__ Alo,
                const float* __restrict__ Wf,
                const float* __restrict__ bf,
                float* __restrict__ Cout)
{
    const uint32_t smb = s2u(dynsm);
    const int tid = threadIdx.x, lane = tid & 31, warp = tid >> 5;
    const int n0 = blockIdx.x * 64;
    const int wm = (warp >> 1) * 64;
    const int wn = (warp & 1) * 32;

    // A copy: 512 chunks of 16B per (hi|lo), 2 per thread
    int arow[2], acol[2]; uint32_t adst[2];
    #pragma unroll
    for (int i = 0; i < 2; ++i) {
        const int f = i * 256 + tid;
        arow[i] = f >> 1;
        const int ch = f & 1;
        acol[i] = ch * 8;
        adst[i] = (uint32_t)(arow[i] * 32 + ((ch * 16) ^ (((arow[i] >> 2) & 1) << 4)));
    }
    // B copy: threads 0..127
    const int brow = tid >> 1, bhalf = tid & 1;
    const uint32_t bdst = (uint32_t)(brow * 32 + ((bhalf * 16) ^ (((brow >> 2) & 1) << 4)));
    const float* bsrc = Wf + (size_t)(n0 + brow) * HDIM + bhalf * 8;
    const bool bldr = (tid < 128);

    const int lr = lane & 7, lq = (lane >> 3) & 1, lh = lane >> 4;
    uint32_t aoff[4], boff[4];
    #pragma unroll
    for (int mf = 0; mf < 4; ++mf) {
        const int row = wm + mf * 16 + lr + lq * 8;
        aoff[mf] = (uint32_t)(row * 32 + ((lh * 16) ^ (((row >> 2) & 1) << 4)));
    }
    #pragma unroll
    for (int nf = 0; nf < 4; ++nf) {
        const int row = wn + nf * 8 + lr;
        boff[nf] = (uint32_t)(row * 32 + ((lq * 16) ^ (((row >> 2) & 1) << 4)));
    }

    float c[4][4][4] = {};

    float4 rb0, rb1;
    if (bldr) {
        rb0 = *(const float4*)bsrc;
        rb1 = *(const float4*)(bsrc + 4);
    }
    #pragma unroll
    for (int st = 0; st < 2; ++st) {
        char* base = dynsm + st * LA_STG;
        #pragma unroll
        for (int i = 0; i < 2; ++i) {
            cp_async16(base + adst[i],        Ahi + (size_t)arow[i] * HDIM + st * 16 + acol[i]);
            cp_async16(base + 8192 + adst[i], Alo + (size_t)arow[i] * HDIM + st * 16 + acol[i]);
        }
        cp_commit();
    }
    if (bldr) {
        uint4 hi, lo;
        split8(rb0, rb1, hi, lo);
        *(uint4*)(dynsm + LB_OFF + bdst) = hi;
        *(uint4*)(dynsm + LB_OFF + 2048 + bdst) = lo;
    }

    const int NS = HDIM / 16;   // 64
    for (int s = 0; s < NS; ++s) {
        const bool more = (s + 1 < NS);
        if (more && bldr) {
            rb0 = *(const float4*)(bsrc + (s + 1) * 16);
            rb1 = *(const float4*)(bsrc + (s + 1) * 16 + 4);
        }
        cp_wait<1>();
        __syncthreads();

        if (s + 2 < NS) {
            char* base = dynsm + ((s + 2) % 3) * LA_STG;
            #pragma unroll
            for (int i = 0; i < 2; ++i) {
                cp_async16(base + adst[i],        Ahi + (size_t)arow[i] * HDIM + (s + 2) * 16 + acol[i]);
                cp_async16(base + 8192 + adst[i], Alo + (size_t)arow[i] * HDIM + (s + 2) * 16 + acol[i]);
            }
        }
        cp_commit();

        if (more && bldr) {
            uint4 hi, lo;
            split8(rb0, rb1, hi, lo);
            char* bb = dynsm + LB_OFF + ((s + 1) & 1) * LB_STG;
            *(uint4*)(bb + bdst) = hi;
            *(uint4*)(bb + 2048 + bdst) = lo;
        }

        const uint32_t Ah = smb + (s % 3) * LA_STG;
        const uint32_t Al = Ah + 8192;
        const uint32_t Bh = smb + LB_OFF + (s & 1) * LB_STG;
        const uint32_t Bl = Bh + 2048;

        uint32_t bh[4][2], bl[4][2];
        #pragma unroll
        for (int nf = 0; nf < 4; ++nf) {
            ldsm2(bh[nf], Bh + boff[nf]);
            ldsm2(bl[nf], Bl + boff[nf]);
        }
        #pragma unroll
        for (int mf = 0; mf < 4; ++mf) {
            uint32_t ah[4], al[4];
            ldsm4(ah, Ah + aoff[mf]);
            ldsm4(al, Al + aoff[mf]);
            #pragma unroll
            for (int nf = 0; nf < 4; ++nf) {
                mma16816(c[mf][nf], ah, bh[nf]);
                mma16816(c[mf][nf], ah, bl[nf]);
                mma16816(c[mf][nf], al, bh[nf]);
            }
        }
    }

    #pragma unroll
    for (int mf = 0; mf < 4; ++mf) {
        const int m = wm + mf * 16 + (lane >> 2);
        #pragma unroll
        for (int nf = 0; nf < 4; ++nf) {
            const int n = n0 + wn + nf * 8 + (lane & 3) * 2;
            const float b0 = bf[n], b1 = bf[n + 1];
            float2 o0 = make_float2(c[mf][nf][0] + b0, c[mf][nf][1] + b1);
            float2 o1 = make_float2(c[mf][nf][2] + b0, c[mf][nf][3] + b1);
            *(float2*)(Cout + (size_t)m * VOC + n) = o0;
            *(float2*)(Cout + (size_t)(m + 8) * VOC + n) = o1;
        }
    }
}

// ---------------------------------------------------------------------------
// Launch
// ---------------------------------------------------------------------------
extern "C" void kernel_launch(void* const* d_in, const int* in_sizes, int n_in,
                              void* d_out, int out_size)
{
    const int*   idx   = (const int*)d_in[0];
    const float* hid   = (const float*)d_in[1];
    const float* enc   = (const float*)d_in[2];
    const float* emb   = (const float*)d_in[3];
    const float* W_ih  = (const float*)d_in[4];
    const float* b_ih  = (const float*)d_in[5];
    const float* W_hh  = (const float*)d_in[6];
    const float* b_hh  = (const float*)d_in[7];
    const float* fc_W  = (const float*)d_in[8];
    const float* fc_b  = (const float*)d_in[9];

    float* out    = (float*)d_out;
    float* logits = out;
    float* hn     = out + (size_t)BSZ * VOC;
    float* attn   = out + (size_t)BSZ * VOC + (size_t)BSZ * HDIM;

    __nv_bfloat16 *Ahi, *Alo;
    cudaGetSymbolAddress((void**)&Ahi, g_Ahi);
    cudaGetSymbolAddress((void**)&Alo, g_Alo);

    const int attn_smem = (3 * TS * HDIM + 8 * TS) * 4;

    cudaFuncSetAttribute(attention_half, cudaFuncAttributeMaxDynamicSharedMemorySize, attn_smem);
    cudaFuncSetAttribute(rnn_mma,        cudaFuncAttributeMaxDynamicSharedMemorySize, R_SMEM);
    cudaFuncSetAttribute(logits_mma,     cudaFuncAttributeMaxDynamicSharedMemorySize, L_SMEM);

    pack_weights<<<HDIM, 256>>>(W_ih, W_hh);
    attention_half<<<BSZ * 2, 256, attn_smem>>>(hid, enc);
    attention_merge<<<BSZ, 256>>>(idx, hid, emb, attn);
    rnn_mma<<<dim3(HDIM / 64, BSZ / 64, 3), 128, R_SMEM>>>(nullptr);
    rnn_finish<<<BSZ, 256>>>(b_ih, b_hh, hn);
    logits_mma<<<VOC / 64, 256, L_SMEM>>>(Ahi, Alo, fc_W, fc_b, logits);
}

// round 8
// speedup vs baseline: 4.5524x; 1.1843x over previous
#include <cuda_runtime.h>
#include <cuda_bf16.h>
#include <cuda_fp16.h>
#include <math.h>
#include <stdint.h>

#define BSZ 256
#define SLEN 512
#define HDIM 1024
#define EDIM 300
#define VOC 32000
#define KX  (EDIM + HDIM + HDIM)   // 2348
#define KXP 2352                   // 147*16 = 3*784

__device__ __nv_bfloat16 g_Xhi[BSZ * KXP];
__device__ __nv_bfloat16 g_Xlo[BSZ * KXP];
__device__ __nv_bfloat16 g_Whi[HDIM * KXP];
__device__ __nv_bfloat16 g_Wlo[HDIM * KXP];
__device__ __half g_Ahi[BSZ * HDIM];
__device__ __half g_Alo[BSZ * HDIM];
__device__ float g_part[3][BSZ][HDIM];
__device__ float g_ctx[2][BSZ][HDIM];
__device__ float g_en[BSZ][SLEN];
__device__ float2 g_md[2][BSZ];

extern __shared__ char dynsm[];

// ---------------------------------------------------------------------------
// helpers
// ---------------------------------------------------------------------------
__device__ __forceinline__ uint32_t s2u(const void* p) {
    return (uint32_t)__cvta_generic_to_shared(p);
}
__device__ __forceinline__ void cp_async16(void* smem_dst, const void* gmem_src) {
    uint32_t s = s2u(smem_dst);
    asm volatile("cp.async.cg.shared.global [%0], [%1], 16;\n" :: "r"(s), "l"(gmem_src));
}
__device__ __forceinline__ void cp_commit() { asm volatile("cp.async.commit_group;\n"); }
template<int N> __device__ __forceinline__ void cp_wait() {
    asm volatile("cp.async.wait_group %0;\n" :: "n"(N) : "memory");
}
__device__ __forceinline__ void ldsm4(uint32_t* r, uint32_t a) {
    asm volatile("ldmatrix.sync.aligned.m8n8.x4.shared.b16 {%0,%1,%2,%3}, [%4];"
                 : "=r"(r[0]), "=r"(r[1]), "=r"(r[2]), "=r"(r[3]) : "r"(a));
}
__device__ __forceinline__ void ldsm2(uint32_t* r, uint32_t a) {
    asm volatile("ldmatrix.sync.aligned.m8n8.x2.shared.b16 {%0,%1}, [%2];"
                 : "=r"(r[0]), "=r"(r[1]) : "r"(a));
}
__device__ __forceinline__ void mma_bf16(float* c, const uint32_t* a, const uint32_t* b) {
    asm volatile(
        "mma.sync.aligned.m16n8k16.row.col.f32.bf16.bf16.f32 "
        "{%0,%1,%2,%3}, {%4,%5,%6,%7}, {%8,%9}, {%0,%1,%2,%3};"
        : "+f"(c[0]), "+f"(c[1]), "+f"(c[2]), "+f"(c[3])
        : "r"(a[0]), "r"(a[1]), "r"(a[2]), "r"(a[3]), "r"(b[0]), "r"(b[1]));
}
__device__ __forceinline__ void mma_f16(float* c, const uint32_t* a, const uint32_t* b) {
    asm volatile(
        "mma.sync.aligned.m16n8k16.row.col.f32.f16.f16.f32 "
        "{%0,%1,%2,%3}, {%4,%5,%6,%7}, {%8,%9}, {%0,%1,%2,%3};"
        : "+f"(c[0]), "+f"(c[1]), "+f"(c[2]), "+f"(c[3])
        : "r"(a[0]), "r"(a[1]), "r"(a[2]), "r"(a[3]), "r"(b[0]), "r"(b[1]));
}
union BF4 { __nv_bfloat16 h[4]; uint2 u; };
union HF4 { __half h[4]; uint2 u; };
__device__ __forceinline__ void split4v(const float4 v, uint2& hi, uint2& lo) {
    BF4 H, L;
    H.h[0] = __float2bfloat16(v.x); L.h[0] = __float2bfloat16(v.x - __bfloat162float(H.h[0]));
    H.h[1] = __float2bfloat16(v.y); L.h[1] = __float2bfloat16(v.y - __bfloat162float(H.h[1]));
    H.h[2] = __float2bfloat16(v.z); L.h[2] = __float2bfloat16(v.z - __bfloat162float(H.h[2]));
    H.h[3] = __float2bfloat16(v.w); L.h[3] = __float2bfloat16(v.w - __bfloat162float(H.h[3]));
    hi = H.u; lo = L.u;
}
__device__ __forceinline__ void split4h(const float4 v, uint2& hi, uint2& lo) {
    HF4 H, L;
    H.h[0] = __float2half_rn(v.x); L.h[0] = __float2half_rn(v.x - __half2float(H.h[0]));
    H.h[1] = __float2half_rn(v.y); L.h[1] = __float2half_rn(v.y - __half2float(H.h[1]));
    H.h[2] = __float2half_rn(v.z); L.h[2] = __float2half_rn(v.z - __half2float(H.h[2]));
    H.h[3] = __float2half_rn(v.w); L.h[3] = __float2half_rn(v.w - __half2float(H.h[3]));
    hi = H.u; lo = L.u;
}

// ---------------------------------------------------------------------------
// Kernel 1: attention halves (unchanged)
// ---------------------------------------------------------------------------
#define TS 8
#define HSTAGES 32
__global__ __launch_bounds__(256)
void attention_half(const float* __restrict__ hid,
                    const float* __restrict__ enc)
{
    float* tile = (float*)dynsm;
    float* red  = tile + 3 * TS * HDIM;

    const int b = blockIdx.x >> 1;
    const int half = blockIdx.x & 1;
    const int t = threadIdx.x;
    const int warp = t >> 5;

    const float4* enc4 = (const float4*)(enc + (size_t)b * SLEN * HDIM + (size_t)half * 256 * HDIM);
    const float4  h4   = ((const float4*)(hid + (size_t)b * HDIM))[t];

    #pragma unroll
    for (int st = 0; st < 2; ++st) {
        #pragma unroll
        for (int i = 0; i < TS; ++i)
            cp_async16(&tile[st * TS * HDIM + i * HDIM + t * 4], &enc4[(st * TS + i) * 256 + t]);
        cp_commit();
    }

    float4 ctx = make_float4(0.f, 0.f, 0.f, 0.f);
    float m = -1e30f, d = 0.f;

    for (int c = 0; c < HSTAGES; ++c) {
        if (c + 2 < HSTAGES) {
            float* nxt = tile + ((c + 2) % 3) * TS * HDIM;
            const int s0n = (c + 2) * TS;
            #pragma unroll
            for (int i = 0; i < TS; ++i)
                cp_async16(&nxt[i * HDIM + t * 4], &enc4[(size_t)(s0n + i) * 256 + t]);
        }
        cp_commit();
        cp_wait<2>();
        __syncthreads();

        float* cur = tile + (c % 3) * TS * HDIM;
        float part[TS];
        #pragma unroll
        for (int s = 0; s < TS; ++s) {
            const float4 e4 = ((const float4*)&cur[s * HDIM])[t];
            part[s] = e4.x * h4.x + e4.y * h4.y + e4.z * h4.z + e4.w * h4.w;
        }
        #pragma unroll
        for (int s = 0; s < TS; ++s)
            #pragma unroll
            for (int o = 16; o > 0; o >>= 1)
                part[s] += __shfl_down_sync(0xffffffffu, part[s], o);
        if ((t & 31) == 0) {
            #pragma unroll
            for (int s = 0; s < TS; ++s) red[warp * TS + s] = part[s];
        }
        __syncthreads();

        float en[TS];
        #pragma unroll
        for (int s = 0; s < TS; ++s) {
            float e = 0.f;
            #pragma unroll
            for (int w = 0; w < 8; ++w) e += red[w * TS + s];
            en[s] = e;
        }
        float tmax = en[0];
        #pragma unroll
        for (int s = 1; s < TS; ++s) tmax = fmaxf(tmax, en[s]);
        const float nm = fmaxf(m, tmax);
        const float f = __expf(m - nm);
        float p[TS], psum = 0.f;
        #pragma unroll
        for (int s = 0; s < TS; ++s) { p[s] = __expf(en[s] - nm); psum += p[s]; }
        d = d * f + psum;
        m = nm;

        ctx.x *= f; ctx.y *= f; ctx.z *= f; ctx.w *= f;
        #pragma unroll
        for (int s = 0; s < TS; ++s) {
            const float4 e4 = ((const float4*)&cur[s * HDIM])[t];
            ctx.x += p[s] * e4.x;
            ctx.y += p[s] * e4.y;
            ctx.z += p[s] * e4.z;
            ctx.w += p[s] * e4.w;
        }
        if (t < TS) g_en[b][half * 256 + c * TS + t] = en[t];
    }

    ((float4*)&g_ctx[half][b][0])[t] = ctx;
    if (t == 0) g_md[half][b] = make_float2(m, d);
}

// ---------------------------------------------------------------------------
// Kernel 1c: merge halves (unchanged)
// ---------------------------------------------------------------------------
__global__ __launch_bounds__(256)
void attention_merge(const int* __restrict__ idx,
                     const float* __restrict__ hid,
                     const float* __restrict__ emb_table,
                     float* __restrict__ attn_out)
{
    const int b = blockIdx.x;
    const int t = threadIdx.x;

    const float2 md0 = g_md[0][b];
    const float2 md1 = g_md[1][b];
    const float m = fmaxf(md0.x, md1.x);
    const float f0 = __expf(md0.x - m), f1 = __expf(md1.x - m);
    const float dd = md0.y * f0 + md1.y * f1;
    const float inv = 1.f / dd;

    __nv_bfloat16* Xh = g_Xhi + (size_t)b * KXP;
    __nv_bfloat16* Xl = g_Xlo + (size_t)b * KXP;

    const float4 c0 = ((const float4*)&g_ctx[0][b][0])[t];
    const float4 c1 = ((const float4*)&g_ctx[1][b][0])[t];
    float4 cc;
    cc.x = (c0.x * f0 + c1.x * f1) * inv;
    cc.y = (c0.y * f0 + c1.y * f1) * inv;
    cc.z = (c0.z * f0 + c1.z * f1) * inv;
    cc.w = (c0.w * f0 + c1.w * f1) * inv;
    uint2 hi, lo;
    split4v(cc, hi, lo);
    *(uint2*)(Xh + EDIM + t * 4) = hi;
    *(uint2*)(Xl + EDIM + t * 4) = lo;

    const float4 h4 = ((const float4*)(hid + (size_t)b * HDIM))[t];
    split4v(h4, hi, lo);
    *(uint2*)(Xh + EDIM + HDIM + t * 4) = hi;
    *(uint2*)(Xl + EDIM + HDIM + t * 4) = lo;

    const int ci = idx[b];
    for (int j = t; j < EDIM; j += 256) {
        const float v = emb_table[(size_t)ci * EDIM + j];
        const __nv_bfloat16 H = __float2bfloat16(v);
        Xh[j] = H;
        Xl[j] = __float2bfloat16(v - __bfloat162float(H));
    }
    if (t < 4) { Xh[KX + t] = __float2bfloat16(0.f); Xl[KX + t] = __float2bfloat16(0.f); }

    for (int s = t; s < SLEN; s += 256)
        attn_out[(size_t)b * SLEN + s] = __expf(g_en[b][s] - m) * inv;
}

// ---------------------------------------------------------------------------
// Kernel 1b: pack weights -> bf16 hi/lo, one block per output row
// ---------------------------------------------------------------------------
__global__ __launch_bounds__(256)
void pack_weights(const float* __restrict__ W_ih,
                  const float* __restrict__ W_hh)
{
    const int n = blockIdx.x;
    const float* src_ih = W_ih + (size_t)n * (EDIM + HDIM);
    const float* src_hh = W_hh + (size_t)n * HDIM;
    __nv_bfloat16* dh = g_Whi + (size_t)n * KXP;
    __nv_bfloat16* dl = g_Wlo + (size_t)n * KXP;
    for (int k = threadIdx.x; k < KXP; k += 256) {
        float v = 0.f;
        if (k < EDIM + HDIM)      v = src_ih[k];
        else if (k < KX)          v = src_hh[k - (EDIM + HDIM)];
        const __nv_bfloat16 H = __float2bfloat16(v);
        dh[k] = H;
        dl[k] = __float2bfloat16(v - __bfloat162float(H));
    }
}

// ---------------------------------------------------------------------------
// Kernel 2: RNN split-K mma (unchanged, bf16x3)
// ---------------------------------------------------------------------------
#define R_STG 4096
#define R_BOFF 12288
#define R_SMEM 24576
#define KCH 784   // KXP/3

__global__ __launch_bounds__(128, 4)
void rnn_mma(float* __restrict__ dummy)
{
    const uint32_t smb = s2u(dynsm);
    const int tid = threadIdx.x, lane = tid & 31, warp = tid >> 5;
    const int m0 = blockIdx.y * 64;
    const int n0 = blockIdx.x * 64;
    const int kc = blockIdx.z;
    const int kbase = kc * KCH;
    const int wm = (warp >> 1) * 32;
    const int wn = (warp & 1) * 32;

    const int crow = tid >> 1, chalf = tid & 1;
    const uint32_t cdst = (uint32_t)(crow * 32 + ((chalf * 16) ^ (((crow >> 2) & 1) << 4)));
    const __nv_bfloat16* Asrc_h = g_Xhi + (size_t)(m0 + crow) * KXP + kbase + chalf * 8;
    const __nv_bfloat16* Asrc_l = g_Xlo + (size_t)(m0 + crow) * KXP + kbase + chalf * 8;
    const __nv_bfloat16* Bsrc_h = g_Whi + (size_t)(n0 + crow) * KXP + kbase + chalf * 8;
    const __nv_bfloat16* Bsrc_l = g_Wlo + (size_t)(n0 + crow) * KXP + kbase + chalf * 8;

    const int lr = lane & 7, lq = (lane >> 3) & 1, lh = lane >> 4;
    uint32_t aoff[2], boff[4];
    #pragma unroll
    for (int mf = 0; mf < 2; ++mf) {
        const int row = wm + mf * 16 + lr + lq * 8;
        aoff[mf] = (uint32_t)(row * 32 + ((lh * 16) ^ (((row >> 2) & 1) << 4)));
    }
    #pragma unroll
    for (int nf = 0; nf < 4; ++nf) {
        const int row = wn + nf * 8 + lr;
        boff[nf] = (uint32_t)(row * 32 + ((lq * 16) ^ (((row >> 2) & 1) << 4)));
    }

    float c[2][4][4] = {};
    const int NS = KCH / 16;   // 49

    #pragma unroll
    for (int st = 0; st < 2; ++st) {
        char* ab = dynsm + st * R_STG;
        char* bb = dynsm + R_BOFF + st * R_STG;
        cp_async16(ab + cdst,        Asrc_h + st * 16);
        cp_async16(ab + 2048 + cdst, Asrc_l + st * 16);
        cp_async16(bb + cdst,        Bsrc_h + st * 16);
        cp_async16(bb + 2048 + cdst, Bsrc_l + st * 16);
        cp_commit();
    }

    for (int s = 0; s < NS; ++s) {
        if (s + 2 < NS) {
            char* ab = dynsm + ((s + 2) % 3) * R_STG;
            char* bb = dynsm + R_BOFF + ((s + 2) % 3) * R_STG;
            cp_async16(ab + cdst,        Asrc_h + (s + 2) * 16);
            cp_async16(ab + 2048 + cdst, Asrc_l + (s + 2) * 16);
            cp_async16(bb + cdst,        Bsrc_h + (s + 2) * 16);
            cp_async16(bb + 2048 + cdst, Bsrc_l + (s + 2) * 16);
        }
        cp_commit();
        cp_wait<2>();
        __syncthreads();

        const uint32_t Ah = smb + (s % 3) * R_STG;
        const uint32_t Al = Ah + 2048;
        const uint32_t Bh = smb + R_BOFF + (s % 3) * R_STG;
        const uint32_t Bl = Bh + 2048;

        uint32_t bh[4][2], bl[4][2];
        #pragma unroll
        for (int nf = 0; nf < 4; ++nf) {
            ldsm2(bh[nf], Bh + boff[nf]);
            ldsm2(bl[nf], Bl + boff[nf]);
        }
        #pragma unroll
        for (int mf = 0; mf < 2; ++mf) {
            uint32_t ah[4], al[4];
            ldsm4(ah, Ah + aoff[mf]);
            ldsm4(al, Al + aoff[mf]);
            #pragma unroll
            for (int nf = 0; nf < 4; ++nf) {
                mma_bf16(c[mf][nf], ah, bh[nf]);
                mma_bf16(c[mf][nf], ah, bl[nf]);
                mma_bf16(c[mf][nf], al, bh[nf]);
            }
        }
        __syncthreads();
    }

    #pragma unroll
    for (int mf = 0; mf < 2; ++mf) {
        #pragma unroll
        for (int nf = 0; nf < 4; ++nf) {
            const int n = n0 + wn + nf * 8 + (lane & 3) * 2;
            #pragma unroll
            for (int rr = 0; rr < 2; ++rr) {
                const int m = m0 + wm + mf * 16 + (lane >> 2) + rr * 8;
                *(float2*)&g_part[kc][m][n] =
                    make_float2(c[mf][nf][rr * 2 + 0], c[mf][nf][rr * 2 + 1]);
            }
        }
    }
}

// ---------------------------------------------------------------------------
// Kernel 2b: reduce partials, bias+tanh, write hn and fp16 hi/lo split
// ---------------------------------------------------------------------------
__global__ __launch_bounds__(256)
void rnn_finish(const float* __restrict__ b_ih,
                const float* __restrict__ b_hh,
                float* __restrict__ hn)
{
    const int m = blockIdx.x;
    const int n = threadIdx.x * 4;
    const float4 p0 = *(const float4*)&g_part[0][m][n];
    const float4 p1 = *(const float4*)&g_part[1][m][n];
    const float4 p2 = *(const float4*)&g_part[2][m][n];
    const float4 bi = *(const float4*)(b_ih + n);
    const float4 bh = *(const float4*)(b_hh + n);
    float4 o;
    o.x = tanhf(p0.x + p1.x + p2.x + bi.x + bh.x);
    o.y = tanhf(p0.y + p1.y + p2.y + bi.y + bh.y);
    o.z = tanhf(p0.z + p1.z + p2.z + bi.z + bh.z);
    o.w = tanhf(p0.w + p1.w + p2.w + bi.w + bh.w);
    *(float4*)(hn + (size_t)m * HDIM + n) = o;
    uint2 hi, lo;
    split4h(o, hi, lo);
    *(uint2*)(g_Ahi + (size_t)m * HDIM + n) = hi;
    *(uint2*)(g_Alo + (size_t)m * HDIM + n) = lo;
}

// ---------------------------------------------------------------------------
// Kernel 3: logits, fp16 x2 (A split, B single-rounded).
// CTA 128x64, 128 threads (4 warps 2x2, warp 64x32), 4 CTA/SM.
// smem: A ring-3 x 8192 (hi 4096 | lo 4096) = 24576; B dbuf 2 x 2048 at 24576.
// Per iter/warp: 8 ldsm4 + 4 ldsm2 + 32 HMMA.
// ---------------------------------------------------------------------------
#define LA_STG 8192
#define LB_OFF 24576
#define LB_STG 2048
#define L_SMEM 28672

__global__ __launch_bounds__(128, 4)
void logits_mma(const __half* __restrict__ Ahi,
                const __half* __restrict__ Alo,
                const float* __restrict__ Wf,
                const float* __restrict__ bf,
                float* __restrict__ Cout)
{
    const uint32_t smb = s2u(dynsm);
    const int tid = threadIdx.x, lane = tid & 31, warp = tid >> 5;
    const int n0 = blockIdx.x * 64;
    const int m0 = blockIdx.y * 128;
    const int wm = (warp >> 1) * 64;
    const int wn = (warp & 1) * 32;

    // A cp.async mapping: 2 x 16B chunks per thread per (hi|lo)
    int arow[2], acol[2]; uint32_t adst[2];
    #pragma unroll
    for (int i = 0; i < 2; ++i) {
        const int f = i * 128 + tid;
        arow[i] = f >> 1;
        const int ch = f & 1;
        acol[i] = ch * 8;
        adst[i] = (uint32_t)(arow[i] * 32 + ((ch * 16) ^ (((arow[i] >> 2) & 1) << 4)));
    }
    // B: each thread loads 8 fp32, converts to 8 fp16 (one 16B chunk)
    const int brow = tid >> 1, bhalf = tid & 1;
    const uint32_t bdst = (uint32_t)(brow * 32 + ((bhalf * 16) ^ (((brow >> 2) & 1) << 4)));
    const float* bsrc = Wf + (size_t)(n0 + brow) * HDIM + bhalf * 8;

    const int lr = lane & 7, lq = (lane >> 3) & 1, lh = lane >> 4;
    uint32_t aoff[4], boff[4];
    #pragma unroll
    for (int mf = 0; mf < 4; ++mf) {
        const int row = wm + mf * 16 + lr + lq * 8;
        aoff[mf] = (uint32_t)(row * 32 + ((lh * 16) ^ (((row >> 2) & 1) << 4)));
    }
    #pragma unroll
    for (int nf = 0; nf < 4; ++nf) {
        const int row = wn + nf * 8 + lr;
        boff[nf] = (uint32_t)(row * 32 + ((lq * 16) ^ (((row >> 2) & 1) << 4)));
    }

    float c[4][4][4] = {};

    // prologue
    float4 rb0 = *(const float4*)bsrc;
    float4 rb1 = *(const float4*)(bsrc + 4);
    #pragma unroll
    for (int st = 0; st < 2; ++st) {
        char* base = dynsm + st * LA_STG;
        #pragma unroll
        for (int i = 0; i < 2; ++i) {
            cp_async16(base + adst[i],        Ahi + (size_t)(m0 + arow[i]) * HDIM + st * 16 + acol[i]);
            cp_async16(base + 4096 + adst[i], Alo + (size_t)(m0 + arow[i]) * HDIM + st * 16 + acol[i]);
        }
        cp_commit();
    }
    {
        HF4 v0, v1;
        v0.h[0] = __float2half_rn(rb0.x); v0.h[1] = __float2half_rn(rb0.y);
        v0.h[2] = __float2half_rn(rb0.z); v0.h[3] = __float2half_rn(rb0.w);
        v1.h[0] = __float2half_rn(rb1.x); v1.h[1] = __float2half_rn(rb1.y);
        v1.h[2] = __float2half_rn(rb1.z); v1.h[3] = __float2half_rn(rb1.w);
        *(uint4*)(dynsm + LB_OFF + bdst) = make_uint4(v0.u.x, v0.u.y, v1.u.x, v1.u.y);
    }

    const int NS = HDIM / 16;   // 64
    for (int s = 0; s < NS; ++s) {
        const bool more = (s + 1 < NS);
        if (more) {
            rb0 = *(const float4*)(bsrc + (s + 1) * 16);
            rb1 = *(const float4*)(bsrc + (s + 1) * 16 + 4);
        }
        cp_wait<1>();
        __syncthreads();

        if (s + 2 < NS) {
            char* base = dynsm + ((s + 2) % 3) * LA_STG;
            #pragma unroll
            for (int i = 0; i < 2; ++i) {
                cp_async16(base + adst[i],        Ahi + (size_t)(m0 + arow[i]) * HDIM + (s + 2) * 16 + acol[i]);
                cp_async16(base + 4096 + adst[i], Alo + (size_t)(m0 + arow[i]) * HDIM + (s + 2) * 16 + acol[i]);
            }
        }
        cp_commit();

        if (more) {
            HF4 v0, v1;
            v0.h[0] = __float2half_rn(rb0.x); v0.h[1] = __float2half_rn(rb0.y);
            v0.h[2] = __float2half_rn(rb0.z); v0.h[3] = __float2half_rn(rb0.w);
            v1.h[0] = __float2half_rn(rb1.x); v1.h[1] = __float2half_rn(rb1.y);
            v1.h[2] = __float2half_rn(rb1.z); v1.h[3] = __float2half_rn(rb1.w);
            char* bb = dynsm + LB_OFF + ((s + 1) & 1) * LB_STG;
            *(uint4*)(bb + bdst) = make_uint4(v0.u.x, v0.u.y, v1.u.x, v1.u.y);
        }

        const uint32_t Ah = smb + (s % 3) * LA_STG;
        const uint32_t Al = Ah + 4096;
        const uint32_t Bh = smb + LB_OFF + (s & 1) * LB_STG;

        uint32_t bh[4][2];
        #pragma unroll
        for (int nf = 0; nf < 4; ++nf)
            ldsm2(bh[nf], Bh + boff[nf]);
        #pragma unroll
        for (int mf = 0; mf < 4; ++mf) {
            uint32_t ah[4], al[4];
            ldsm4(ah, Ah + aoff[mf]);
            ldsm4(al, Al + aoff[mf]);
            #pragma unroll
            for (int nf = 0; nf < 4; ++nf) {
                mma_f16(c[mf][nf], ah, bh[nf]);
                mma_f16(c[mf][nf], al, bh[nf]);
            }
        }
    }

    #pragma unroll
    for (int mf = 0; mf < 4; ++mf) {
        const int m = m0 + wm + mf * 16 + (lane >> 2);
        #pragma unroll
        for (int nf = 0; nf < 4; ++nf) {
            const int n = n0 + wn + nf * 8 + (lane & 3) * 2;
            const float b0 = bf[n], b1 = bf[n + 1];
            float2 o0 = make_float2(c[mf][nf][0] + b0, c[mf][nf][1] + b1);
            float2 o1 = make_float2(c[mf][nf][2] + b0, c[mf][nf][3] + b1);
            *(float2*)(Cout + (size_t)m * VOC + n) = o0;
            *(float2*)(Cout + (size_t)(m + 8) * VOC + n) = o1;
        }
    }
}

// ---------------------------------------------------------------------------
// Launch
// ---------------------------------------------------------------------------
extern "C" void kernel_launch(void* const* d_in, const int* in_sizes, int n_in,
                              void* d_out, int out_size)
{
    const int*   idx   = (const int*)d_in[0];
    const float* hid   = (const float*)d_in[1];
    const float* enc   = (const float*)d_in[2];
    const float* emb   = (const float*)d_in[3];
    const float* W_ih  = (const float*)d_in[4];
    const float* b_ih  = (const float*)d_in[5];
    const float* W_hh  = (const float*)d_in[6];
    const float* b_hh  = (const float*)d_in[7];
    const float* fc_W  = (const float*)d_in[8];
    const float* fc_b  = (const float*)d_in[9];

    float* out    = (float*)d_out;
    float* logits = out;
    float* hn     = out + (size_t)BSZ * VOC;
    float* attn   = out + (size_t)BSZ * VOC + (size_t)BSZ * HDIM;

    __half *Ahi, *Alo;
    cudaGetSymbolAddress((void**)&Ahi, g_Ahi);
    cudaGetSymbolAddress((void**)&Alo, g_Alo);

    const int attn_smem = (3 * TS * HDIM + 8 * TS) * 4;

    cudaFuncSetAttribute(attention_half, cudaFuncAttributeMaxDynamicSharedMemorySize, attn_smem);
    cudaFuncSetAttribute(rnn_mma,        cudaFuncAttributeMaxDynamicSharedMemorySize, R_SMEM);
    cudaFuncSetAttribute(logits_mma,     cudaFuncAttributeMaxDynamicSharedMemorySize, L_SMEM);

    pack_weights<<<HDIM, 256>>>(W_ih, W_hh);
    attention_half<<<BSZ * 2, 256, attn_smem>>>(hid, enc);
    attention_merge<<<BSZ, 256>>>(idx, hid, emb, attn);
    rnn_mma<<<dim3(HDIM / 64, BSZ / 64, 3), 128, R_SMEM>>>(nullptr);
    rnn_finish<<<BSZ, 256>>>(b_ih, b_hh, hn);
    logits_mma<<<dim3(VOC / 64, BSZ / 128), 128, L_SMEM>>>(Ahi, Alo, fc_W, fc_b, logits);
}

// round 9
// speedup vs baseline: 5.4590x; 1.1991x over previous
#include <cuda_runtime.h>
#include <cuda_bf16.h>
#include <cuda_fp16.h>
#include <math.h>
#include <stdint.h>

#define BSZ 256
#define SLEN 512
#define HDIM 1024
#define EDIM 300
#define VOC 32000
#define KX  (EDIM + HDIM + HDIM)   // 2348
#define KXP 2352                   // 147*16 = 3*784

__device__ __nv_bfloat16 g_Xhi[BSZ * KXP];
__device__ __nv_bfloat16 g_Xlo[BSZ * KXP];
__device__ __nv_bfloat16 g_Whi[HDIM * KXP];
__device__ __nv_bfloat16 g_Wlo[HDIM * KXP];
__device__ __half g_Ah[BSZ * HDIM];
__device__ float g_part[3][BSZ][HDIM];
__device__ float g_ctx[2][BSZ][HDIM];
__device__ float g_en[BSZ][SLEN];
__device__ float2 g_md[2][BSZ];

extern __shared__ char dynsm[];

// ---------------------------------------------------------------------------
// helpers
// ---------------------------------------------------------------------------
__device__ __forceinline__ uint32_t s2u(const void* p) {
    return (uint32_t)__cvta_generic_to_shared(p);
}
__device__ __forceinline__ void cp_async16(void* smem_dst, const void* gmem_src) {
    uint32_t s = s2u(smem_dst);
    asm volatile("cp.async.cg.shared.global [%0], [%1], 16;\n" :: "r"(s), "l"(gmem_src));
}
__device__ __forceinline__ void cp_commit() { asm volatile("cp.async.commit_group;\n"); }
template<int N> __device__ __forceinline__ void cp_wait() {
    asm volatile("cp.async.wait_group %0;\n" :: "n"(N) : "memory");
}
__device__ __forceinline__ void ldsm4(uint32_t* r, uint32_t a) {
    asm volatile("ldmatrix.sync.aligned.m8n8.x4.shared.b16 {%0,%1,%2,%3}, [%4];"
                 : "=r"(r[0]), "=r"(r[1]), "=r"(r[2]), "=r"(r[3]) : "r"(a));
}
__device__ __forceinline__ void ldsm2(uint32_t* r, uint32_t a) {
    asm volatile("ldmatrix.sync.aligned.m8n8.x2.shared.b16 {%0,%1}, [%2];"
                 : "=r"(r[0]), "=r"(r[1]) : "r"(a));
}
__device__ __forceinline__ void mma_bf16(float* c, const uint32_t* a, const uint32_t* b) {
    asm volatile(
        "mma.sync.aligned.m16n8k16.row.col.f32.bf16.bf16.f32 "
        "{%0,%1,%2,%3}, {%4,%5,%6,%7}, {%8,%9}, {%0,%1,%2,%3};"
        : "+f"(c[0]), "+f"(c[1]), "+f"(c[2]), "+f"(c[3])
        : "r"(a[0]), "r"(a[1]), "r"(a[2]), "r"(a[3]), "r"(b[0]), "r"(b[1]));
}
__device__ __forceinline__ void mma_f16(float* c, const uint32_t* a, const uint32_t* b) {
    asm volatile(
        "mma.sync.aligned.m16n8k16.row.col.f32.f16.f16.f32 "
        "{%0,%1,%2,%3}, {%4,%5,%6,%7}, {%8,%9}, {%0,%1,%2,%3};"
        : "+f"(c[0]), "+f"(c[1]), "+f"(c[2]), "+f"(c[3])
        : "r"(a[0]), "r"(a[1]), "r"(a[2]), "r"(a[3]), "r"(b[0]), "r"(b[1]));
}
union BF4 { __nv_bfloat16 h[4]; uint2 u; };
union HF4 { __half h[4]; uint2 u; };
__device__ __forceinline__ void split4v(const float4 v, uint2& hi, uint2& lo) {
    BF4 H, L;
    H.h[0] = __float2bfloat16(v.x); L.h[0] = __float2bfloat16(v.x - __bfloat162float(H.h[0]));
    H.h[1] = __float2bfloat16(v.y); L.h[1] = __float2bfloat16(v.y - __bfloat162float(H.h[1]));
    H.h[2] = __float2bfloat16(v.z); L.h[2] = __float2bfloat16(v.z - __bfloat162float(H.h[2]));
    H.h[3] = __float2bfloat16(v.w); L.h[3] = __float2bfloat16(v.w - __bfloat162float(H.h[3]));
    hi = H.u; lo = L.u;
}

// ---------------------------------------------------------------------------
// Kernel 1: attention halves (unchanged)
// ---------------------------------------------------------------------------
#define TS 8
#define HSTAGES 32
__global__ __launch_bounds__(256)
void attention_half(const float* __restrict__ hid,
                    const float* __restrict__ enc)
{
    float* tile = (float*)dynsm;
    float* red  = tile + 3 * TS * HDIM;

    const int b = blockIdx.x >> 1;
    const int half = blockIdx.x & 1;
    const int t = threadIdx.x;
    const int warp = t >> 5;

    const float4* enc4 = (const float4*)(enc + (size_t)b * SLEN * HDIM + (size_t)half * 256 * HDIM);
    const float4  h4   = ((const float4*)(hid + (size_t)b * HDIM))[t];

    #pragma unroll
    for (int st = 0; st < 2; ++st) {
        #pragma unroll
        for (int i = 0; i < TS; ++i)
            cp_async16(&tile[st * TS * HDIM + i * HDIM + t * 4], &enc4[(st * TS + i) * 256 + t]);
        cp_commit();
    }

    float4 ctx = make_float4(0.f, 0.f, 0.f, 0.f);
    float m = -1e30f, d = 0.f;

    for (int c = 0; c < HSTAGES; ++c) {
        if (c + 2 < HSTAGES) {
            float* nxt = tile + ((c + 2) % 3) * TS * HDIM;
            const int s0n = (c + 2) * TS;
            #pragma unroll
            for (int i = 0; i < TS; ++i)
                cp_async16(&nxt[i * HDIM + t * 4], &enc4[(size_t)(s0n + i) * 256 + t]);
        }
        cp_commit();
        cp_wait<2>();
        __syncthreads();

        float* cur = tile + (c % 3) * TS * HDIM;
        float part[TS];
        #pragma unroll
        for (int s = 0; s < TS; ++s) {
            const float4 e4 = ((const float4*)&cur[s * HDIM])[t];
            part[s] = e4.x * h4.x + e4.y * h4.y + e4.z * h4.z + e4.w * h4.w;
        }
        #pragma unroll
        for (int s = 0; s < TS; ++s)
            #pragma unroll
            for (int o = 16; o > 0; o >>= 1)
                part[s] += __shfl_down_sync(0xffffffffu, part[s], o);
        if ((t & 31) == 0) {
            #pragma unroll
            for (int s = 0; s < TS; ++s) red[warp * TS + s] = part[s];
        }
        __syncthreads();

        float en[TS];
        #pragma unroll
        for (int s = 0; s < TS; ++s) {
            float e = 0.f;
            #pragma unroll
            for (int w = 0; w < 8; ++w) e += red[w * TS + s];
            en[s] = e;
        }
        float tmax = en[0];
        #pragma unroll
        for (int s = 1; s < TS; ++s) tmax = fmaxf(tmax, en[s]);
        const float nm = fmaxf(m, tmax);
        const float f = __expf(m - nm);
        float p[TS], psum = 0.f;
        #pragma unroll
        for (int s = 0; s < TS; ++s) { p[s] = __expf(en[s] - nm); psum += p[s]; }
        d = d * f + psum;
        m = nm;

        ctx.x *= f; ctx.y *= f; ctx.z *= f; ctx.w *= f;
        #pragma unroll
        for (int s = 0; s < TS; ++s) {
            const float4 e4 = ((const float4*)&cur[s * HDIM])[t];
            ctx.x += p[s] * e4.x;
            ctx.y += p[s] * e4.y;
            ctx.z += p[s] * e4.z;
            ctx.w += p[s] * e4.w;
        }
        if (t < TS) g_en[b][half * 256 + c * TS + t] = en[t];
    }

    ((float4*)&g_ctx[half][b][0])[t] = ctx;
    if (t == 0) g_md[half][b] = make_float2(m, d);
}

// ---------------------------------------------------------------------------
// Kernel 1c: merge halves (unchanged)
// ---------------------------------------------------------------------------
__global__ __launch_bounds__(256)
void attention_merge(const int* __restrict__ idx,
                     const float* __restrict__ hid,
                     const float* __restrict__ emb_table,
                     float* __restrict__ attn_out)
{
    const int b = blockIdx.x;
    const int t = threadIdx.x;

    const float2 md0 = g_md[0][b];
    const float2 md1 = g_md[1][b];
    const float m = fmaxf(md0.x, md1.x);
    const float f0 = __expf(md0.x - m), f1 = __expf(md1.x - m);
    const float dd = md0.y * f0 + md1.y * f1;
    const float inv = 1.f / dd;

    __nv_bfloat16* Xh = g_Xhi + (size_t)b * KXP;
    __nv_bfloat16* Xl = g_Xlo + (size_t)b * KXP;

    const float4 c0 = ((const float4*)&g_ctx[0][b][0])[t];
    const float4 c1 = ((const float4*)&g_ctx[1][b][0])[t];
    float4 cc;
    cc.x = (c0.x * f0 + c1.x * f1) * inv;
    cc.y = (c0.y * f0 + c1.y * f1) * inv;
    cc.z = (c0.z * f0 + c1.z * f1) * inv;
    cc.w = (c0.w * f0 + c1.w * f1) * inv;
    uint2 hi, lo;
    split4v(cc, hi, lo);
    *(uint2*)(Xh + EDIM + t * 4) = hi;
    *(uint2*)(Xl + EDIM + t * 4) = lo;

    const float4 h4 = ((const float4*)(hid + (size_t)b * HDIM))[t];
    split4v(h4, hi, lo);
    *(uint2*)(Xh + EDIM + HDIM + t * 4) = hi;
    *(uint2*)(Xl + EDIM + HDIM + t * 4) = lo;

    const int ci = idx[b];
    for (int j = t; j < EDIM; j += 256) {
        const float v = emb_table[(size_t)ci * EDIM + j];
        const __nv_bfloat16 H = __float2bfloat16(v);
        Xh[j] = H;
        Xl[j] = __float2bfloat16(v - __bfloat162float(H));
    }
    if (t < 4) { Xh[KX + t] = __float2bfloat16(0.f); Xl[KX + t] = __float2bfloat16(0.f); }

    for (int s = t; s < SLEN; s += 256)
        attn_out[(size_t)b * SLEN + s] = __expf(g_en[b][s] - m) * inv;
}

// ---------------------------------------------------------------------------
// Kernel 1b: pack weights -> bf16 hi/lo, one block per output row
// ---------------------------------------------------------------------------
__global__ __launch_bounds__(256)
void pack_weights(const float* __restrict__ W_ih,
                  const float* __restrict__ W_hh)
{
    const int n = blockIdx.x;
    const float* src_ih = W_ih + (size_t)n * (EDIM + HDIM);
    const float* src_hh = W_hh + (size_t)n * HDIM;
    __nv_bfloat16* dh = g_Whi + (size_t)n * KXP;
    __nv_bfloat16* dl = g_Wlo + (size_t)n * KXP;
    for (int k = threadIdx.x; k < KXP; k += 256) {
        float v = 0.f;
        if (k < EDIM + HDIM)      v = src_ih[k];
        else if (k < KX)          v = src_hh[k - (EDIM + HDIM)];
        const __nv_bfloat16 H = __float2bfloat16(v);
        dh[k] = H;
        dl[k] = __float2bfloat16(v - __bfloat162float(H));
    }
}

// ---------------------------------------------------------------------------
// Kernel 2: RNN split-K mma (unchanged, bf16x3)
// ---------------------------------------------------------------------------
#define R_STG 4096
#define R_BOFF 12288
#define R_SMEM 24576
#define KCH 784   // KXP/3

__global__ __launch_bounds__(128, 4)
void rnn_mma(float* __restrict__ dummy)
{
    const uint32_t smb = s2u(dynsm);
    const int tid = threadIdx.x, lane = tid & 31, warp = tid >> 5;
    const int m0 = blockIdx.y * 64;
    const int n0 = blockIdx.x * 64;
    const int kc = blockIdx.z;
    const int kbase = kc * KCH;
    const int wm = (warp >> 1) * 32;
    const int wn = (warp & 1) * 32;

    const int crow = tid >> 1, chalf = tid & 1;
    const uint32_t cdst = (uint32_t)(crow * 32 + ((chalf * 16) ^ (((crow >> 2) & 1) << 4)));
    const __nv_bfloat16* Asrc_h = g_Xhi + (size_t)(m0 + crow) * KXP + kbase + chalf * 8;
    const __nv_bfloat16* Asrc_l = g_Xlo + (size_t)(m0 + crow) * KXP + kbase + chalf * 8;
    const __nv_bfloat16* Bsrc_h = g_Whi + (size_t)(n0 + crow) * KXP + kbase + chalf * 8;
    const __nv_bfloat16* Bsrc_l = g_Wlo + (size_t)(n0 + crow) * KXP + kbase + chalf * 8;

    const int lr = lane & 7, lq = (lane >> 3) & 1, lh = lane >> 4;
    uint32_t aoff[2], boff[4];
    #pragma unroll
    for (int mf = 0; mf < 2; ++mf) {
        const int row = wm + mf * 16 + lr + lq * 8;
        aoff[mf] = (uint32_t)(row * 32 + ((lh * 16) ^ (((row >> 2) & 1) << 4)));
    }
    #pragma unroll
    for (int nf = 0; nf < 4; ++nf) {
        const int row = wn + nf * 8 + lr;
        boff[nf] = (uint32_t)(row * 32 + ((lq * 16) ^ (((row >> 2) & 1) << 4)));
    }

    float c[2][4][4] = {};
    const int NS = KCH / 16;   // 49

    #pragma unroll
    for (int st = 0; st < 2; ++st) {
        char* ab = dynsm + st * R_STG;
        char* bb = dynsm + R_BOFF + st * R_STG;
        cp_async16(ab + cdst,        Asrc_h + st * 16);
        cp_async16(ab + 2048 + cdst, Asrc_l + st * 16);
        cp_async16(bb + cdst,        Bsrc_h + st * 16);
        cp_async16(bb + 2048 + cdst, Bsrc_l + st * 16);
        cp_commit();
    }

    for (int s = 0; s < NS; ++s) {
        if (s + 2 < NS) {
            char* ab = dynsm + ((s + 2) % 3) * R_STG;
            char* bb = dynsm + R_BOFF + ((s + 2) % 3) * R_STG;
            cp_async16(ab + cdst,        Asrc_h + (s + 2) * 16);
            cp_async16(ab + 2048 + cdst, Asrc_l + (s + 2) * 16);
            cp_async16(bb + cdst,        Bsrc_h + (s + 2) * 16);
            cp_async16(bb + 2048 + cdst, Bsrc_l + (s + 2) * 16);
        }
        cp_commit();
        cp_wait<2>();
        __syncthreads();

        const uint32_t Ah = smb + (s % 3) * R_STG;
        const uint32_t Al = Ah + 2048;
        const uint32_t Bh = smb + R_BOFF + (s % 3) * R_STG;
        const uint32_t Bl = Bh + 2048;

        uint32_t bh[4][2], bl[4][2];
        #pragma unroll
        for (int nf = 0; nf < 4; ++nf) {
            ldsm2(bh[nf], Bh + boff[nf]);
            ldsm2(bl[nf], Bl + boff[nf]);
        }
        #pragma unroll
        for (int mf = 0; mf < 2; ++mf) {
            uint32_t ah[4], al[4];
            ldsm4(ah, Ah + aoff[mf]);
            ldsm4(al, Al + aoff[mf]);
            #pragma unroll
            for (int nf = 0; nf < 4; ++nf) {
                mma_bf16(c[mf][nf], ah, bh[nf]);
                mma_bf16(c[mf][nf], ah, bl[nf]);
                mma_bf16(c[mf][nf], al, bh[nf]);
            }
        }
        __syncthreads();
    }

    #pragma unroll
    for (int mf = 0; mf < 2; ++mf) {
        #pragma unroll
        for (int nf = 0; nf < 4; ++nf) {
            const int n = n0 + wn + nf * 8 + (lane & 3) * 2;
            #pragma unroll
            for (int rr = 0; rr < 2; ++rr) {
                const int m = m0 + wm + mf * 16 + (lane >> 2) + rr * 8;
                *(float2*)&g_part[kc][m][n] =
                    make_float2(c[mf][nf][rr * 2 + 0], c[mf][nf][rr * 2 + 1]);
            }
        }
    }
}

// ---------------------------------------------------------------------------
// Kernel 2b: reduce partials, bias+tanh, write hn (fp32) and fp16 h_new
// ---------------------------------------------------------------------------
__global__ __launch_bounds__(256)
void rnn_finish(const float* __restrict__ b_ih,
                const float* __restrict__ b_hh,
                float* __restrict__ hn)
{
    const int m = blockIdx.x;
    const int n = threadIdx.x * 4;
    const float4 p0 = *(const float4*)&g_part[0][m][n];
    const float4 p1 = *(const float4*)&g_part[1][m][n];
    const float4 p2 = *(const float4*)&g_part[2][m][n];
    const float4 bi = *(const float4*)(b_ih + n);
    const float4 bh = *(const float4*)(b_hh + n);
    float4 o;
    o.x = tanhf(p0.x + p1.x + p2.x + bi.x + bh.x);
    o.y = tanhf(p0.y + p1.y + p2.y + bi.y + bh.y);
    o.z = tanhf(p0.z + p1.z + p2.z + bi.z + bh.z);
    o.w = tanhf(p0.w + p1.w + p2.w + bi.w + bh.w);
    *(float4*)(hn + (size_t)m * HDIM + n) = o;
    HF4 H;
    H.h[0] = __float2half_rn(o.x);
    H.h[1] = __float2half_rn(o.y);
    H.h[2] = __float2half_rn(o.z);
    H.h[3] = __float2half_rn(o.w);
    *(uint2*)(g_Ah + (size_t)m * HDIM + n) = H.u;
}

// ---------------------------------------------------------------------------
// Kernel 3: logits, plain fp16 x fp16 (fp32 accum).
// CTA 128x64, 128 threads (4 warps 2x2, warp 64x32), 4 CTA/SM.
// grid (2, 500): adjacent bids share n0 -> fc_W tile L2 reuse.
// smem: A ring-3 x 4096 = 12288; B dbuf 2 x 2048 at 12288. Total 16KB.
// Per iter/warp: 4 ldsm4 + 4 ldsm2 + 16 HMMA.
// ---------------------------------------------------------------------------
#define LA_STG 4096
#define LB_OFF 12288
#define LB_STG 2048
#define L_SMEM 16384

__global__ __launch_bounds__(128, 4)
void logits_mma(const __half* __restrict__ Ah,
                const float* __restrict__ Wf,
                const float* __restrict__ bf,
                float* __restrict__ Cout)
{
    const uint32_t smb = s2u(dynsm);
    const int tid = threadIdx.x, lane = tid & 31, warp = tid >> 5;
    const int m0 = blockIdx.x * 128;
    const int n0 = blockIdx.y * 64;
    const int wm = (warp >> 1) * 64;
    const int wn = (warp & 1) * 32;

    // A cp.async mapping: 2 x 16B chunks per thread
    int arow[2], acol[2]; uint32_t adst[2];
    #pragma unroll
    for (int i = 0; i < 2; ++i) {
        const int f = i * 128 + tid;
        arow[i] = f >> 1;
        const int ch = f & 1;
        acol[i] = ch * 8;
        adst[i] = (uint32_t)(arow[i] * 32 + ((ch * 16) ^ (((arow[i] >> 2) & 1) << 4)));
    }
    // B: each thread loads 8 fp32, converts to 8 fp16 (one 16B chunk)
    const int brow = tid >> 1, bhalf = tid & 1;
    const uint32_t bdst = (uint32_t)(brow * 32 + ((bhalf * 16) ^ (((brow >> 2) & 1) << 4)));
    const float* bsrc = Wf + (size_t)(n0 + brow) * HDIM + bhalf * 8;

    const int lr = lane & 7, lq = (lane >> 3) & 1, lh = lane >> 4;
    uint32_t aoff[4], boff[4];
    #pragma unroll
    for (int mf = 0; mf < 4; ++mf) {
        const int row = wm + mf * 16 + lr + lq * 8;
        aoff[mf] = (uint32_t)(row * 32 + ((lh * 16) ^ (((row >> 2) & 1) << 4)));
    }
    #pragma unroll
    for (int nf = 0; nf < 4; ++nf) {
        const int row = wn + nf * 8 + lr;
        boff[nf] = (uint32_t)(row * 32 + ((lq * 16) ^ (((row >> 2) & 1) << 4)));
    }

    float c[4][4][4] = {};

    // prologue
    float4 rb0 = *(const float4*)bsrc;
    float4 rb1 = *(const float4*)(bsrc + 4);
    #pragma unroll
    for (int st = 0; st < 2; ++st) {
        char* base = dynsm + st * LA_STG;
        #pragma unroll
        for (int i = 0; i < 2; ++i)
            cp_async16(base + adst[i], Ah + (size_t)(m0 + arow[i]) * HDIM + st * 16 + acol[i]);
        cp_commit();
    }
    {
        HF4 v0, v1;
        v0.h[0] = __float2half_rn(rb0.x); v0.h[1] = __float2half_rn(rb0.y);
        v0.h[2] = __float2half_rn(rb0.z); v0.h[3] = __float2half_rn(rb0.w);
        v1.h[0] = __float2half_rn(rb1.x); v1.h[1] = __float2half_rn(rb1.y);
        v1.h[2] = __float2half_rn(rb1.z); v1.h[3] = __float2half_rn(rb1.w);
        *(uint4*)(dynsm + LB_OFF + bdst) = make_uint4(v0.u.x, v0.u.y, v1.u.x, v1.u.y);
    }

    const int NS = HDIM / 16;   // 64
    for (int s = 0; s < NS; ++s) {
        const bool more = (s + 1 < NS);
        if (more) {
            rb0 = *(const float4*)(bsrc + (s + 1) * 16);
            rb1 = *(const float4*)(bsrc + (s + 1) * 16 + 4);
        }
        cp_wait<1>();
        __syncthreads();

        if (s + 2 < NS) {
            char* base = dynsm + ((s + 2) % 3) * LA_STG;
            #pragma unroll
            for (int i = 0; i < 2; ++i)
                cp_async16(base + adst[i], Ah + (size_t)(m0 + arow[i]) * HDIM + (s + 2) * 16 + acol[i]);
        }
        cp_commit();

        if (more) {
            HF4 v0, v1;
            v0.h[0] = __float2half_rn(rb0.x); v0.h[1] = __float2half_rn(rb0.y);
            v0.h[2] = __float2half_rn(rb0.z); v0.h[3] = __float2half_rn(rb0.w);
            v1.h[0] = __float2half_rn(rb1.x); v1.h[1] = __float2half_rn(rb1.y);
            v1.h[2] = __float2half_rn(rb1.z); v1.h[3] = __float2half_rn(rb1.w);
            char* bb = dynsm + LB_OFF + ((s + 1) & 1) * LB_STG;
            *(uint4*)(bb + bdst) = make_uint4(v0.u.x, v0.u.y, v1.u.x, v1.u.y);
        }

        const uint32_t Asm = smb + (s % 3) * LA_STG;
        const uint32_t Bsm = smb + LB_OFF + (s & 1) * LB_STG;

        uint32_t bh[4][2];
        #pragma unroll
        for (int nf = 0; nf < 4; ++nf)
            ldsm2(bh[nf], Bsm + boff[nf]);
        #pragma unroll
        for (int mf = 0; mf < 4; ++mf) {
            uint32_t ah[4];
            ldsm4(ah, Asm + aoff[mf]);
            #pragma unroll
            for (int nf = 0; nf < 4; ++nf)
                mma_f16(c[mf][nf], ah, bh[nf]);
        }
    }

    #pragma unroll
    for (int mf = 0; mf < 4; ++mf) {
        const int m = m0 + wm + mf * 16 + (lane >> 2);
        #pragma unroll
        for (int nf = 0; nf < 4; ++nf) {
            const int n = n0 + wn + nf * 8 + (lane & 3) * 2;
            const float b0 = bf[n], b1 = bf[n + 1];
            float2 o0 = make_float2(c[mf][nf][0] + b0, c[mf][nf][1] + b1);
            float2 o1 = make_float2(c[mf][nf][2] + b0, c[mf][nf][3] + b1);
            *(float2*)(Cout + (size_t)m * VOC + n) = o0;
            *(float2*)(Cout + (size_t)(m + 8) * VOC + n) = o1;
        }
    }
}

// ---------------------------------------------------------------------------
// Launch
// ---------------------------------------------------------------------------
extern "C" void kernel_launch(void* const* d_in, const int* in_sizes, int n_in,
                              void* d_out, int out_size)
{
    const int*   idx   = (const int*)d_in[0];
    const float* hid   = (const float*)d_in[1];
    const float* enc   = (const float*)d_in[2];
    const float* emb   = (const float*)d_in[3];
    const float* W_ih  = (const float*)d_in[4];
    const float* b_ih  = (const float*)d_in[5];
    const float* W_hh  = (const float*)d_in[6];
    const float* b_hh  = (const float*)d_in[7];
    const float* fc_W  = (const float*)d_in[8];
    const float* fc_b  = (const float*)d_in[9];

    float* out    = (float*)d_out;
    float* logits = out;
    float* hn     = out + (size_t)BSZ * VOC;
    float* attn   = out + (size_t)BSZ * VOC + (size_t)BSZ * HDIM;

    __half* Ah;
    cudaGetSymbolAddress((void**)&Ah, g_Ah);

    const int attn_smem = (3 * TS * HDIM + 8 * TS) * 4;

    cudaFuncSetAttribute(attention_half, cudaFuncAttributeMaxDynamicSharedMemorySize, attn_smem);
    cudaFuncSetAttribute(rnn_mma,        cudaFuncAttributeMaxDynamicSharedMemorySize, R_SMEM);
    cudaFuncSetAttribute(logits_mma,     cudaFuncAttributeMaxDynamicSharedMemorySize, L_SMEM);

    pack_weights<<<HDIM, 256>>>(W_ih, W_hh);
    attention_half<<<BSZ * 2, 256, attn_smem>>>(hid, enc);
    attention_merge<<<BSZ, 256>>>(idx, hid, emb, attn);
    rnn_mma<<<dim3(HDIM / 64, BSZ / 64, 3), 128, R_SMEM>>>(nullptr);
    rnn_finish<<<BSZ, 256>>>(b_ih, b_hh, hn);
    logits_mma<<<dim3(BSZ / 128, VOC / 64), 128, L_SMEM>>>(Ah, fc_W, fc_b, logits);
}

// round 10
// speedup vs baseline: 6.1521x; 1.1270x over previous
#include <cuda_runtime.h>
#include <cuda_bf16.h>
#include <cuda_fp16.h>
#include <math.h>
#include <stdint.h>

#define BSZ 256
#define SLEN 512
#define HDIM 1024
#define EDIM 300
#define VOC 32000
#define KX  (EDIM + HDIM + HDIM)   // 2348
#define KXP 2352                   // 147*16 = 3*784

__device__ __nv_bfloat16 g_Xhi[BSZ * KXP];
__device__ __nv_bfloat16 g_Xlo[BSZ * KXP];
__device__ __nv_bfloat16 g_Whi[HDIM * KXP];
__device__ __nv_bfloat16 g_Wlo[HDIM * KXP];
__device__ __half g_Ah[BSZ * HDIM];
__device__ float g_part[3][BSZ][HDIM];
__device__ float g_ctx[2][BSZ][HDIM];
__device__ float g_en[BSZ][SLEN];
__device__ float2 g_md[2][BSZ];

extern __shared__ char dynsm[];

// ---------------------------------------------------------------------------
// helpers
// ---------------------------------------------------------------------------
__device__ __forceinline__ uint32_t s2u(const void* p) {
    return (uint32_t)__cvta_generic_to_shared(p);
}
__device__ __forceinline__ void cp_async16(void* smem_dst, const void* gmem_src) {
    uint32_t s = s2u(smem_dst);
    asm volatile("cp.async.cg.shared.global [%0], [%1], 16;\n" :: "r"(s), "l"(gmem_src));
}
__device__ __forceinline__ void cp_commit() { asm volatile("cp.async.commit_group;\n"); }
template<int N> __device__ __forceinline__ void cp_wait() {
    asm volatile("cp.async.wait_group %0;\n" :: "n"(N) : "memory");
}
__device__ __forceinline__ void ldsm4(uint32_t* r, uint32_t a) {
    asm volatile("ldmatrix.sync.aligned.m8n8.x4.shared.b16 {%0,%1,%2,%3}, [%4];"
                 : "=r"(r[0]), "=r"(r[1]), "=r"(r[2]), "=r"(r[3]) : "r"(a));
}
__device__ __forceinline__ void ldsm2(uint32_t* r, uint32_t a) {
    asm volatile("ldmatrix.sync.aligned.m8n8.x2.shared.b16 {%0,%1}, [%2];"
                 : "=r"(r[0]), "=r"(r[1]) : "r"(a));
}
__device__ __forceinline__ void mma_bf16(float* c, const uint32_t* a, const uint32_t* b) {
    asm volatile(
        "mma.sync.aligned.m16n8k16.row.col.f32.bf16.bf16.f32 "
        "{%0,%1,%2,%3}, {%4,%5,%6,%7}, {%8,%9}, {%0,%1,%2,%3};"
        : "+f"(c[0]), "+f"(c[1]), "+f"(c[2]), "+f"(c[3])
        : "r"(a[0]), "r"(a[1]), "r"(a[2]), "r"(a[3]), "r"(b[0]), "r"(b[1]));
}
__device__ __forceinline__ void mma_f16(float* c, const uint32_t* a, const uint32_t* b) {
    asm volatile(
        "mma.sync.aligned.m16n8k16.row.col.f32.f16.f16.f32 "
        "{%0,%1,%2,%3}, {%4,%5,%6,%7}, {%8,%9}, {%0,%1,%2,%3};"
        : "+f"(c[0]), "+f"(c[1]), "+f"(c[2]), "+f"(c[3])
        : "r"(a[0]), "r"(a[1]), "r"(a[2]), "r"(a[3]), "r"(b[0]), "r"(b[1]));
}
union BF4 { __nv_bfloat16 h[4]; uint2 u; };
union HF4 { __half h[4]; uint2 u; };
__device__ __forceinline__ void split4v(const float4 v, uint2& hi, uint2& lo) {
    BF4 H, L;
    H.h[0] = __float2bfloat16(v.x); L.h[0] = __float2bfloat16(v.x - __bfloat162float(H.h[0]));
    H.h[1] = __float2bfloat16(v.y); L.h[1] = __float2bfloat16(v.y - __bfloat162float(H.h[1]));
    H.h[2] = __float2bfloat16(v.z); L.h[2] = __float2bfloat16(v.z - __bfloat162float(H.h[2]));
    H.h[3] = __float2bfloat16(v.w); L.h[3] = __float2bfloat16(v.w - __bfloat162float(H.h[3]));
    hi = H.u; lo = L.u;
}

// ---------------------------------------------------------------------------
// Kernel 1: attention halves, per-warp seq ownership.
// grid = BSZ*2. 256 threads = 8 warps; warp w owns seq c*8+w.
// smem ring-3 x 32KB; 1 barrier per stage; intra-warp reduce only.
// ---------------------------------------------------------------------------
#define HSTAGES 32   // 256 seq / 8
__global__ __launch_bounds__(256)
void attention_half(const float* __restrict__ hid,
                    const float* __restrict__ enc)
{
    float* tile = (float*)dynsm;          // 3 x 8192 floats
    __shared__ float2 wmd[8];

    const int b = blockIdx.x >> 1;
    const int half = blockIdx.x & 1;
    const int t = threadIdx.x;
    const int warp = t >> 5;
    const int lane = t & 31;

    const float4* enc4 = (const float4*)(enc + (size_t)b * SLEN * HDIM + (size_t)half * 256 * HDIM);
    const float4* hrow = (const float4*)(hid + (size_t)b * HDIM);

    float4 h4[8];
    #pragma unroll
    for (int j = 0; j < 8; ++j) h4[j] = hrow[lane + 32 * j];

    // prologue: stages 0,1
    #pragma unroll
    for (int st = 0; st < 2; ++st) {
        #pragma unroll
        for (int i = 0; i < 8; ++i)
            cp_async16(&tile[st * 8192 + i * HDIM + t * 4], &enc4[(st * 8 + i) * 256 + t]);
        cp_commit();
    }

    float4 ctx[8];
    #pragma unroll
    for (int j = 0; j < 8; ++j) ctx[j] = make_float4(0.f, 0.f, 0.f, 0.f);
    float m = -1e30f, d = 0.f;

    for (int c = 0; c < HSTAGES; ++c) {
        cp_wait<1>();
        __syncthreads();   // stage c ready; all warps done with stage c-1

        // prefetch stage c+2 into slot (c+2)%3 (safe: slot was consumed at c-1)
        if (c + 2 < HSTAGES) {
            float* nxt = tile + ((c + 2) % 3) * 8192;
            #pragma unroll
            for (int i = 0; i < 8; ++i)
                cp_async16(&nxt[i * HDIM + t * 4], &enc4[(size_t)((c + 2) * 8 + i) * 256 + t]);
        }
        cp_commit();

        const float4* row = (const float4*)(tile + (c % 3) * 8192 + warp * HDIM);
        float4 e4[8];
        float part = 0.f;
        #pragma unroll
        for (int j = 0; j < 8; ++j) {
            e4[j] = row[lane + 32 * j];
            part += e4[j].x * h4[j].x + e4[j].y * h4[j].y
                  + e4[j].z * h4[j].z + e4[j].w * h4[j].w;
        }
        #pragma unroll
        for (int o = 16; o > 0; o >>= 1)
            part += __shfl_xor_sync(0xffffffffu, part, o);
        const float en = part;

        const float nm = fmaxf(m, en);
        const float f = __expf(m - nm);
        const float p = __expf(en - nm);
        d = d * f + p;
        m = nm;
        #pragma unroll
        for (int j = 0; j < 8; ++j) {
            ctx[j].x = ctx[j].x * f + p * e4[j].x;
            ctx[j].y = ctx[j].y * f + p * e4[j].y;
            ctx[j].z = ctx[j].z * f + p * e4[j].z;
            ctx[j].w = ctx[j].w * f + p * e4[j].w;
        }
        if (lane == 0) g_en[b][half * 256 + c * 8 + warp] = en;
    }

    // merge 8 per-warp partials (scratch = slot 0: 8192 floats)
    __syncthreads();
    float* scratch = tile;
    #pragma unroll
    for (int j = 0; j < 8; ++j)
        ((float4*)(scratch + warp * HDIM))[lane + 32 * j] = ctx[j];
    if (lane == 0) wmd[warp] = make_float2(m, d);
    __syncthreads();

    float M = -1e30f;
    #pragma unroll
    for (int w = 0; w < 8; ++w) M = fmaxf(M, wmd[w].x);
    float fw[8], D = 0.f;
    #pragma unroll
    for (int w = 0; w < 8; ++w) { fw[w] = __expf(wmd[w].x - M); D += fw[w] * wmd[w].y; }

    float4 acc = make_float4(0.f, 0.f, 0.f, 0.f);
    #pragma unroll
    for (int w = 0; w < 8; ++w) {
        const float4 v = ((const float4*)(scratch + w * HDIM))[t];
        acc.x += fw[w] * v.x; acc.y += fw[w] * v.y;
        acc.z += fw[w] * v.z; acc.w += fw[w] * v.w;
    }
    ((float4*)&g_ctx[half][b][0])[t] = acc;
    if (t == 0) g_md[half][b] = make_float2(M, D);
}

// ---------------------------------------------------------------------------
// Kernel 1c: merge halves (unchanged)
// ---------------------------------------------------------------------------
__global__ __launch_bounds__(256)
void attention_merge(const int* __restrict__ idx,
                     const float* __restrict__ hid,
                     const float* __restrict__ emb_table,
                     float* __restrict__ attn_out)
{
    const int b = blockIdx.x;
    const int t = threadIdx.x;

    const float2 md0 = g_md[0][b];
    const float2 md1 = g_md[1][b];
    const float m = fmaxf(md0.x, md1.x);
    const float f0 = __expf(md0.x - m), f1 = __expf(md1.x - m);
    const float dd = md0.y * f0 + md1.y * f1;
    const float inv = 1.f / dd;

    __nv_bfloat16* Xh = g_Xhi + (size_t)b * KXP;
    __nv_bfloat16* Xl = g_Xlo + (size_t)b * KXP;

    const float4 c0 = ((const float4*)&g_ctx[0][b][0])[t];
    const float4 c1 = ((const float4*)&g_ctx[1][b][0])[t];
    float4 cc;
    cc.x = (c0.x * f0 + c1.x * f1) * inv;
    cc.y = (c0.y * f0 + c1.y * f1) * inv;
    cc.z = (c0.z * f0 + c1.z * f1) * inv;
    cc.w = (c0.w * f0 + c1.w * f1) * inv;
    uint2 hi, lo;
    split4v(cc, hi, lo);
    *(uint2*)(Xh + EDIM + t * 4) = hi;
    *(uint2*)(Xl + EDIM + t * 4) = lo;

    const float4 h4 = ((const float4*)(hid + (size_t)b * HDIM))[t];
    split4v(h4, hi, lo);
    *(uint2*)(Xh + EDIM + HDIM + t * 4) = hi;
    *(uint2*)(Xl + EDIM + HDIM + t * 4) = lo;

    const int ci = idx[b];
    for (int j = t; j < EDIM; j += 256) {
        const float v = emb_table[(size_t)ci * EDIM + j];
        const __nv_bfloat16 H = __float2bfloat16(v);
        Xh[j] = H;
        Xl[j] = __float2bfloat16(v - __bfloat162float(H));
    }
    if (t < 4) { Xh[KX + t] = __float2bfloat16(0.f); Xl[KX + t] = __float2bfloat16(0.f); }

    for (int s = t; s < SLEN; s += 256)
        attn_out[(size_t)b * SLEN + s] = __expf(g_en[b][s] - m) * inv;
}

// ---------------------------------------------------------------------------
// Kernel 1b: pack weights -> bf16 hi/lo, one block per output row
// ---------------------------------------------------------------------------
__global__ __launch_bounds__(256)
void pack_weights(const float* __restrict__ W_ih,
                  const float* __restrict__ W_hh)
{
    const int n = blockIdx.x;
    const float* src_ih = W_ih + (size_t)n * (EDIM + HDIM);
    const float* src_hh = W_hh + (size_t)n * HDIM;
    __nv_bfloat16* dh = g_Whi + (size_t)n * KXP;
    __nv_bfloat16* dl = g_Wlo + (size_t)n * KXP;
    for (int k = threadIdx.x; k < KXP; k += 256) {
        float v = 0.f;
        if (k < EDIM + HDIM)      v = src_ih[k];
        else if (k < KX)          v = src_hh[k - (EDIM + HDIM)];
        const __nv_bfloat16 H = __float2bfloat16(v);
        dh[k] = H;
        dl[k] = __float2bfloat16(v - __bfloat162float(H));
    }
}

// ---------------------------------------------------------------------------
// Kernel 2: RNN split-K mma (unchanged, bf16x3)
// ---------------------------------------------------------------------------
#define R_STG 4096
#define R_BOFF 12288
#define R_SMEM 24576
#define KCH 784   // KXP/3

__global__ __launch_bounds__(128, 4)
void rnn_mma(float* __restrict__ dummy)
{
    const uint32_t smb = s2u(dynsm);
    const int tid = threadIdx.x, lane = tid & 31, warp = tid >> 5;
    const int m0 = blockIdx.y * 64;
    const int n0 = blockIdx.x * 64;
    const int kc = blockIdx.z;
    const int kbase = kc * KCH;
    const int wm = (warp >> 1) * 32;
    const int wn = (warp & 1) * 32;

    const int crow = tid >> 1, chalf = tid & 1;
    const uint32_t cdst = (uint32_t)(crow * 32 + ((chalf * 16) ^ (((crow >> 2) & 1) << 4)));
    const __nv_bfloat16* Asrc_h = g_Xhi + (size_t)(m0 + crow) * KXP + kbase + chalf * 8;
    const __nv_bfloat16* Asrc_l = g_Xlo + (size_t)(m0 + crow) * KXP + kbase + chalf * 8;
    const __nv_bfloat16* Bsrc_h = g_Whi + (size_t)(n0 + crow) * KXP + kbase + chalf * 8;
    const __nv_bfloat16* Bsrc_l = g_Wlo + (size_t)(n0 + crow) * KXP + kbase + chalf * 8;

    const int lr = lane & 7, lq = (lane >> 3) & 1, lh = lane >> 4;
    uint32_t aoff[2], boff[4];
    #pragma unroll
    for (int mf = 0; mf < 2; ++mf) {
        const int row = wm + mf * 16 + lr + lq * 8;
        aoff[mf] = (uint32_t)(row * 32 + ((lh * 16) ^ (((row >> 2) & 1) << 4)));
    }
    #pragma unroll
    for (int nf = 0; nf < 4; ++nf) {
        const int row = wn + nf * 8 + lr;
        boff[nf] = (uint32_t)(row * 32 + ((lq * 16) ^ (((row >> 2) & 1) << 4)));
    }

    float c[2][4][4] = {};
    const int NS = KCH / 16;   // 49

    #pragma unroll
    for (int st = 0; st < 2; ++st) {
        char* ab = dynsm + st * R_STG;
        char* bb = dynsm + R_BOFF + st * R_STG;
        cp_async16(ab + cdst,        Asrc_h + st * 16);
        cp_async16(ab + 2048 + cdst, Asrc_l + st * 16);
        cp_async16(bb + cdst,        Bsrc_h + st * 16);
        cp_async16(bb + 2048 + cdst, Bsrc_l + st * 16);
        cp_commit();
    }

    for (int s = 0; s < NS; ++s) {
        if (s + 2 < NS) {
            char* ab = dynsm + ((s + 2) % 3) * R_STG;
            char* bb = dynsm + R_BOFF + ((s + 2) % 3) * R_STG;
            cp_async16(ab + cdst,        Asrc_h + (s + 2) * 16);
            cp_async16(ab + 2048 + cdst, Asrc_l + (s + 2) * 16);
            cp_async16(bb + cdst,        Bsrc_h + (s + 2) * 16);
            cp_async16(bb + 2048 + cdst, Bsrc_l + (s + 2) * 16);
        }
        cp_commit();
        cp_wait<2>();
        __syncthreads();

        const uint32_t Ah = smb + (s % 3) * R_STG;
        const uint32_t Al = Ah + 2048;
        const uint32_t Bh = smb + R_BOFF + (s % 3) * R_STG;
        const uint32_t Bl = Bh + 2048;

        uint32_t bh[4][2], bl[4][2];
        #pragma unroll
        for (int nf = 0; nf < 4; ++nf) {
            ldsm2(bh[nf], Bh + boff[nf]);
            ldsm2(bl[nf], Bl + boff[nf]);
        }
        #pragma unroll
        for (int mf = 0; mf < 2; ++mf) {
            uint32_t ah[4], al[4];
            ldsm4(ah, Ah + aoff[mf]);
            ldsm4(al, Al + aoff[mf]);
            #pragma unroll
            for (int nf = 0; nf < 4; ++nf) {
                mma_bf16(c[mf][nf], ah, bh[nf]);
                mma_bf16(c[mf][nf], ah, bl[nf]);
                mma_bf16(c[mf][nf], al, bh[nf]);
            }
        }
        __syncthreads();
    }

    #pragma unroll
    for (int mf = 0; mf < 2; ++mf) {
        #pragma unroll
        for (int nf = 0; nf < 4; ++nf) {
            const int n = n0 + wn + nf * 8 + (lane & 3) * 2;
            #pragma unroll
            for (int rr = 0; rr < 2; ++rr) {
                const int m = m0 + wm + mf * 16 + (lane >> 2) + rr * 8;
                *(float2*)&g_part[kc][m][n] =
                    make_float2(c[mf][nf][rr * 2 + 0], c[mf][nf][rr * 2 + 1]);
            }
        }
    }
}

// ---------------------------------------------------------------------------
// Kernel 2b: reduce partials, bias+tanh, write hn (fp32) and fp16 h_new
// ---------------------------------------------------------------------------
__global__ __launch_bounds__(256)
void rnn_finish(const float* __restrict__ b_ih,
                const float* __restrict__ b_hh,
                float* __restrict__ hn)
{
    const int m = blockIdx.x;
    const int n = threadIdx.x * 4;
    const float4 p0 = *(const float4*)&g_part[0][m][n];
    const float4 p1 = *(const float4*)&g_part[1][m][n];
    const float4 p2 = *(const float4*)&g_part[2][m][n];
    const float4 bi = *(const float4*)(b_ih + n);
    const float4 bh = *(const float4*)(b_hh + n);
    float4 o;
    o.x = tanhf(p0.x + p1.x + p2.x + bi.x + bh.x);
    o.y = tanhf(p0.y + p1.y + p2.y + bi.y + bh.y);
    o.z = tanhf(p0.z + p1.z + p2.z + bi.z + bh.z);
    o.w = tanhf(p0.w + p1.w + p2.w + bi.w + bh.w);
    *(float4*)(hn + (size_t)m * HDIM + n) = o;
    HF4 H;
    H.h[0] = __float2half_rn(o.x);
    H.h[1] = __float2half_rn(o.y);
    H.h[2] = __float2half_rn(o.z);
    H.h[3] = __float2half_rn(o.w);
    *(uint2*)(g_Ah + (size_t)m * HDIM + n) = H.u;
}

// ---------------------------------------------------------------------------
// Kernel 3: logits, fp16 x fp16, k32 per iteration.
// CTA 128x64, 128 threads (4 warps 2x2, warp 64x32), 4 CTA/SM.
// Stage layout: rows of 32 fp16 (64B), chunk swizzle c16 ^= (row>>1)&3
// (8 consecutive rows hit 8 distinct 16B regions mod 128B: conflict-free ldsm).
// smem: A ring-3 x 8192 = 24576; B dbuf 2 x 4096 at 24576. Total 32KB.
// Per iter/warp: 8 ldsm4(A) + 4 ldsm4(B) + 32 HMMA; 32 iterations.
// ---------------------------------------------------------------------------
#define LA_STG 8192
#define LB_OFF 24576
#define LB_STG 4096
#define L_SMEM 32768

__global__ __launch_bounds__(128, 4)
void logits_mma(const __half* __restrict__ Ah,
                const float* __restrict__ Wf,
                const float* __restrict__ bf,
                float* __restrict__ Cout)
{
    const uint32_t smb = s2u(dynsm);
    const int tid = threadIdx.x, lane = tid & 31, warp = tid >> 5;
    const int m0 = blockIdx.x * 128;
    const int n0 = blockIdx.y * 64;
    const int wm = (warp >> 1) * 64;
    const int wn = (warp & 1) * 32;

    // A cp.async mapping: 512 chunks of 16B, 4 per thread
    int arow[4], acol[4]; uint32_t adst[4];
    #pragma unroll
    for (int i = 0; i < 4; ++i) {
        const int f = i * 128 + tid;
        arow[i] = f >> 2;
        const int c16 = f & 3;
        acol[i] = c16 * 8;
        adst[i] = (uint32_t)(arow[i] * 64 + ((c16 ^ ((arow[i] >> 1) & 3)) << 4));
    }
    // B mapping: 256 chunks, 2 per thread (each = 8 fp32 -> 8 fp16)
    int brow[2], bcol[2]; uint32_t bdst[2];
    #pragma unroll
    for (int i = 0; i < 2; ++i) {
        const int f = i * 128 + tid;
        brow[i] = f >> 2;
        const int c16 = f & 3;
        bcol[i] = c16 * 8;
        bdst[i] = (uint32_t)(brow[i] * 64 + ((c16 ^ ((brow[i] >> 1) & 3)) << 4));
    }

    // ldsm offsets
    const int lr = lane & 7, lq = (lane >> 3) & 1, lh = lane >> 4;
    uint32_t aoff[4][2], boff[4];
    #pragma unroll
    for (int mf = 0; mf < 4; ++mf) {
        const int row = wm + mf * 16 + lr + lq * 8;
        #pragma unroll
        for (int kk = 0; kk < 2; ++kk)
            aoff[mf][kk] = (uint32_t)(row * 64 + (((kk * 2 + lh) ^ ((row >> 1) & 3)) << 4));
    }
    #pragma unroll
    for (int nf = 0; nf < 4; ++nf) {
        const int row = wn + nf * 8 + (lane & 7);
        const int g = lane >> 3;
        boff[nf] = (uint32_t)(row * 64 + ((g ^ ((row >> 1) & 3)) << 4));
    }

    float c[4][4][4] = {};

    // prologue: A stages 0,1 via cp.async; B stage 0 via LDG+cvt+STS
    float4 rb[2][2];
    #pragma unroll
    for (int i = 0; i < 2; ++i) {
        rb[i][0] = *(const float4*)(Wf + (size_t)(n0 + brow[i]) * HDIM + bcol[i]);
        rb[i][1] = *(const float4*)(Wf + (size_t)(n0 + brow[i]) * HDIM + bcol[i] + 4);
    }
    #pragma unroll
    for (int st = 0; st < 2; ++st) {
        char* base = dynsm + st * LA_STG;
        #pragma unroll
        for (int i = 0; i < 4; ++i)
            cp_async16(base + adst[i], Ah + (size_t)(m0 + arow[i]) * HDIM + st * 32 + acol[i]);
        cp_commit();
    }
    #pragma unroll
    for (int i = 0; i < 2; ++i) {
        HF4 v0, v1;
        v0.h[0] = __float2half_rn(rb[i][0].x); v0.h[1] = __float2half_rn(rb[i][0].y);
        v0.h[2] = __float2half_rn(rb[i][0].z); v0.h[3] = __float2half_rn(rb[i][0].w);
        v1.h[0] = __float2half_rn(rb[i][1].x); v1.h[1] = __float2half_rn(rb[i][1].y);
        v1.h[2] = __float2half_rn(rb[i][1].z); v1.h[3] = __float2half_rn(rb[i][1].w);
        *(uint4*)(dynsm + LB_OFF + bdst[i]) = make_uint4(v0.u.x, v0.u.y, v1.u.x, v1.u.y);
    }

    const int NS = HDIM / 32;   // 32
    for (int s = 0; s < NS; ++s) {
        const bool more = (s + 1 < NS);
        if (more) {
            #pragma unroll
            for (int i = 0; i < 2; ++i) {
                rb[i][0] = *(const float4*)(Wf + (size_t)(n0 + brow[i]) * HDIM + (s + 1) * 32 + bcol[i]);
                rb[i][1] = *(const float4*)(Wf + (size_t)(n0 + brow[i]) * HDIM + (s + 1) * 32 + bcol[i] + 4);
            }
        }
        cp_wait<1>();
        __syncthreads();

        if (s + 2 < NS) {
            char* base = dynsm + ((s + 2) % 3) * LA_STG;
            #pragma unroll
            for (int i = 0; i < 4; ++i)
                cp_async16(base + adst[i], Ah + (size_t)(m0 + arow[i]) * HDIM + (s + 2) * 32 + acol[i]);
        }
        cp_commit();

        if (more) {
            char* bb = dynsm + LB_OFF + ((s + 1) & 1) * LB_STG;
            #pragma unroll
            for (int i = 0; i < 2; ++i) {
                HF4 v0, v1;
                v0.h[0] = __float2half_rn(rb[i][0].x); v0.h[1] = __float2half_rn(rb[i][0].y);
                v0.h[2] = __float2half_rn(rb[i][0].z); v0.h[3] = __float2half_rn(rb[i][0].w);
                v1.h[0] = __float2half_rn(rb[i][1].x); v1.h[1] = __float2half_rn(rb[i][1].y);
                v1.h[2] = __float2half_rn(rb[i][1].z); v1.h[3] = __float2half_rn(rb[i][1].w);
                *(uint4*)(bb + bdst[i]) = make_uint4(v0.u.x, v0.u.y, v1.u.x, v1.u.y);
            }
        }

        const uint32_t Asm = smb + (s % 3) * LA_STG;
        const uint32_t Bsm = smb + LB_OFF + (s & 1) * LB_STG;

        uint32_t bq[4][4];
        #pragma unroll
        for (int nf = 0; nf < 4; ++nf)
            ldsm4(bq[nf], Bsm + boff[nf]);
        #pragma unroll
        for (int mf = 0; mf < 4; ++mf) {
            uint32_t aq0[4], aq1[4];
            ldsm4(aq0, Asm + aoff[mf][0]);
            ldsm4(aq1, Asm + aoff[mf][1]);
            #pragma unroll
            for (int nf = 0; nf < 4; ++nf) {
                mma_f16(c[mf][nf], aq0, &bq[nf][0]);
                mma_f16(c[mf][nf], aq1, &bq[nf][2]);
            }
        }
    }

    #pragma unroll
    for (int mf = 0; mf < 4; ++mf) {
        const int m = m0 + wm + mf * 16 + (lane >> 2);
        #pragma unroll
        for (int nf = 0; nf < 4; ++nf) {
            const int n = n0 + wn + nf * 8 + (lane & 3) * 2;
            const float b0 = bf[n], b1 = bf[n + 1];
            float2 o0 = make_float2(c[mf][nf][0] + b0, c[mf][nf][1] + b1);
            float2 o1 = make_float2(c[mf][nf][2] + b0, c[mf][nf][3] + b1);
            *(float2*)(Cout + (size_t)m * VOC + n) = o0;
            *(float2*)(Cout + (size_t)(m + 8) * VOC + n) = o1;
        }
    }
}

// ---------------------------------------------------------------------------
// Launch
// ---------------------------------------------------------------------------
extern "C" void kernel_launch(void* const* d_in, const int* in_sizes, int n_in,
                              void* d_out, int out_size)
{
    const int*   idx   = (const int*)d_in[0];
    const float* hid   = (const float*)d_in[1];
    const float* enc   = (const float*)d_in[2];
    const float* emb   = (const float*)d_in[3];
    const float* W_ih  = (const float*)d_in[4];
    const float* b_ih  = (const float*)d_in[5];
    const float* W_hh  = (const float*)d_in[6];
    const float* b_hh  = (const float*)d_in[7];
    const float* fc_W  = (const float*)d_in[8];
    const float* fc_b  = (const float*)d_in[9];

    float* out    = (float*)d_out;
    float* logits = out;
    float* hn     = out + (size_t)BSZ * VOC;
    float* attn   = out + (size_t)BSZ * VOC + (size_t)BSZ * HDIM;

    __half* Ah;
    cudaGetSymbolAddress((void**)&Ah, g_Ah);

    const int attn_smem = 3 * 8192 * 4;   // 96KB ring

    cudaFuncSetAttribute(attention_half, cudaFuncAttributeMaxDynamicSharedMemorySize, attn_smem);
    cudaFuncSetAttribute(rnn_mma,        cudaFuncAttributeMaxDynamicSharedMemorySize, R_SMEM);
    cudaFuncSetAttribute(logits_mma,     cudaFuncAttributeMaxDynamicSharedMemorySize, L_SMEM);

    pack_weights<<<HDIM, 256>>>(W_ih, W_hh);
    attention_half<<<BSZ * 2, 256, attn_smem>>>(hid, enc);
    attention_merge<<<BSZ, 256>>>(idx, hid, emb, attn);
    rnn_mma<<<dim3(HDIM / 64, BSZ / 64, 3), 128, R_SMEM>>>(nullptr);
    rnn_finish<<<BSZ, 256>>>(b_ih, b_hh, hn);
    logits_mma<<<dim3(BSZ / 128, VOC / 64), 128, L_SMEM>>>(Ah, fc_W, fc_b, logits);
}